// round 7
// baseline (speedup 1.0000x reference)
#include <cuda_runtime.h>
#include <cstdint>

// ---------------- problem constants ----------------
#define BB   1024
#define NN   128
#define FF   16
#define GG   48
#define HH   6
#define DD   8
#define GRUU 256
#define EMBB 128
#define XG   (NN*GG)       // 6144
#define G3   (3*GRUU)      // 768
#define SK0  8             // split-K for GRU0
#define TG   192           // GAT block size

// ---------------- scratch ----------------
__device__ float g_x  [BB*XG];
__device__ float g_gip[SK0*BB*G3];      // split-K partials (shared by all GEMMs)
__device__ float g_h  [BB*GRUU];
__device__ float g_hln[BB*GRUU];
__device__ float g_emb[BB*EMBB];

// ---------------- helpers ----------------
__device__ __forceinline__ void tf32split(float v, uint32_t& h, uint32_t& l) {
    uint32_t hb; asm("cvt.rna.tf32.f32 %0, %1;" : "=r"(hb) : "f"(v));
    float lv = v - __uint_as_float(hb);
    uint32_t lb; asm("cvt.rna.tf32.f32 %0, %1;" : "=r"(lb) : "f"(lv));
    h = hb; l = lb;
}

__device__ __forceinline__ uint32_t smem_u32(const void* p) {
    uint32_t a;
    asm("{ .reg .u64 t; cvta.to.shared.u64 t, %1; cvt.u32.u64 %0, t; }" : "=r"(a) : "l"(p));
    return a;
}

__device__ __forceinline__ void ldsm_x4(uint32_t* d, uint32_t addr) {
    asm volatile("ldmatrix.sync.aligned.m8n8.x4.shared.b16 {%0,%1,%2,%3}, [%4];"
        : "=r"(d[0]), "=r"(d[1]), "=r"(d[2]), "=r"(d[3]) : "r"(addr));
}

__device__ __forceinline__ void mma_tf32(float* c, const uint32_t* a, const uint32_t* b) {
    asm volatile("mma.sync.aligned.m16n8k8.row.col.f32.tf32.tf32.f32 "
        "{%0,%1,%2,%3}, {%4,%5,%6,%7}, {%8,%9}, {%0,%1,%2,%3};\n"
        : "+f"(c[0]), "+f"(c[1]), "+f"(c[2]), "+f"(c[3])
        : "r"(a[0]), "r"(a[1]), "r"(a[2]), "r"(a[3]), "r"(b[0]), "r"(b[1]));
}

// =======================================================================
// GAT attention: 192 threads = 32/head; each thread does 4 rows of ONE
// head. Rank-1 exp trick.
// =======================================================================
__device__ __forceinline__ void gat_attention(
    const float* __restrict__ sh, const float* __restrict__ sei,
    const float* __restrict__ sej, const float* __restrict__ sPj,
    const float* __restrict__ sQj, const unsigned* __restrict__ smask,
    float* __restrict__ sy, int tid)
{
    int hd = tid >> 5, i0 = tid & 31;
    const float* ejp = sej + (hd << 7);
    const float* Pjp = sPj + (hd << 7);
    const float* Qjp = sQj + (hd << 7);
    const float* hp  = sh  + (hd << 10);

    float eiv[4], Pi[4], Qi[4], ssum[4];
    float acc[4][8];
    #pragma unroll
    for (int r = 0; r < 4; r++) {
        eiv[r] = sei[(hd << 7) + i0 + (r << 5)];
        Pi[r] = __expf(eiv[r]); Qi[r] = __expf(0.01f * eiv[r]);
        ssum[r] = 0.f;
        #pragma unroll
        for (int d = 0; d < 8; d++) acc[r][d] = 0.f;
    }

    #pragma unroll 1
    for (int jw = 0; jw < 4; jw++) {
        unsigned bits[4];
        #pragma unroll
        for (int r = 0; r < 4; r++)
            bits[r] = smask[((i0 + (r << 5)) << 2) + jw];
        #pragma unroll 1
        for (int jq = 0; jq < 8; jq++) {
            int j0 = (jw << 5) + (jq << 2);
            float4 e4 = *(const float4*)(ejp + j0);
            float4 P4 = *(const float4*)(Pjp + j0);
            float4 Q4 = *(const float4*)(Qjp + j0);
            float ee[4] = {e4.x, e4.y, e4.z, e4.w};
            float PP[4] = {P4.x, P4.y, P4.z, P4.w};
            float QQ[4] = {Q4.x, Q4.y, Q4.z, Q4.w};
            #pragma unroll
            for (int t = 0; t < 4; t++) {
                int j = j0 + t;
                float4 h0 = *(const float4*)(hp + (j << 3));
                float4 h1 = *(const float4*)(hp + (j << 3) + 4);
                unsigned bsel = 1u << ((jq << 2) + t);
                #pragma unroll
                for (int r = 0; r < 4; r++) {
                    float w = (eiv[r] + ee[t] > 0.f) ? (Pi[r] * PP[t]) : (Qi[r] * QQ[t]);
                    w = (bits[r] & bsel) ? w : 0.f;
                    ssum[r] += w;
                    acc[r][0] = fmaf(w, h0.x, acc[r][0]);
                    acc[r][1] = fmaf(w, h0.y, acc[r][1]);
                    acc[r][2] = fmaf(w, h0.z, acc[r][2]);
                    acc[r][3] = fmaf(w, h0.w, acc[r][3]);
                    acc[r][4] = fmaf(w, h1.x, acc[r][4]);
                    acc[r][5] = fmaf(w, h1.y, acc[r][5]);
                    acc[r][6] = fmaf(w, h1.z, acc[r][6]);
                    acc[r][7] = fmaf(w, h1.w, acc[r][7]);
                }
            }
        }
    }
    #pragma unroll
    for (int r = 0; r < 4; r++) {
        float inv = 1.0f / ssum[r];
        float* o = sy + (i0 + (r << 5)) * 49 + (hd << 3);
        #pragma unroll
        for (int d = 0; d < 8; d++) o[d] = acc[r][d] * inv;
    }
}

// LayerNorm over all [N,G] of one batch, + ReLU. sy row stride 49. 6 warps.
__device__ __forceinline__ void ln2d_apply(
    float* __restrict__ sy, const float* __restrict__ gamma,
    const float* __restrict__ beta, float* __restrict__ sred,
    int tid, float* __restrict__ gout)
{
    float s = 0.f, q = 0.f;
    for (int t = tid; t < XG; t += TG) {
        int n = t / 48, c = t - n * 48;
        float v = sy[n * 49 + c];
        s += v; q += v * v;
    }
    #pragma unroll
    for (int o = 16; o; o >>= 1) {
        s += __shfl_xor_sync(0xffffffffu, s, o);
        q += __shfl_xor_sync(0xffffffffu, q, o);
    }
    int wid = tid >> 5;
    if ((tid & 31) == 0) { sred[wid] = s; sred[8 + wid] = q; }
    __syncthreads();
    if (tid == 0) {
        float S = 0.f, Q = 0.f;
        #pragma unroll
        for (int i = 0; i < 6; i++) { S += sred[i]; Q += sred[8 + i]; }
        float m   = S * (1.f / (float)XG);
        float var = Q * (1.f / (float)XG) - m * m;
        sred[16] = m;
        sred[17] = rsqrtf(var + 1e-5f);
    }
    __syncthreads();
    float m = sred[16], rs = sred[17];
    for (int t = tid; t < XG; t += TG) {
        int n = t / 48, c = t - n * 48;
        float v = (sy[n * 49 + c] - m) * rs * gamma[t] + beta[t];
        v = fmaxf(v, 0.f);
        if (gout) gout[t] = v; else sy[n * 49 + c] = v;
    }
}

__global__ __launch_bounds__(TG)
void gat_kernel(const float* __restrict__ X,  const int* __restrict__ A,
                const float* __restrict__ W1, const float* __restrict__ a1,
                const float* __restrict__ W2, const float* __restrict__ a2,
                const float* __restrict__ Wr, const float* __restrict__ br,
                const float* __restrict__ g1, const float* __restrict__ b1,
                const float* __restrict__ g2, const float* __restrict__ b2)
{
    extern __shared__ float sm[];
    float*    sX    = sm;               // 2176
    float*    sh    = sX  + 2176;       // 6144
    float*    sy    = sh  + 6144;       // 6272
    float*    sei   = sy  + 6272;       // 768
    float*    sej   = sei + 768;        // 768
    float*    sPj   = sej + 768;        // 768
    float*    sQj   = sPj + 768;        // 768
    float*    sW    = sQj + 768;        // 2304
    float*    sa    = sW  + 2304;       // 96
    float*    sred  = sa  + 96;         // 20
    unsigned* smask = (unsigned*)(sred + 20); // 512

    int b = blockIdx.x, tid = threadIdx.x;

    const float* Xb = X + (size_t)b * (NN * FF);
    for (int t = tid; t < NN * FF; t += TG)
        sX[(t >> 4) * 17 + (t & 15)] = Xb[t];

    {
        const int* Ab = A + (size_t)b * (NN * NN);
        int lane = tid & 31, wid = tid >> 5;
        for (int w = wid; w < 512; w += 6) {
            int i = w >> 2, j0 = (w & 3) << 5;
            unsigned bits = __ballot_sync(0xffffffffu, Ab[(i << 7) + j0 + lane] != 0);
            if (lane == 0) smask[w] = bits;
        }
    }
    for (int t = tid; t < HH * FF * DD; t += TG) sW[t] = W1[t];
    if (tid < HH * 2 * DD) sa[tid] = a1[tid];
    __syncthreads();

    for (int t = tid; t < HH * NN; t += TG) {
        int hd = t >> 7, n = t & 127;
        float acc[8];
        #pragma unroll
        for (int d = 0; d < 8; d++) acc[d] = 0.f;
        const float* w = sW + hd * (FF * DD);
        const float* x = sX + n * 17;
        #pragma unroll
        for (int f = 0; f < FF; f++) {
            float xv = x[f];
            #pragma unroll
            for (int d = 0; d < 8; d++) acc[d] = fmaf(xv, w[(f << 3) + d], acc[d]);
        }
        const float* av = sa + (hd << 4);
        float ei = 0.f, ej = 0.f;
        #pragma unroll
        for (int d = 0; d < 8; d++) { ei = fmaf(acc[d], av[d], ei); ej = fmaf(acc[d], av[8 + d], ej); }
        #pragma unroll
        for (int d = 0; d < 8; d++) sh[(t << 3) + d] = acc[d];
        sei[t] = ei; sej[t] = ej;
        sPj[t] = __expf(ej); sQj[t] = __expf(0.01f * ej);
    }
    __syncthreads();
    gat_attention(sh, sei, sej, sPj, sQj, smask, sy, tid);
    __syncthreads();
    ln2d_apply(sy, g1, b1, sred, tid, nullptr);
    __syncthreads();

    for (int t = tid; t < HH * GG * DD; t += TG) sW[t] = W2[t];
    if (tid < HH * 2 * DD) sa[tid] = a2[tid];
    __syncthreads();

    for (int t = tid; t < HH * NN; t += TG) {
        int hd = t >> 7, n = t & 127;
        float acc[8];
        #pragma unroll
        for (int d = 0; d < 8; d++) acc[d] = 0.f;
        const float* w = sW + hd * (GG * DD);
        const float* x = sy + n * 49;
        #pragma unroll
        for (int f = 0; f < GG; f++) {
            float xv = x[f];
            #pragma unroll
            for (int d = 0; d < 8; d++) acc[d] = fmaf(xv, w[(f << 3) + d], acc[d]);
        }
        const float* av = sa + (hd << 4);
        float ei = 0.f, ej = 0.f;
        #pragma unroll
        for (int d = 0; d < 8; d++) { ei = fmaf(acc[d], av[d], ei); ej = fmaf(acc[d], av[8 + d], ej); }
        #pragma unroll
        for (int d = 0; d < 8; d++) sh[(t << 3) + d] = acc[d];
        sei[t] = ei; sej[t] = ej;
        sPj[t] = __expf(ej); sQj[t] = __expf(0.01f * ej);
    }
    __syncthreads();
    gat_attention(sh, sei, sej, sPj, sQj, smask, sy, tid);
    __syncthreads();

    for (int t = tid; t < FF * GG; t += TG) sW[t] = Wr[t];
    if (tid < GG) sa[tid] = br[tid];
    __syncthreads();
    for (int t = tid; t < XG; t += TG) {
        int n = t / 48, c = t - n * 48;
        float accv = sa[c];
        const float* x = sX + n * 17;
        #pragma unroll
        for (int f = 0; f < FF; f++) accv = fmaf(x[f], sW[f * 48 + c], accv);
        sy[n * 49 + c] += accv;
    }
    __syncthreads();
    ln2d_apply(sy, g2, b2, sred, tid, g_x + (size_t)b * XG);
}

// =======================================================================
// Double-buffered 3xTF32 GEMM, BK=16, stride-20 smem (40KB/CTA -> 4/SM).
// B row-major [N,K]. Split-K via grid.z -> partial C at z*M*N.
// BM=BN=64, 256 thr / 8 warps (4x2), warp tile 16x32.
// =======================================================================
#define PLANE_W   (64*20)             // 1280 words per plane
#define BUF_W     (2*PLANE_W)         // hi+lo = 2560 words
#define LO_BYTES  (PLANE_W*4)         // 5120
#define BUF_BYTES (BUF_W*4)           // 10240
#define GEMM_SMEM (4*BUF_BYTES)       // 40960

__global__ __launch_bounds__(256)
void gemm_nk(const float* __restrict__ Af, const float* __restrict__ Bf,
             float* __restrict__ C, int M, int N, int K, int kChunk)
{
    extern __shared__ uint32_t smem[];
    uint32_t* sA = smem;                 // [2 bufs][hi/lo][64][20]
    uint32_t* sB = smem + 2 * BUF_W;

    int tid  = threadIdx.x;
    int lane = tid & 31, wid = tid >> 5;
    int warpM = (wid >> 1) << 4;
    int warpN = (wid & 1) << 5;
    int g = lane >> 2, tig = lane & 3;
    int bm = blockIdx.y << 6, bn = blockIdx.x << 6;
    int kBeg = blockIdx.z * kChunk;
    int nt   = kChunk >> 4;

    uint32_t aOff = (((warpM + (lane & 15)) * 20 + ((lane >> 4) << 2)) << 2);
    uint32_t bOff = (((warpN + ((lane >> 4) << 3) + (lane & 7)) * 20 + (((lane >> 3) & 1) << 2)) << 2);
    uint32_t aBaseS = smem_u32(sA);
    uint32_t bBaseS = smem_u32(sB);

    int frow = tid >> 2;                 // 0..63
    int fkc  = (tid & 3) << 2;           // 0,4,8,12

    float acc[4][4];
    #pragma unroll
    for (int ns = 0; ns < 4; ns++)
        #pragma unroll
        for (int r = 0; r < 4; r++) acc[ns][r] = 0.f;

    float4 pA, pB;

    auto FETCH = [&](int kt) {
        pA = *(const float4*)(Af + (size_t)(bm + frow) * K + kBeg + kt + fkc);
        pB = *(const float4*)(Bf + (size_t)(bn + frow) * K + kBeg + kt + fkc);
    };
    auto STORE = [&](int buf) {
        uint32_t* dA = sA + buf * BUF_W;
        uint32_t* dB = sB + buf * BUF_W;
        uint4 hi, lo;
        tf32split(pA.x, hi.x, lo.x); tf32split(pA.y, hi.y, lo.y);
        tf32split(pA.z, hi.z, lo.z); tf32split(pA.w, hi.w, lo.w);
        *(uint4*)(dA + frow * 20 + fkc)           = hi;
        *(uint4*)(dA + PLANE_W + frow * 20 + fkc) = lo;
        tf32split(pB.x, hi.x, lo.x); tf32split(pB.y, hi.y, lo.y);
        tf32split(pB.z, hi.z, lo.z); tf32split(pB.w, hi.w, lo.w);
        *(uint4*)(dB + frow * 20 + fkc)           = hi;
        *(uint4*)(dB + PLANE_W + frow * 20 + fkc) = lo;
    };

    FETCH(0);
    STORE(0);
    __syncthreads();

    for (int t = 0; t < nt; t++) {
        int cur = t & 1;
        bool more = (t + 1 < nt);
        if (more) FETCH((t + 1) << 4);

        uint32_t aB  = aBaseS + cur * BUF_BYTES + aOff;
        uint32_t bB0 = bBaseS + cur * BUF_BYTES + bOff;
        uint32_t bB1 = bB0 + ((16 * 20) << 2);
        #pragma unroll
        for (int ks = 0; ks < 2; ks++) {
            uint32_t koff = (ks << 3) << 2;
            uint32_t ah[4], al[4], bh[2][4], bl[2][4];
            ldsm_x4(ah, aB + koff);
            ldsm_x4(al, aB + LO_BYTES + koff);
            ldsm_x4(bh[0], bB0 + koff);
            ldsm_x4(bl[0], bB0 + LO_BYTES + koff);
            ldsm_x4(bh[1], bB1 + koff);
            ldsm_x4(bl[1], bB1 + LO_BYTES + koff);
            #pragma unroll
            for (int p = 0; p < 2; p++)
                #pragma unroll
                for (int half = 0; half < 2; half++) {
                    int ns = (p << 1) + half;
                    const uint32_t bfh[2] = {bh[p][half << 1], bh[p][(half << 1) + 1]};
                    const uint32_t bfl[2] = {bl[p][half << 1], bl[p][(half << 1) + 1]};
                    mma_tf32(acc[ns], ah, bfh);
                    mma_tf32(acc[ns], ah, bfl);
                    mma_tf32(acc[ns], al, bfh);
                }
        }
        if (more) STORE(cur ^ 1);
        __syncthreads();
    }

    float* Cp = C + (size_t)blockIdx.z * M * N;
    int r0 = bm + warpM + g;
    #pragma unroll
    for (int ns = 0; ns < 4; ns++) {
        int c0 = bn + warpN + (ns << 3) + (tig << 1);
        size_t o0 = (size_t)r0 * N + c0, o2 = (size_t)(r0 + 8) * N + c0;
        Cp[o0] = acc[ns][0]; Cp[o0 + 1] = acc[ns][1];
        Cp[o2] = acc[ns][2]; Cp[o2 + 1] = acc[ns][3];
    }
}

// =======================================================================
// GEMM for transposed-B (B row-major [K,N]) with split-K; partial out.
// =======================================================================
__global__ __launch_bounds__(256)
void gemm_t(const float* __restrict__ Af, const float* __restrict__ Bf,
            float* __restrict__ C, int M, int N, int K, int ldb, int kChunk)
{
    __shared__ uint32_t sA[2][64][36];
    __shared__ uint32_t sB[2][64][36];

    int tid  = threadIdx.x;
    int lane = tid & 31, wid = tid >> 5;
    int warpM = (wid >> 1) << 4;
    int warpN = (wid & 1) << 5;
    int g = lane >> 2, tig = lane & 3;
    int bm = blockIdx.y << 6, bn = blockIdx.x << 6;
    int kBeg = blockIdx.z * kChunk;

    uint32_t aBase = smem_u32(&sA[0][0][0]) +
        (((warpM + (lane & 15)) * 36 + ((lane >> 4) << 2)) << 2);
    uint32_t bBase0 = smem_u32(&sB[0][0][0]) +
        (((warpN + ((lane >> 4) << 3) + (lane & 7)) * 36 + (((lane >> 3) & 1) << 2)) << 2);
    uint32_t bBase1 = bBase0 + (16 * 36 << 2);
    const uint32_t LO = (64 * 36) << 2;

    float acc[4][4];
    #pragma unroll
    for (int ns = 0; ns < 4; ns++)
        #pragma unroll
        for (int r = 0; r < 4; r++) acc[ns][r] = 0.f;

    float4 pA[2], pB[2];
    #pragma unroll
    for (int q = 0; q < 2; q++) {
        int idx = tid + (q << 8);
        int row = idx >> 3, kc = (idx & 7) << 2;
        pA[q] = *(const float4*)(Af + (size_t)(bm + row) * K + kBeg + kc);
        int k = idx >> 4, n0 = (idx & 15) << 2;
        pB[q] = *(const float4*)(Bf + (size_t)(kBeg + k) * ldb + bn + n0);
    }

    for (int kt = 0; kt < kChunk; kt += 32) {
        #pragma unroll
        for (int q = 0; q < 2; q++) {
            int idx = tid + (q << 8);
            {
                int row = idx >> 3, kc = (idx & 7) << 2;
                uint4 hi, lo;
                tf32split(pA[q].x, hi.x, lo.x); tf32split(pA[q].y, hi.y, lo.y);
                tf32split(pA[q].z, hi.z, lo.z); tf32split(pA[q].w, hi.w, lo.w);
                *(uint4*)&sA[0][row][kc] = hi;
                *(uint4*)&sA[1][row][kc] = lo;
            }
            {
                int k = idx >> 4, n0 = (idx & 15) << 2;
                float v[4] = {pB[q].x, pB[q].y, pB[q].z, pB[q].w};
                #pragma unroll
                for (int j = 0; j < 4; j++) {
                    uint32_t hb, lb; tf32split(v[j], hb, lb);
                    sB[0][n0 + j][k] = hb; sB[1][n0 + j][k] = lb;
                }
            }
        }
        __syncthreads();

        int ktn = kt + 32;
        if (ktn < kChunk) {
            #pragma unroll
            for (int q = 0; q < 2; q++) {
                int idx = tid + (q << 8);
                int row = idx >> 3, kc = (idx & 7) << 2;
                pA[q] = *(const float4*)(Af + (size_t)(bm + row) * K + kBeg + ktn + kc);
                int k = idx >> 4, n0 = (idx & 15) << 2;
                pB[q] = *(const float4*)(Bf + (size_t)(kBeg + ktn + k) * ldb + bn + n0);
            }
        }

        #pragma unroll
        for (int ks = 0; ks < 4; ks++) {
            uint32_t koff = (ks << 3) << 2;
            uint32_t ah[4], al[4], bh[2][4], bl[2][4];
            ldsm_x4(ah, aBase + koff);
            ldsm_x4(al, aBase + LO + koff);
            ldsm_x4(bh[0], bBase0 + koff);
            ldsm_x4(bl[0], bBase0 + LO + koff);
            ldsm_x4(bh[1], bBase1 + koff);
            ldsm_x4(bl[1], bBase1 + LO + koff);
            #pragma unroll
            for (int p = 0; p < 2; p++)
                #pragma unroll
                for (int half = 0; half < 2; half++) {
                    int ns = (p << 1) + half;
                    const uint32_t bfh[2] = {bh[p][half << 1], bh[p][(half << 1) + 1]};
                    const uint32_t bfl[2] = {bl[p][half << 1], bl[p][(half << 1) + 1]};
                    mma_tf32(acc[ns], ah, bfh);
                    mma_tf32(acc[ns], ah, bfl);
                    mma_tf32(acc[ns], al, bfh);
                }
        }
        __syncthreads();
    }

    float* Cp = C + (size_t)blockIdx.z * M * N;
    int r0 = bm + warpM + g;
    #pragma unroll
    for (int ns = 0; ns < 4; ns++) {
        int c0 = bn + warpN + (ns << 3) + (tig << 1);
        size_t o0 = (size_t)r0 * N + c0, o2 = (size_t)(r0 + 8) * N + c0;
        Cp[o0] = acc[ns][0]; Cp[o0 + 1] = acc[ns][1];
        Cp[o2] = acc[ns][2]; Cp[o2 + 1] = acc[ns][3];
    }
}

// =======================================================================
// Reduce split-K partials + bias (+relu)
// =======================================================================
__global__ __launch_bounds__(256)
void reduceSK(const float* __restrict__ part, int S, int plane,
              const float* __restrict__ bias, int act,
              float* __restrict__ out, int total, int N)
{
    int idx = blockIdx.x * 256 + threadIdx.x;
    if (idx >= total) return;
    float v = bias[idx % N];
    for (int s = 0; s < S; s++) v += part[(size_t)s * plane + idx];
    if (act) v = fmaxf(v, 0.f);
    out[idx] = v;
}

// =======================================================================
// GRU gates (hidden==0): reduce S split-K partials + bih + bhh; h=(1-z)n
// =======================================================================
__global__ __launch_bounds__(256)
void gru_gatesS(const float* __restrict__ gip, int S,
                const float* __restrict__ bih, const float* __restrict__ bhh,
                float* __restrict__ h)
{
    int idx = blockIdx.x * 256 + threadIdx.x;
    int b = idx >> 8, j = idx & 255;
    const float* g0 = gip + (size_t)b * G3;
    const size_t P = (size_t)BB * G3;
    float vr = bih[j], vz = bih[256 + j], vn = bih[512 + j];
    for (int s = 0; s < S; s++) {
        vr += g0[s * P + j];
        vz += g0[s * P + 256 + j];
        vn += g0[s * P + 512 + j];
    }
    float r = 1.f / (1.f + __expf(-(vr + bhh[j])));
    float z = 1.f / (1.f + __expf(-(vz + bhh[256 + j])));
    float n = tanhf(vn + r * bhh[512 + j]);
    h[idx] = (1.f - z) * n;
}

// =======================================================================
// LayerNorm over GRU dim
// =======================================================================
__global__ __launch_bounds__(256)
void ln1d_k(const float* __restrict__ h, const float* __restrict__ g,
            const float* __restrict__ b, float* __restrict__ o)
{
    __shared__ float s1[8], s2[8], mv[2];
    int row = blockIdx.x, tid = threadIdx.x;
    float v = h[(size_t)row * GRUU + tid];
    float s = v, q = v * v;
    #pragma unroll
    for (int off = 16; off; off >>= 1) {
        s += __shfl_xor_sync(0xffffffffu, s, off);
        q += __shfl_xor_sync(0xffffffffu, q, off);
    }
    if ((tid & 31) == 0) { s1[tid >> 5] = s; s2[tid >> 5] = q; }
    __syncthreads();
    if (tid == 0) {
        float S = 0.f, Q = 0.f;
        #pragma unroll
        for (int i = 0; i < 8; i++) { S += s1[i]; Q += s2[i]; }
        float m = S * (1.f / 256.f);
        float var = Q * (1.f / 256.f) - m * m;
        mv[0] = m; mv[1] = rsqrtf(var + 1e-5f);
    }
    __syncthreads();
    o[(size_t)row * GRUU + tid] = (v - mv[0]) * mv[1] * g[tid] + b[tid];
}

// =======================================================================
// host launcher
// =======================================================================
extern "C" void kernel_launch(void* const* d_in, const int* in_sizes, int n_in,
                              void* d_out, int out_size)
{
    const float* X    = (const float*)d_in[0];
    const int*   A    = (const int*)  d_in[1];
    const float* W1   = (const float*)d_in[2];
    const float* a1   = (const float*)d_in[3];
    const float* W2   = (const float*)d_in[4];
    const float* a2   = (const float*)d_in[5];
    const float* Wr   = (const float*)d_in[6];
    const float* br   = (const float*)d_in[7];
    const float* g1   = (const float*)d_in[8];
    const float* b1   = (const float*)d_in[9];
    const float* g2   = (const float*)d_in[10];
    const float* b2   = (const float*)d_in[11];
    const float* Wih0 = (const float*)d_in[12];
    const float* bih0 = (const float*)d_in[14];
    const float* bhh0 = (const float*)d_in[15];
    const float* Wih1 = (const float*)d_in[16];
    const float* bih1 = (const float*)d_in[18];
    const float* bhh1 = (const float*)d_in[19];
    const float* Wih2 = (const float*)d_in[20];
    const float* bih2 = (const float*)d_in[22];
    const float* bhh2 = (const float*)d_in[23];
    const float* gng  = (const float*)d_in[24];
    const float* gnb  = (const float*)d_in[25];
    const float* We   = (const float*)d_in[26];
    const float* be   = (const float*)d_in[27];
    const float* Wp   = (const float*)d_in[28];
    const float* bp   = (const float*)d_in[29];
    float* out = (float*)d_out;

    float *px, *pgip, *ph, *phln, *pemb;
    cudaGetSymbolAddress((void**)&px,   g_x);
    cudaGetSymbolAddress((void**)&pgip, g_gip);
    cudaGetSymbolAddress((void**)&ph,   g_h);
    cudaGetSymbolAddress((void**)&phln, g_hln);
    cudaGetSymbolAddress((void**)&pemb, g_emb);

    const int GAT_SMEM = (2176 + 6144 + 6272 + 4 * 768 + 2304 + 96 + 20 + 512) * 4;
    cudaFuncSetAttribute(gat_kernel, cudaFuncAttributeMaxDynamicSharedMemorySize, GAT_SMEM);
    cudaFuncSetAttribute(gemm_nk, cudaFuncAttributeMaxDynamicSharedMemorySize, GEMM_SMEM);

    gat_kernel<<<BB, TG, GAT_SMEM>>>(X, A, W1, a1, W2, a2, Wr, br, g1, b1, g2, b2);

    // GRU layer 0: split-K x8 (chunk 768 -> 48 BK16 tiles)
    dim3 g0(G3 / 64, BB / 64, SK0);
    gemm_nk<<<g0, 256, GEMM_SMEM>>>(px, Wih0, pgip, BB, G3, XG, XG / SK0);
    gru_gatesS<<<BB, 256>>>(pgip, SK0, bih0, bhh0, ph);

    // GRU layers 1 & 2: split-K x4 (chunk 64 -> 4 tiles)
    dim3 g12(G3 / 64, BB / 64, 4);
    gemm_nk<<<g12, 256, GEMM_SMEM>>>(ph, Wih1, pgip, BB, G3, GRUU, GRUU / 4);
    gru_gatesS<<<BB, 256>>>(pgip, 4, bih1, bhh1, ph);
    gemm_nk<<<g12, 256, GEMM_SMEM>>>(ph, Wih2, pgip, BB, G3, GRUU, GRUU / 4);
    gru_gatesS<<<BB, 256>>>(pgip, 4, bih2, bhh2, ph);

    ln1d_k<<<BB, 256>>>(ph, gng, gnb, phln);

    float* embp = (out_size >= 2 * BB * EMBB) ? (out + (size_t)BB * EMBB) : pemb;

    // emb = relu(hln @ We + be): split-K x4 (K=256, chunk 64)
    dim3 gEmb(EMBB / 64, BB / 64, 4);
    gemm_t<<<gEmb, 256>>>(phln, We, pgip, BB, EMBB, GRUU, EMBB, GRUU / 4);
    reduceSK<<<(BB * EMBB + 255) / 256, 256>>>(pgip, 4, BB * EMBB, be, 1,
                                               embp, BB * EMBB, EMBB);

    // pred = emb @ Wp + bp: split-K x2 (K=128, chunk 64)
    dim3 gPred(NN / 64, BB / 64, 2);
    gemm_t<<<gPred, 256>>>(embp, Wp, pgip, BB, NN, EMBB, NN, EMBB / 2);
    reduceSK<<<(BB * NN + 255) / 256, 256>>>(pgip, 2, BB * NN, bp, 0,
                                             out, BB * NN, NN);
}

// round 8
// speedup vs baseline: 1.1685x; 1.1685x over previous
#include <cuda_runtime.h>
#include <cstdint>

// ---------------- problem constants ----------------
#define BB   1024
#define NN   128
#define FF   16
#define GG   48
#define HH   6
#define DD   8
#define GRUU 256
#define EMBB 128
#define XG   (NN*GG)       // 6144
#define G3   (3*GRUU)      // 768
#define SPLITK 4

// ---------------- scratch ----------------
__device__ float g_x  [BB*XG];
__device__ float g_gip[SPLITK*BB*G3];
__device__ float g_h  [BB*GRUU];
__device__ float g_hln[BB*GRUU];
__device__ float g_emb[BB*EMBB];

// ---------------- helpers ----------------
__device__ __forceinline__ void tf32split(float v, uint32_t& h, uint32_t& l) {
    uint32_t hb; asm("cvt.rna.tf32.f32 %0, %1;" : "=r"(hb) : "f"(v));
    float lv = v - __uint_as_float(hb);
    uint32_t lb; asm("cvt.rna.tf32.f32 %0, %1;" : "=r"(lb) : "f"(lv));
    h = hb; l = lb;
}

__device__ __forceinline__ uint32_t tf32rna(float v) {
    uint32_t r; asm("cvt.rna.tf32.f32 %0, %1;" : "=r"(r) : "f"(v));
    return r;
}

__device__ __forceinline__ uint32_t smem_u32(const void* p) {
    uint32_t a;
    asm("{ .reg .u64 t; cvta.to.shared.u64 t, %1; cvt.u32.u64 %0, t; }" : "=r"(a) : "l"(p));
    return a;
}

__device__ __forceinline__ void ldsm_x4(uint32_t* d, uint32_t addr) {
    asm volatile("ldmatrix.sync.aligned.m8n8.x4.shared.b16 {%0,%1,%2,%3}, [%4];"
        : "=r"(d[0]), "=r"(d[1]), "=r"(d[2]), "=r"(d[3]) : "r"(addr));
}

__device__ __forceinline__ void mma_tf32(float* c, const uint32_t* a, const uint32_t* b) {
    asm volatile("mma.sync.aligned.m16n8k8.row.col.f32.tf32.tf32.f32 "
        "{%0,%1,%2,%3}, {%4,%5,%6,%7}, {%8,%9}, {%0,%1,%2,%3};\n"
        : "+f"(c[0]), "+f"(c[1]), "+f"(c[2]), "+f"(c[3])
        : "r"(a[0]), "r"(a[1]), "r"(a[2]), "r"(a[3]), "r"(b[0]), "r"(b[1]));
}

// =======================================================================
// GAT attention via tensor cores.
// 256 threads = 8 warps. 48 warp-tasks = (6 heads) x (8 m-tiles of 16 rows).
// SIMT computes w = masked(exp(lrelu(ei+ej))) directly in mma A-fragment
// layout (rank-1 exp trick), rounded to tf32; aggregation hp = w @ h done
// with 2 MMAs per 16x8 k-tile against pre-split h_hi/h_lo (exact V).
// Row sums accumulate on the SAME rounded w -> softmax exactly normalized.
//
// m16n8k8 fragments (thread: g = lane>>2, tig = lane&3):
//   A: a0=(g,tig) a1=(g+8,tig) a2=(g,tig+4) a3=(g+8,tig+4)
//   B: b0=(k=tig,n=g) b1=(k=tig+4,n=g)
//   C: c0=(g,2tig) c1=(g,2tig+1) c2=(g+8,2tig) c3=(g+8,2tig+1)
// =======================================================================
__device__ __forceinline__ void gat_attention_mma(
    const uint32_t* __restrict__ sh_hi, const uint32_t* __restrict__ sh_lo,
    const float* __restrict__ sei, const float* __restrict__ sej,
    const float* __restrict__ sPj, const float* __restrict__ sQj,
    const unsigned* __restrict__ smask, float* __restrict__ sy, int tid)
{
    int lane = tid & 31, wid = tid >> 5;
    int g = lane >> 2, tig = lane & 3;

    #pragma unroll 1
    for (int task = wid; task < 48; task += 8) {
        int hd = task >> 3, m0 = (task & 7) << 4;
        int r0 = m0 + g, r1 = r0 + 8;
        float ei0 = sei[(hd << 7) + r0], ei1 = sei[(hd << 7) + r1];
        float Pi0 = __expf(ei0), Qi0 = __expf(0.01f * ei0);
        float Pi1 = __expf(ei1), Qi1 = __expf(0.01f * ei1);
        const unsigned* mr0 = smask + (r0 << 2);
        const unsigned* mr1 = smask + (r1 << 2);
        const float* ejp = sej + (hd << 7);
        const float* Pjp = sPj + (hd << 7);
        const float* Qjp = sQj + (hd << 7);
        const uint32_t* hhi = sh_hi + (hd << 10);
        const uint32_t* hlo = sh_lo + (hd << 10);

        float c[4] = {0.f, 0.f, 0.f, 0.f};
        float ssum0 = 0.f, ssum1 = 0.f;

        #pragma unroll 1
        for (int jw = 0; jw < 4; jw++) {
            unsigned w0 = mr0[jw], w1 = mr1[jw];
            #pragma unroll
            for (int q = 0; q < 4; q++) {
                int j0 = (jw << 5) + (q << 3);
                unsigned mt0 = w0 >> ((q << 3) + tig);
                unsigned mt1 = w1 >> ((q << 3) + tig);
                int jA = j0 + tig, jB = jA + 4;
                float ejA = ejp[jA], ejB = ejp[jB];
                float PjA = Pjp[jA], PjB = Pjp[jB];
                float QjA = Qjp[jA], QjB = Qjp[jB];

                float wa0 = (ei0 + ejA > 0.f) ? (Pi0 * PjA) : (Qi0 * QjA);
                float wa1 = (ei1 + ejA > 0.f) ? (Pi1 * PjA) : (Qi1 * QjA);
                float wa2 = (ei0 + ejB > 0.f) ? (Pi0 * PjB) : (Qi0 * QjB);
                float wa3 = (ei1 + ejB > 0.f) ? (Pi1 * PjB) : (Qi1 * QjB);
                wa0 = (mt0 & 1u)  ? wa0 : 0.f;
                wa1 = (mt1 & 1u)  ? wa1 : 0.f;
                wa2 = (mt0 & 16u) ? wa2 : 0.f;
                wa3 = (mt1 & 16u) ? wa3 : 0.f;

                uint32_t a[4];
                a[0] = tf32rna(wa0); a[1] = tf32rna(wa1);
                a[2] = tf32rna(wa2); a[3] = tf32rna(wa3);
                ssum0 += __uint_as_float(a[0]) + __uint_as_float(a[2]);
                ssum1 += __uint_as_float(a[1]) + __uint_as_float(a[3]);

                uint32_t bh[2] = { hhi[(jA << 3) + g], hhi[(jB << 3) + g] };
                uint32_t bl[2] = { hlo[(jA << 3) + g], hlo[(jB << 3) + g] };
                mma_tf32(c, a, bh);
                mma_tf32(c, a, bl);
            }
        }
        // full row sums: reduce across tig lanes (same g group)
        ssum0 += __shfl_xor_sync(0xffffffffu, ssum0, 1);
        ssum0 += __shfl_xor_sync(0xffffffffu, ssum0, 2);
        ssum1 += __shfl_xor_sync(0xffffffffu, ssum1, 1);
        ssum1 += __shfl_xor_sync(0xffffffffu, ssum1, 2);
        float inv0 = 1.0f / ssum0, inv1 = 1.0f / ssum1;

        float* o0 = sy + r0 * 49 + (hd << 3) + (tig << 1);
        float* o1 = sy + r1 * 49 + (hd << 3) + (tig << 1);
        o0[0] = c[0] * inv0; o0[1] = c[1] * inv0;
        o1[0] = c[2] * inv1; o1[1] = c[3] * inv1;
    }
}

// LayerNorm over all [N,G] of one batch, + ReLU. sy row stride 49. 8 warps.
__device__ __forceinline__ void ln2d_apply(
    float* __restrict__ sy, const float* __restrict__ gamma,
    const float* __restrict__ beta, float* __restrict__ sred,
    int tid, float* __restrict__ gout)
{
    float s = 0.f, q = 0.f;
    for (int t = tid; t < XG; t += 256) {
        int n = t / 48, c = t - n * 48;
        float v = sy[n * 49 + c];
        s += v; q += v * v;
    }
    #pragma unroll
    for (int o = 16; o; o >>= 1) {
        s += __shfl_xor_sync(0xffffffffu, s, o);
        q += __shfl_xor_sync(0xffffffffu, q, o);
    }
    int wid = tid >> 5;
    if ((tid & 31) == 0) { sred[wid] = s; sred[8 + wid] = q; }
    __syncthreads();
    if (tid == 0) {
        float S = 0.f, Q = 0.f;
        #pragma unroll
        for (int i = 0; i < 8; i++) { S += sred[i]; Q += sred[8 + i]; }
        float m   = S * (1.f / (float)XG);
        float var = Q * (1.f / (float)XG) - m * m;
        sred[16] = m;
        sred[17] = rsqrtf(var + 1e-5f);
    }
    __syncthreads();
    float m = sred[16], rs = sred[17];
    for (int t = tid; t < XG; t += 256) {
        int n = t / 48, c = t - n * 48;
        float v = (sy[n * 49 + c] - m) * rs * gamma[t] + beta[t];
        v = fmaxf(v, 0.f);
        if (gout) gout[t] = v; else sy[n * 49 + c] = v;
    }
}

// GAT smem layout (words)
#define S_X    0
#define S_HHI  2176
#define S_HLO  (S_HHI + 6144)
#define S_Y    (S_HLO + 6144)
#define S_EI   (S_Y + 6272)
#define S_EJ   (S_EI + 768)
#define S_PJ   (S_EJ + 768)
#define S_QJ   (S_PJ + 768)
#define S_W    (S_QJ + 768)
#define S_A    (S_W + 2304)
#define S_RED  (S_A + 96)
#define S_MASK (S_RED + 20)
#define GAT_WORDS (S_MASK + 512)

__global__ __launch_bounds__(256)
void gat_kernel(const float* __restrict__ X,  const int* __restrict__ A,
                const float* __restrict__ W1, const float* __restrict__ a1,
                const float* __restrict__ W2, const float* __restrict__ a2,
                const float* __restrict__ Wr, const float* __restrict__ br,
                const float* __restrict__ g1, const float* __restrict__ b1,
                const float* __restrict__ g2, const float* __restrict__ b2)
{
    extern __shared__ float sm[];
    float*    sX    = sm + S_X;
    uint32_t* sh_hi = (uint32_t*)(sm + S_HHI);
    uint32_t* sh_lo = (uint32_t*)(sm + S_HLO);
    float*    sy    = sm + S_Y;
    float*    sei   = sm + S_EI;
    float*    sej   = sm + S_EJ;
    float*    sPj   = sm + S_PJ;
    float*    sQj   = sm + S_QJ;
    float*    sW    = sm + S_W;
    float*    sa    = sm + S_A;
    float*    sred  = sm + S_RED;
    unsigned* smask = (unsigned*)(sm + S_MASK);

    int b = blockIdx.x, tid = threadIdx.x;

    const float* Xb = X + (size_t)b * (NN * FF);
    for (int t = tid; t < NN * FF; t += 256)
        sX[(t >> 4) * 17 + (t & 15)] = Xb[t];

    {
        const int* Ab = A + (size_t)b * (NN * NN);
        int lane = tid & 31, wid = tid >> 5;
        for (int w = wid; w < 512; w += 8) {
            int i = w >> 2, j0 = (w & 3) << 5;
            unsigned bits = __ballot_sync(0xffffffffu, Ab[(i << 7) + j0 + lane] != 0);
            if (lane == 0) smask[w] = bits;
        }
    }
    for (int t = tid; t < HH * FF * DD; t += 256) sW[t] = W1[t];
    if (tid < HH * 2 * DD) sa[tid] = a1[tid];
    __syncthreads();

    // ---- layer 1: h = X@W1 (split to hi/lo), scores, per-node exps ----
    for (int t = tid; t < HH * NN; t += 256) {
        int hd = t >> 7, n = t & 127;
        float acc[8];
        #pragma unroll
        for (int d = 0; d < 8; d++) acc[d] = 0.f;
        const float* w = sW + hd * (FF * DD);
        const float* x = sX + n * 17;
        #pragma unroll
        for (int f = 0; f < FF; f++) {
            float xv = x[f];
            #pragma unroll
            for (int d = 0; d < 8; d++) acc[d] = fmaf(xv, w[(f << 3) + d], acc[d]);
        }
        const float* av = sa + (hd << 4);
        float ei = 0.f, ej = 0.f;
        #pragma unroll
        for (int d = 0; d < 8; d++) { ei = fmaf(acc[d], av[d], ei); ej = fmaf(acc[d], av[8 + d], ej); }
        #pragma unroll
        for (int d = 0; d < 8; d++) {
            uint32_t hb, lb; tf32split(acc[d], hb, lb);
            sh_hi[(t << 3) + d] = hb; sh_lo[(t << 3) + d] = lb;
        }
        sei[t] = ei; sej[t] = ej;
        sPj[t] = __expf(ej); sQj[t] = __expf(0.01f * ej);
    }
    __syncthreads();
    gat_attention_mma(sh_hi, sh_lo, sei, sej, sPj, sQj, smask, sy, tid);
    __syncthreads();
    ln2d_apply(sy, g1, b1, sred, tid, nullptr);
    __syncthreads();

    // ---- layer 2 weights ----
    for (int t = tid; t < HH * GG * DD; t += 256) sW[t] = W2[t];
    if (tid < HH * 2 * DD) sa[tid] = a2[tid];
    __syncthreads();

    // ---- layer 2: h2 = y@W2 ----
    for (int t = tid; t < HH * NN; t += 256) {
        int hd = t >> 7, n = t & 127;
        float acc[8];
        #pragma unroll
        for (int d = 0; d < 8; d++) acc[d] = 0.f;
        const float* w = sW + hd * (GG * DD);
        const float* x = sy + n * 49;
        #pragma unroll
        for (int f = 0; f < GG; f++) {
            float xv = x[f];
            #pragma unroll
            for (int d = 0; d < 8; d++) acc[d] = fmaf(xv, w[(f << 3) + d], acc[d]);
        }
        const float* av = sa + (hd << 4);
        float ei = 0.f, ej = 0.f;
        #pragma unroll
        for (int d = 0; d < 8; d++) { ei = fmaf(acc[d], av[d], ei); ej = fmaf(acc[d], av[8 + d], ej); }
        #pragma unroll
        for (int d = 0; d < 8; d++) {
            uint32_t hb, lb; tf32split(acc[d], hb, lb);
            sh_hi[(t << 3) + d] = hb; sh_lo[(t << 3) + d] = lb;
        }
        sei[t] = ei; sej[t] = ej;
        sPj[t] = __expf(ej); sQj[t] = __expf(0.01f * ej);
    }
    __syncthreads();
    gat_attention_mma(sh_hi, sh_lo, sei, sej, sPj, sQj, smask, sy, tid);
    __syncthreads();

    // ---- residual: sy += X@Wr + br ----
    for (int t = tid; t < FF * GG; t += 256) sW[t] = Wr[t];
    if (tid < GG) sa[tid] = br[tid];
    __syncthreads();
    for (int t = tid; t < XG; t += 256) {
        int n = t / 48, c = t - n * 48;
        float accv = sa[c];
        const float* x = sX + n * 17;
        #pragma unroll
        for (int f = 0; f < FF; f++) accv = fmaf(x[f], sW[f * 48 + c], accv);
        sy[n * 49 + c] += accv;
    }
    __syncthreads();
    ln2d_apply(sy, g2, b2, sred, tid, g_x + (size_t)b * XG);
}

// =======================================================================
// Double-buffered 3xTF32 GEMM, BK=32 (R5/R6 proven body).
// B row-major [N,K]. Split-K via grid.z -> partial C at z*M*N.
// =======================================================================
#define PLANE_W   (64*36)
#define BUF_W     (2*PLANE_W)
#define LO_BYTES  (PLANE_W*4)
#define BUF_BYTES (BUF_W*4)
#define GEMM_SMEM (4*BUF_BYTES)   // 73728

__global__ __launch_bounds__(256)
void gemm_nk(const float* __restrict__ Af, const float* __restrict__ Bf,
             float* __restrict__ C, int M, int N, int K, int kChunk)
{
    extern __shared__ uint32_t smem[];
    uint32_t* sA = smem;
    uint32_t* sB = smem + 2 * BUF_W;

    int tid  = threadIdx.x;
    int lane = tid & 31, wid = tid >> 5;
    int warpM = (wid >> 1) << 4;
    int warpN = (wid & 1) << 5;
    int g = lane >> 2, tig = lane & 3;
    int bm = blockIdx.y << 6, bn = blockIdx.x << 6;
    int kBeg = blockIdx.z * kChunk;
    int nt   = kChunk >> 5;

    uint32_t aOff = (((warpM + (lane & 15)) * 36 + ((lane >> 4) << 2)) << 2);
    uint32_t bOff = (((warpN + ((lane >> 4) << 3) + (lane & 7)) * 36 + (((lane >> 3) & 1) << 2)) << 2);
    uint32_t aBaseS = smem_u32(sA);
    uint32_t bBaseS = smem_u32(sB);

    int frow = tid >> 3;
    int fkc  = (tid & 7) << 2;

    float acc[4][4];
    #pragma unroll
    for (int ns = 0; ns < 4; ns++)
        #pragma unroll
        for (int r = 0; r < 4; r++) acc[ns][r] = 0.f;

    float4 pA[2], pB[2];

    auto FETCH = [&](int kt) {
        #pragma unroll
        for (int q = 0; q < 2; q++) {
            int row = frow + (q << 5);
            pA[q] = *(const float4*)(Af + (size_t)(bm + row) * K + kBeg + kt + fkc);
            pB[q] = *(const float4*)(Bf + (size_t)(bn + row) * K + kBeg + kt + fkc);
        }
    };
    auto STORE = [&](int buf) {
        uint32_t* dA = sA + buf * BUF_W;
        uint32_t* dB = sB + buf * BUF_W;
        #pragma unroll
        for (int q = 0; q < 2; q++) {
            int row = frow + (q << 5);
            uint4 hi, lo;
            tf32split(pA[q].x, hi.x, lo.x); tf32split(pA[q].y, hi.y, lo.y);
            tf32split(pA[q].z, hi.z, lo.z); tf32split(pA[q].w, hi.w, lo.w);
            *(uint4*)(dA + row * 36 + fkc)           = hi;
            *(uint4*)(dA + PLANE_W + row * 36 + fkc) = lo;
            tf32split(pB[q].x, hi.x, lo.x); tf32split(pB[q].y, hi.y, lo.y);
            tf32split(pB[q].z, hi.z, lo.z); tf32split(pB[q].w, hi.w, lo.w);
            *(uint4*)(dB + row * 36 + fkc)           = hi;
            *(uint4*)(dB + PLANE_W + row * 36 + fkc) = lo;
        }
    };

    FETCH(0);
    STORE(0);
    __syncthreads();

    for (int t = 0; t < nt; t++) {
        int cur = t & 1;
        bool more = (t + 1 < nt);
        if (more) FETCH((t + 1) << 5);

        uint32_t aB  = aBaseS + cur * BUF_BYTES + aOff;
        uint32_t bB0 = bBaseS + cur * BUF_BYTES + bOff;
        uint32_t bB1 = bB0 + ((16 * 36) << 2);
        #pragma unroll
        for (int ks = 0; ks < 4; ks++) {
            uint32_t koff = (ks << 3) << 2;
            uint32_t ah[4], al[4], bh[2][4], bl[2][4];
            ldsm_x4(ah, aB + koff);
            ldsm_x4(al, aB + LO_BYTES + koff);
            ldsm_x4(bh[0], bB0 + koff);
            ldsm_x4(bl[0], bB0 + LO_BYTES + koff);
            ldsm_x4(bh[1], bB1 + koff);
            ldsm_x4(bl[1], bB1 + LO_BYTES + koff);
            #pragma unroll
            for (int p = 0; p < 2; p++)
                #pragma unroll
                for (int half = 0; half < 2; half++) {
                    int ns = (p << 1) + half;
                    const uint32_t bfh[2] = {bh[p][half << 1], bh[p][(half << 1) + 1]};
                    const uint32_t bfl[2] = {bl[p][half << 1], bl[p][(half << 1) + 1]};
                    mma_tf32(acc[ns], ah, bfh);
                    mma_tf32(acc[ns], ah, bfl);
                    mma_tf32(acc[ns], al, bfh);
                }
        }
        if (more) STORE(cur ^ 1);
        __syncthreads();
    }

    float* Cp = C + (size_t)blockIdx.z * M * N;
    int r0 = bm + warpM + g;
    #pragma unroll
    for (int ns = 0; ns < 4; ns++) {
        int c0 = bn + warpN + (ns << 3) + (tig << 1);
        size_t o0 = (size_t)r0 * N + c0, o2 = (size_t)(r0 + 8) * N + c0;
        Cp[o0] = acc[ns][0]; Cp[o0 + 1] = acc[ns][1];
        Cp[o2] = acc[ns][2]; Cp[o2 + 1] = acc[ns][3];
    }
}

// =======================================================================
// GEMM for transposed-B (B row-major [K,N]) with split-K; partial out.
// =======================================================================
__global__ __launch_bounds__(256)
void gemm_t(const float* __restrict__ Af, const float* __restrict__ Bf,
            float* __restrict__ C, int M, int N, int K, int ldb, int kChunk)
{
    __shared__ uint32_t sA[2][64][36];
    __shared__ uint32_t sB[2][64][36];

    int tid  = threadIdx.x;
    int lane = tid & 31, wid = tid >> 5;
    int warpM = (wid >> 1) << 4;
    int warpN = (wid & 1) << 5;
    int g = lane >> 2, tig = lane & 3;
    int bm = blockIdx.y << 6, bn = blockIdx.x << 6;
    int kBeg = blockIdx.z * kChunk;

    uint32_t aBase = smem_u32(&sA[0][0][0]) +
        (((warpM + (lane & 15)) * 36 + ((lane >> 4) << 2)) << 2);
    uint32_t bBase0 = smem_u32(&sB[0][0][0]) +
        (((warpN + ((lane >> 4) << 3) + (lane & 7)) * 36 + (((lane >> 3) & 1) << 2)) << 2);
    uint32_t bBase1 = bBase0 + (16 * 36 << 2);
    const uint32_t LO = (64 * 36) << 2;

    float acc[4][4];
    #pragma unroll
    for (int ns = 0; ns < 4; ns++)
        #pragma unroll
        for (int r = 0; r < 4; r++) acc[ns][r] = 0.f;

    float4 pA[2], pB[2];
    #pragma unroll
    for (int q = 0; q < 2; q++) {
        int idx = tid + (q << 8);
        int row = idx >> 3, kc = (idx & 7) << 2;
        pA[q] = *(const float4*)(Af + (size_t)(bm + row) * K + kBeg + kc);
        int k = idx >> 4, n0 = (idx & 15) << 2;
        pB[q] = *(const float4*)(Bf + (size_t)(kBeg + k) * ldb + bn + n0);
    }

    for (int kt = 0; kt < kChunk; kt += 32) {
        #pragma unroll
        for (int q = 0; q < 2; q++) {
            int idx = tid + (q << 8);
            {
                int row = idx >> 3, kc = (idx & 7) << 2;
                uint4 hi, lo;
                tf32split(pA[q].x, hi.x, lo.x); tf32split(pA[q].y, hi.y, lo.y);
                tf32split(pA[q].z, hi.z, lo.z); tf32split(pA[q].w, hi.w, lo.w);
                *(uint4*)&sA[0][row][kc] = hi;
                *(uint4*)&sA[1][row][kc] = lo;
            }
            {
                int k = idx >> 4, n0 = (idx & 15) << 2;
                float v[4] = {pB[q].x, pB[q].y, pB[q].z, pB[q].w};
                #pragma unroll
                for (int j = 0; j < 4; j++) {
                    uint32_t hb, lb; tf32split(v[j], hb, lb);
                    sB[0][n0 + j][k] = hb; sB[1][n0 + j][k] = lb;
                }
            }
        }
        __syncthreads();

        int ktn = kt + 32;
        if (ktn < kChunk) {
            #pragma unroll
            for (int q = 0; q < 2; q++) {
                int idx = tid + (q << 8);
                int row = idx >> 3, kc = (idx & 7) << 2;
                pA[q] = *(const float4*)(Af + (size_t)(bm + row) * K + kBeg + ktn + kc);
                int k = idx >> 4, n0 = (idx & 15) << 2;
                pB[q] = *(const float4*)(Bf + (size_t)(kBeg + ktn + k) * ldb + bn + n0);
            }
        }

        #pragma unroll
        for (int ks = 0; ks < 4; ks++) {
            uint32_t koff = (ks << 3) << 2;
            uint32_t ah[4], al[4], bh[2][4], bl[2][4];
            ldsm_x4(ah, aBase + koff);
            ldsm_x4(al, aBase + LO + koff);
            ldsm_x4(bh[0], bBase0 + koff);
            ldsm_x4(bl[0], bBase0 + LO + koff);
            ldsm_x4(bh[1], bBase1 + koff);
            ldsm_x4(bl[1], bBase1 + LO + koff);
            #pragma unroll
            for (int p = 0; p < 2; p++)
                #pragma unroll
                for (int half = 0; half < 2; half++) {
                    int ns = (p << 1) + half;
                    const uint32_t bfh[2] = {bh[p][half << 1], bh[p][(half << 1) + 1]};
                    const uint32_t bfl[2] = {bl[p][half << 1], bl[p][(half << 1) + 1]};
                    mma_tf32(acc[ns], ah, bfh);
                    mma_tf32(acc[ns], ah, bfl);
                    mma_tf32(acc[ns], al, bfh);
                }
        }
        __syncthreads();
    }

    float* Cp = C + (size_t)blockIdx.z * M * N;
    int r0 = bm + warpM + g;
    #pragma unroll
    for (int ns = 0; ns < 4; ns++) {
        int c0 = bn + warpN + (ns << 3) + (tig << 1);
        size_t o0 = (size_t)r0 * N + c0, o2 = (size_t)(r0 + 8) * N + c0;
        Cp[o0] = acc[ns][0]; Cp[o0 + 1] = acc[ns][1];
        Cp[o2] = acc[ns][2]; Cp[o2 + 1] = acc[ns][3];
    }
}

// =======================================================================
// Reduce split-K partials + bias (+relu)
// =======================================================================
__global__ __launch_bounds__(256)
void reduceSK(const float* __restrict__ part, int S, int plane,
              const float* __restrict__ bias, int act,
              float* __restrict__ out, int total, int N)
{
    int idx = blockIdx.x * 256 + threadIdx.x;
    if (idx >= total) return;
    float v = bias[idx % N];
    for (int s = 0; s < S; s++) v += part[(size_t)s * plane + idx];
    if (act) v = fmaxf(v, 0.f);
    out[idx] = v;
}

// =======================================================================
// GRU gates (hidden==0): reduce S split-K partials + bih + bhh; h=(1-z)n
// =======================================================================
__global__ __launch_bounds__(256)
void gru_gatesS(const float* __restrict__ gip, int S,
                const float* __restrict__ bih, const float* __restrict__ bhh,
                float* __restrict__ h)
{
    int idx = blockIdx.x * 256 + threadIdx.x;
    int b = idx >> 8, j = idx & 255;
    const float* g0 = gip + (size_t)b * G3;
    const size_t P = (size_t)BB * G3;
    float vr = bih[j], vz = bih[256 + j], vn = bih[512 + j];
    for (int s = 0; s < S; s++) {
        vr += g0[s * P + j];
        vz += g0[s * P + 256 + j];
        vn += g0[s * P + 512 + j];
    }
    float r = 1.f / (1.f + __expf(-(vr + bhh[j])));
    float z = 1.f / (1.f + __expf(-(vz + bhh[256 + j])));
    float n = tanhf(vn + r * bhh[512 + j]);
    h[idx] = (1.f - z) * n;
}

// =======================================================================
// LayerNorm over GRU dim
// =======================================================================
__global__ __launch_bounds__(256)
void ln1d_k(const float* __restrict__ h, const float* __restrict__ g,
            const float* __restrict__ b, float* __restrict__ o)
{
    __shared__ float s1[8], s2[8], mv[2];
    int row = blockIdx.x, tid = threadIdx.x;
    float v = h[(size_t)row * GRUU + tid];
    float s = v, q = v * v;
    #pragma unroll
    for (int off = 16; off; off >>= 1) {
        s += __shfl_xor_sync(0xffffffffu, s, off);
        q += __shfl_xor_sync(0xffffffffu, q, off);
    }
    if ((tid & 31) == 0) { s1[tid >> 5] = s; s2[tid >> 5] = q; }
    __syncthreads();
    if (tid == 0) {
        float S = 0.f, Q = 0.f;
        #pragma unroll
        for (int i = 0; i < 8; i++) { S += s1[i]; Q += s2[i]; }
        float m = S * (1.f / 256.f);
        float var = Q * (1.f / 256.f) - m * m;
        mv[0] = m; mv[1] = rsqrtf(var + 1e-5f);
    }
    __syncthreads();
    o[(size_t)row * GRUU + tid] = (v - mv[0]) * mv[1] * g[tid] + b[tid];
}

// =======================================================================
// host launcher
// =======================================================================
extern "C" void kernel_launch(void* const* d_in, const int* in_sizes, int n_in,
                              void* d_out, int out_size)
{
    const float* X    = (const float*)d_in[0];
    const int*   A    = (const int*)  d_in[1];
    const float* W1   = (const float*)d_in[2];
    const float* a1   = (const float*)d_in[3];
    const float* W2   = (const float*)d_in[4];
    const float* a2   = (const float*)d_in[5];
    const float* Wr   = (const float*)d_in[6];
    const float* br   = (const float*)d_in[7];
    const float* g1   = (const float*)d_in[8];
    const float* b1   = (const float*)d_in[9];
    const float* g2   = (const float*)d_in[10];
    const float* b2   = (const float*)d_in[11];
    const float* Wih0 = (const float*)d_in[12];
    const float* bih0 = (const float*)d_in[14];
    const float* bhh0 = (const float*)d_in[15];
    const float* Wih1 = (const float*)d_in[16];
    const float* bih1 = (const float*)d_in[18];
    const float* bhh1 = (const float*)d_in[19];
    const float* Wih2 = (const float*)d_in[20];
    const float* bih2 = (const float*)d_in[22];
    const float* bhh2 = (const float*)d_in[23];
    const float* gng  = (const float*)d_in[24];
    const float* gnb  = (const float*)d_in[25];
    const float* We   = (const float*)d_in[26];
    const float* be   = (const float*)d_in[27];
    const float* Wp   = (const float*)d_in[28];
    const float* bp   = (const float*)d_in[29];
    float* out = (float*)d_out;

    float *px, *pgip, *ph, *phln, *pemb;
    cudaGetSymbolAddress((void**)&px,   g_x);
    cudaGetSymbolAddress((void**)&pgip, g_gip);
    cudaGetSymbolAddress((void**)&ph,   g_h);
    cudaGetSymbolAddress((void**)&phln, g_hln);
    cudaGetSymbolAddress((void**)&pemb, g_emb);

    const int GAT_SMEM = GAT_WORDS * 4;
    cudaFuncSetAttribute(gat_kernel, cudaFuncAttributeMaxDynamicSharedMemorySize, GAT_SMEM);
    cudaFuncSetAttribute(gemm_nk, cudaFuncAttributeMaxDynamicSharedMemorySize, GEMM_SMEM);

    gat_kernel<<<BB, 256, GAT_SMEM>>>(X, A, W1, a1, W2, a2, Wr, br, g1, b1, g2, b2);

    // GRU layer 0: split-K x4 (chunk 1536 -> 48 BK32 tiles)
    dim3 g0(G3 / 64, BB / 64, SPLITK);
    gemm_nk<<<g0, 256, GEMM_SMEM>>>(px, Wih0, pgip, BB, G3, XG, XG / SPLITK);
    gru_gatesS<<<BB, 256>>>(pgip, SPLITK, bih0, bhh0, ph);

    // GRU layers 1 & 2: split-K x2 (chunk 128 -> 4 tiles)
    dim3 g12(G3 / 64, BB / 64, 2);
    gemm_nk<<<g12, 256, GEMM_SMEM>>>(ph, Wih1, pgip, BB, G3, GRUU, GRUU / 2);
    gru_gatesS<<<BB, 256>>>(pgip, 2, bih1, bhh1, ph);
    gemm_nk<<<g12, 256, GEMM_SMEM>>>(ph, Wih2, pgip, BB, G3, GRUU, GRUU / 2);
    gru_gatesS<<<BB, 256>>>(pgip, 2, bih2, bhh2, ph);

    ln1d_k<<<BB, 256>>>(ph, gng, gnb, phln);

    float* embp = (out_size >= 2 * BB * EMBB) ? (out + (size_t)BB * EMBB) : pemb;

    // emb = relu(hln @ We + be): split-K x4 (K=256, chunk 64)
    dim3 gEmb(EMBB / 64, BB / 64, 4);
    gemm_t<<<gEmb, 256>>>(phln, We, pgip, BB, EMBB, GRUU, EMBB, GRUU / 4);
    reduceSK<<<(BB * EMBB + 255) / 256, 256>>>(pgip, 4, BB * EMBB, be, 1,
                                               embp, BB * EMBB, EMBB);

    // pred = emb @ Wp + bp: split-K x2 (K=128, chunk 64)
    dim3 gPred(NN / 64, BB / 64, 2);
    gemm_t<<<gPred, 256>>>(embp, Wp, pgip, BB, NN, EMBB, NN, EMBB / 2);
    reduceSK<<<(BB * NN + 255) / 256, 256>>>(pgip, 2, BB * NN, bp, 0,
                                             out, BB * NN, NN);
}

// round 9
// speedup vs baseline: 1.3005x; 1.1130x over previous
#include <cuda_runtime.h>
#include <cstdint>

// ---------------- problem constants ----------------
#define BB   1024
#define NN   128
#define FF   16
#define GG   48
#define HH   6
#define DD   8
#define GRUU 256
#define EMBB 128
#define XG   (NN*GG)       // 6144
#define G3   (3*GRUU)      // 768
#define SK0  8             // split-K for GRU0

// ---------------- scratch ----------------
__device__ float g_x  [BB*XG];
__device__ float g_gip[SK0*BB*G3];
__device__ float g_h  [BB*GRUU];
__device__ float g_hln[BB*GRUU];
__device__ float g_emb[BB*EMBB];

// ---------------- helpers ----------------
__device__ __forceinline__ void tf32split(float v, uint32_t& h, uint32_t& l) {
    uint32_t hb; asm("cvt.rna.tf32.f32 %0, %1;" : "=r"(hb) : "f"(v));
    float lv = v - __uint_as_float(hb);
    uint32_t lb; asm("cvt.rna.tf32.f32 %0, %1;" : "=r"(lb) : "f"(lv));
    h = hb; l = lb;
}

__device__ __forceinline__ uint32_t tf32rna(float v) {
    uint32_t r; asm("cvt.rna.tf32.f32 %0, %1;" : "=r"(r) : "f"(v));
    return r;
}

__device__ __forceinline__ uint32_t smem_u32(const void* p) {
    uint32_t a;
    asm("{ .reg .u64 t; cvta.to.shared.u64 t, %1; cvt.u32.u64 %0, t; }" : "=r"(a) : "l"(p));
    return a;
}

__device__ __forceinline__ void ldsm_x4(uint32_t* d, uint32_t addr) {
    asm volatile("ldmatrix.sync.aligned.m8n8.x4.shared.b16 {%0,%1,%2,%3}, [%4];"
        : "=r"(d[0]), "=r"(d[1]), "=r"(d[2]), "=r"(d[3]) : "r"(addr));
}

__device__ __forceinline__ void mma_tf32(float* c, const uint32_t* a, const uint32_t* b) {
    asm volatile("mma.sync.aligned.m16n8k8.row.col.f32.tf32.tf32.f32 "
        "{%0,%1,%2,%3}, {%4,%5,%6,%7}, {%8,%9}, {%0,%1,%2,%3};\n"
        : "+f"(c[0]), "+f"(c[1]), "+f"(c[2]), "+f"(c[3])
        : "r"(a[0]), "r"(a[1]), "r"(a[2]), "r"(a[3]), "r"(b[0]), "r"(b[1]));
}

// =======================================================================
// GAT attention via tensor cores (R8 proven; exact-h 2-MMA form).
// =======================================================================
__device__ __forceinline__ void gat_attention_mma(
    const uint32_t* __restrict__ sh_hi, const uint32_t* __restrict__ sh_lo,
    const float* __restrict__ sei, const float* __restrict__ sej,
    const float* __restrict__ sPj, const float* __restrict__ sQj,
    const unsigned* __restrict__ smask, float* __restrict__ sy, int tid)
{
    int lane = tid & 31, wid = tid >> 5;
    int g = lane >> 2, tig = lane & 3;

    #pragma unroll 1
    for (int task = wid; task < 48; task += 8) {
        int hd = task >> 3, m0 = (task & 7) << 4;
        int r0 = m0 + g, r1 = r0 + 8;
        float ei0 = sei[(hd << 7) + r0], ei1 = sei[(hd << 7) + r1];
        float Pi0 = __expf(ei0), Qi0 = __expf(0.01f * ei0);
        float Pi1 = __expf(ei1), Qi1 = __expf(0.01f * ei1);
        const unsigned* mr0 = smask + (r0 << 2);
        const unsigned* mr1 = smask + (r1 << 2);
        const float* ejp = sej + (hd << 7);
        const float* Pjp = sPj + (hd << 7);
        const float* Qjp = sQj + (hd << 7);
        const uint32_t* hhi = sh_hi + (hd << 10);
        const uint32_t* hlo = sh_lo + (hd << 10);

        float c[4] = {0.f, 0.f, 0.f, 0.f};
        float ssum0 = 0.f, ssum1 = 0.f;

        #pragma unroll 1
        for (int jw = 0; jw < 4; jw++) {
            unsigned w0 = mr0[jw], w1 = mr1[jw];
            #pragma unroll
            for (int q = 0; q < 4; q++) {
                int j0 = (jw << 5) + (q << 3);
                unsigned mt0 = w0 >> ((q << 3) + tig);
                unsigned mt1 = w1 >> ((q << 3) + tig);
                int jA = j0 + tig, jB = jA + 4;
                float ejA = ejp[jA], ejB = ejp[jB];
                float PjA = Pjp[jA], PjB = Pjp[jB];
                float QjA = Qjp[jA], QjB = Qjp[jB];

                float wa0 = (ei0 + ejA > 0.f) ? (Pi0 * PjA) : (Qi0 * QjA);
                float wa1 = (ei1 + ejA > 0.f) ? (Pi1 * PjA) : (Qi1 * QjA);
                float wa2 = (ei0 + ejB > 0.f) ? (Pi0 * PjB) : (Qi0 * QjB);
                float wa3 = (ei1 + ejB > 0.f) ? (Pi1 * PjB) : (Qi1 * QjB);
                wa0 = (mt0 & 1u)  ? wa0 : 0.f;
                wa1 = (mt1 & 1u)  ? wa1 : 0.f;
                wa2 = (mt0 & 16u) ? wa2 : 0.f;
                wa3 = (mt1 & 16u) ? wa3 : 0.f;

                uint32_t a[4];
                a[0] = tf32rna(wa0); a[1] = tf32rna(wa1);
                a[2] = tf32rna(wa2); a[3] = tf32rna(wa3);
                ssum0 += __uint_as_float(a[0]) + __uint_as_float(a[2]);
                ssum1 += __uint_as_float(a[1]) + __uint_as_float(a[3]);

                uint32_t bh[2] = { hhi[(jA << 3) + g], hhi[(jB << 3) + g] };
                uint32_t bl[2] = { hlo[(jA << 3) + g], hlo[(jB << 3) + g] };
                mma_tf32(c, a, bh);
                mma_tf32(c, a, bl);
            }
        }
        ssum0 += __shfl_xor_sync(0xffffffffu, ssum0, 1);
        ssum0 += __shfl_xor_sync(0xffffffffu, ssum0, 2);
        ssum1 += __shfl_xor_sync(0xffffffffu, ssum1, 1);
        ssum1 += __shfl_xor_sync(0xffffffffu, ssum1, 2);
        float inv0 = 1.0f / ssum0, inv1 = 1.0f / ssum1;

        float* o0 = sy + r0 * 49 + (hd << 3) + (tig << 1);
        float* o1 = sy + r1 * 49 + (hd << 3) + (tig << 1);
        o0[0] = c[0] * inv0; o0[1] = c[1] * inv0;
        o1[0] = c[2] * inv1; o1[1] = c[3] * inv1;
    }
}

// LayerNorm over all [N,G] of one batch, + ReLU. sy row stride 49. 8 warps.
__device__ __forceinline__ void ln2d_apply(
    float* __restrict__ sy, const float* __restrict__ gamma,
    const float* __restrict__ beta, float* __restrict__ sred,
    int tid, float* __restrict__ gout)
{
    float s = 0.f, q = 0.f;
    for (int t = tid; t < XG; t += 256) {
        int n = t / 48, c = t - n * 48;
        float v = sy[n * 49 + c];
        s += v; q += v * v;
    }
    #pragma unroll
    for (int o = 16; o; o >>= 1) {
        s += __shfl_xor_sync(0xffffffffu, s, o);
        q += __shfl_xor_sync(0xffffffffu, q, o);
    }
    int wid = tid >> 5;
    if ((tid & 31) == 0) { sred[wid] = s; sred[8 + wid] = q; }
    __syncthreads();
    if (tid == 0) {
        float S = 0.f, Q = 0.f;
        #pragma unroll
        for (int i = 0; i < 8; i++) { S += sred[i]; Q += sred[8 + i]; }
        float m   = S * (1.f / (float)XG);
        float var = Q * (1.f / (float)XG) - m * m;
        sred[16] = m;
        sred[17] = rsqrtf(var + 1e-5f);
    }
    __syncthreads();
    float m = sred[16], rs = sred[17];
    for (int t = tid; t < XG; t += 256) {
        int n = t / 48, c = t - n * 48;
        float v = (sy[n * 49 + c] - m) * rs * gamma[t] + beta[t];
        v = fmaxf(v, 0.f);
        if (gout) gout[t] = v; else sy[n * 49 + c] = v;
    }
}

// GAT smem layout (words)
#define S_X    0
#define S_HHI  2176
#define S_HLO  (S_HHI + 6144)
#define S_Y    (S_HLO + 6144)
#define S_EI   (S_Y + 6272)
#define S_EJ   (S_EI + 768)
#define S_PJ   (S_EJ + 768)
#define S_QJ   (S_PJ + 768)
#define S_W    (S_QJ + 768)
#define S_A    (S_W + 2304)
#define S_RED  (S_A + 96)
#define S_MASK (S_RED + 20)
#define GAT_WORDS (S_MASK + 512)

__global__ __launch_bounds__(256)
void gat_kernel(const float* __restrict__ X,  const int* __restrict__ A,
                const float* __restrict__ W1, const float* __restrict__ a1,
                const float* __restrict__ W2, const float* __restrict__ a2,
                const float* __restrict__ Wr, const float* __restrict__ br,
                const float* __restrict__ g1, const float* __restrict__ b1,
                const float* __restrict__ g2, const float* __restrict__ b2)
{
    extern __shared__ float sm[];
    float*    sX    = sm + S_X;
    uint32_t* sh_hi = (uint32_t*)(sm + S_HHI);
    uint32_t* sh_lo = (uint32_t*)(sm + S_HLO);
    float*    sy    = sm + S_Y;
    float*    sei   = sm + S_EI;
    float*    sej   = sm + S_EJ;
    float*    sPj   = sm + S_PJ;
    float*    sQj   = sm + S_QJ;
    float*    sW    = sm + S_W;
    float*    sa    = sm + S_A;
    float*    sred  = sm + S_RED;
    unsigned* smask = (unsigned*)(sm + S_MASK);

    int b = blockIdx.x, tid = threadIdx.x;

    const float* Xb = X + (size_t)b * (NN * FF);
    for (int t = tid; t < NN * FF; t += 256)
        sX[(t >> 4) * 17 + (t & 15)] = Xb[t];

    {
        const int* Ab = A + (size_t)b * (NN * NN);
        int lane = tid & 31, wid = tid >> 5;
        for (int w = wid; w < 512; w += 8) {
            int i = w >> 2, j0 = (w & 3) << 5;
            unsigned bits = __ballot_sync(0xffffffffu, Ab[(i << 7) + j0 + lane] != 0);
            if (lane == 0) smask[w] = bits;
        }
    }
    for (int t = tid; t < HH * FF * DD; t += 256) sW[t] = W1[t];
    if (tid < HH * 2 * DD) sa[tid] = a1[tid];
    __syncthreads();

    // ---- layer 1: h = X@W1 (split to hi/lo), scores, per-node exps ----
    for (int t = tid; t < HH * NN; t += 256) {
        int hd = t >> 7, n = t & 127;
        float acc[8];
        #pragma unroll
        for (int d = 0; d < 8; d++) acc[d] = 0.f;
        const float* w = sW + hd * (FF * DD);
        const float* x = sX + n * 17;
        #pragma unroll
        for (int f = 0; f < FF; f++) {
            float xv = x[f];
            #pragma unroll
            for (int d = 0; d < 8; d++) acc[d] = fmaf(xv, w[(f << 3) + d], acc[d]);
        }
        const float* av = sa + (hd << 4);
        float ei = 0.f, ej = 0.f;
        #pragma unroll
        for (int d = 0; d < 8; d++) { ei = fmaf(acc[d], av[d], ei); ej = fmaf(acc[d], av[8 + d], ej); }
        #pragma unroll
        for (int d = 0; d < 8; d++) {
            uint32_t hb, lb; tf32split(acc[d], hb, lb);
            sh_hi[(t << 3) + d] = hb; sh_lo[(t << 3) + d] = lb;
        }
        sei[t] = ei; sej[t] = ej;
        sPj[t] = __expf(ej); sQj[t] = __expf(0.01f * ej);
    }
    __syncthreads();
    gat_attention_mma(sh_hi, sh_lo, sei, sej, sPj, sQj, smask, sy, tid);
    __syncthreads();
    ln2d_apply(sy, g1, b1, sred, tid, nullptr);
    __syncthreads();

    // ---- layer 2 weights ----
    for (int t = tid; t < HH * GG * DD; t += 256) sW[t] = W2[t];
    if (tid < HH * 2 * DD) sa[tid] = a2[tid];
    __syncthreads();

    // ---- layer 2: h2 = y@W2 ----
    for (int t = tid; t < HH * NN; t += 256) {
        int hd = t >> 7, n = t & 127;
        float acc[8];
        #pragma unroll
        for (int d = 0; d < 8; d++) acc[d] = 0.f;
        const float* w = sW + hd * (GG * DD);
        const float* x = sy + n * 49;
        #pragma unroll
        for (int f = 0; f < GG; f++) {
            float xv = x[f];
            #pragma unroll
            for (int d = 0; d < 8; d++) acc[d] = fmaf(xv, w[(f << 3) + d], acc[d]);
        }
        const float* av = sa + (hd << 4);
        float ei = 0.f, ej = 0.f;
        #pragma unroll
        for (int d = 0; d < 8; d++) { ei = fmaf(acc[d], av[d], ei); ej = fmaf(acc[d], av[8 + d], ej); }
        #pragma unroll
        for (int d = 0; d < 8; d++) {
            uint32_t hb, lb; tf32split(acc[d], hb, lb);
            sh_hi[(t << 3) + d] = hb; sh_lo[(t << 3) + d] = lb;
        }
        sei[t] = ei; sej[t] = ej;
        sPj[t] = __expf(ej); sQj[t] = __expf(0.01f * ej);
    }
    __syncthreads();
    gat_attention_mma(sh_hi, sh_lo, sei, sej, sPj, sQj, smask, sy, tid);
    __syncthreads();

    // ---- residual: sy += X@Wr + br ----
    for (int t = tid; t < FF * GG; t += 256) sW[t] = Wr[t];
    if (tid < GG) sa[tid] = br[tid];
    __syncthreads();
    for (int t = tid; t < XG; t += 256) {
        int n = t / 48, c = t - n * 48;
        float accv = sa[c];
        const float* x = sX + n * 17;
        #pragma unroll
        for (int f = 0; f < FF; f++) accv = fmaf(x[f], sW[f * 48 + c], accv);
        sy[n * 49 + c] += accv;
    }
    __syncthreads();
    ln2d_apply(sy, g2, b2, sred, tid, g_x + (size_t)b * XG);
}

// =======================================================================
// Double-buffered 2xTF32 GEMM, BK=32. A split hi/lo; B hi-only.
// C = A_hi@B_hi^T + A_lo@B_hi^T  (error ~2^-12 rel, fine vs 1e-3).
// B row-major [N,K]. Split-K via grid.z -> partial C at z*M*N.
// smem: 2 bufs x (A hi+lo + B hi) x 64x36 words = 55296 B -> 4 CTA/SM.
// =======================================================================
#define PLANE_W     (64*36)
#define LO_BYTES    (PLANE_W*4)
#define A_BUF_W     (2*PLANE_W)
#define A_BUF_BYTES (A_BUF_W*4)
#define B_BUF_BYTES (PLANE_W*4)
#define GEMM_SMEM   (6*PLANE_W*4)   // 55296

__global__ __launch_bounds__(256)
void gemm_nk(const float* __restrict__ Af, const float* __restrict__ Bf,
             float* __restrict__ C, int M, int N, int K, int kChunk)
{
    extern __shared__ uint32_t smem[];
    uint32_t* sA = smem;                     // [2][hi/lo][64][36]
    uint32_t* sB = smem + 2 * A_BUF_W;       // [2][64][36]

    int tid  = threadIdx.x;
    int lane = tid & 31, wid = tid >> 5;
    int warpM = (wid >> 1) << 4;
    int warpN = (wid & 1) << 5;
    int g = lane >> 2, tig = lane & 3;
    int bm = blockIdx.y << 6, bn = blockIdx.x << 6;
    int kBeg = blockIdx.z * kChunk;
    int nt   = kChunk >> 5;

    uint32_t aOff = (((warpM + (lane & 15)) * 36 + ((lane >> 4) << 2)) << 2);
    uint32_t bOff = (((warpN + ((lane >> 4) << 3) + (lane & 7)) * 36 + (((lane >> 3) & 1) << 2)) << 2);
    uint32_t aBaseS = smem_u32(sA);
    uint32_t bBaseS = smem_u32(sB);

    int frow = tid >> 3;
    int fkc  = (tid & 7) << 2;

    float acc[4][4];
    #pragma unroll
    for (int ns = 0; ns < 4; ns++)
        #pragma unroll
        for (int r = 0; r < 4; r++) acc[ns][r] = 0.f;

    float4 pA[2], pB[2];

    auto FETCH = [&](int kt) {
        #pragma unroll
        for (int q = 0; q < 2; q++) {
            int row = frow + (q << 5);
            pA[q] = *(const float4*)(Af + (size_t)(bm + row) * K + kBeg + kt + fkc);
            pB[q] = *(const float4*)(Bf + (size_t)(bn + row) * K + kBeg + kt + fkc);
        }
    };
    auto STORE = [&](int buf) {
        uint32_t* dA = sA + buf * A_BUF_W;
        uint32_t* dB = sB + buf * PLANE_W;
        #pragma unroll
        for (int q = 0; q < 2; q++) {
            int row = frow + (q << 5);
            uint4 hi, lo;
            tf32split(pA[q].x, hi.x, lo.x); tf32split(pA[q].y, hi.y, lo.y);
            tf32split(pA[q].z, hi.z, lo.z); tf32split(pA[q].w, hi.w, lo.w);
            *(uint4*)(dA + row * 36 + fkc)           = hi;
            *(uint4*)(dA + PLANE_W + row * 36 + fkc) = lo;
            uint4 bh;
            bh.x = tf32rna(pB[q].x); bh.y = tf32rna(pB[q].y);
            bh.z = tf32rna(pB[q].z); bh.w = tf32rna(pB[q].w);
            *(uint4*)(dB + row * 36 + fkc) = bh;
        }
    };

    FETCH(0);
    STORE(0);
    __syncthreads();

    for (int t = 0; t < nt; t++) {
        int cur = t & 1;
        bool more = (t + 1 < nt);
        if (more) FETCH((t + 1) << 5);

        uint32_t aB  = aBaseS + cur * A_BUF_BYTES + aOff;
        uint32_t bB0 = bBaseS + cur * B_BUF_BYTES + bOff;
        uint32_t bB1 = bB0 + ((16 * 36) << 2);
        #pragma unroll
        for (int ks = 0; ks < 4; ks++) {
            uint32_t koff = (ks << 3) << 2;
            uint32_t ah[4], al[4], bh[2][4];
            ldsm_x4(ah, aB + koff);
            ldsm_x4(al, aB + LO_BYTES + koff);
            ldsm_x4(bh[0], bB0 + koff);
            ldsm_x4(bh[1], bB1 + koff);
            #pragma unroll
            for (int p = 0; p < 2; p++)
                #pragma unroll
                for (int half = 0; half < 2; half++) {
                    int ns = (p << 1) + half;
                    const uint32_t bfh[2] = {bh[p][half << 1], bh[p][(half << 1) + 1]};
                    mma_tf32(acc[ns], ah, bfh);
                    mma_tf32(acc[ns], al, bfh);
                }
        }
        if (more) STORE(cur ^ 1);
        __syncthreads();
    }

    float* Cp = C + (size_t)blockIdx.z * M * N;
    int r0 = bm + warpM + g;
    #pragma unroll
    for (int ns = 0; ns < 4; ns++) {
        int c0 = bn + warpN + (ns << 3) + (tig << 1);
        size_t o0 = (size_t)r0 * N + c0, o2 = (size_t)(r0 + 8) * N + c0;
        Cp[o0] = acc[ns][0]; Cp[o0 + 1] = acc[ns][1];
        Cp[o2] = acc[ns][2]; Cp[o2 + 1] = acc[ns][3];
    }
}

// =======================================================================
// 2xTF32 GEMM for transposed-B (B row-major [K,N]); B hi-only; split-K.
// =======================================================================
__global__ __launch_bounds__(256)
void gemm_t(const float* __restrict__ Af, const float* __restrict__ Bf,
            float* __restrict__ C, int M, int N, int K, int ldb, int kChunk)
{
    __shared__ uint32_t sA[2][64][36];
    __shared__ uint32_t sB[64][36];

    int tid  = threadIdx.x;
    int lane = tid & 31, wid = tid >> 5;
    int warpM = (wid >> 1) << 4;
    int warpN = (wid & 1) << 5;
    int g = lane >> 2, tig = lane & 3;
    int bm = blockIdx.y << 6, bn = blockIdx.x << 6;
    int kBeg = blockIdx.z * kChunk;

    uint32_t aBase = smem_u32(&sA[0][0][0]) +
        (((warpM + (lane & 15)) * 36 + ((lane >> 4) << 2)) << 2);
    uint32_t bBase0 = smem_u32(&sB[0][0]) +
        (((warpN + ((lane >> 4) << 3) + (lane & 7)) * 36 + (((lane >> 3) & 1) << 2)) << 2);
    uint32_t bBase1 = bBase0 + (16 * 36 << 2);
    const uint32_t LO = (64 * 36) << 2;

    float acc[4][4];
    #pragma unroll
    for (int ns = 0; ns < 4; ns++)
        #pragma unroll
        for (int r = 0; r < 4; r++) acc[ns][r] = 0.f;

    float4 pA[2], pB[2];
    #pragma unroll
    for (int q = 0; q < 2; q++) {
        int idx = tid + (q << 8);
        int row = idx >> 3, kc = (idx & 7) << 2;
        pA[q] = *(const float4*)(Af + (size_t)(bm + row) * K + kBeg + kc);
        int k = idx >> 4, n0 = (idx & 15) << 2;
        pB[q] = *(const float4*)(Bf + (size_t)(kBeg + k) * ldb + bn + n0);
    }

    for (int kt = 0; kt < kChunk; kt += 32) {
        #pragma unroll
        for (int q = 0; q < 2; q++) {
            int idx = tid + (q << 8);
            {
                int row = idx >> 3, kc = (idx & 7) << 2;
                uint4 hi, lo;
                tf32split(pA[q].x, hi.x, lo.x); tf32split(pA[q].y, hi.y, lo.y);
                tf32split(pA[q].z, hi.z, lo.z); tf32split(pA[q].w, hi.w, lo.w);
                *(uint4*)&sA[0][row][kc] = hi;
                *(uint4*)&sA[1][row][kc] = lo;
            }
            {
                int k = idx >> 4, n0 = (idx & 15) << 2;
                float v[4] = {pB[q].x, pB[q].y, pB[q].z, pB[q].w};
                #pragma unroll
                for (int j = 0; j < 4; j++)
                    sB[n0 + j][k] = tf32rna(v[j]);
            }
        }
        __syncthreads();

        int ktn = kt + 32;
        if (ktn < kChunk) {
            #pragma unroll
            for (int q = 0; q < 2; q++) {
                int idx = tid + (q << 8);
                int row = idx >> 3, kc = (idx & 7) << 2;
                pA[q] = *(const float4*)(Af + (size_t)(bm + row) * K + kBeg + ktn + kc);
                int k = idx >> 4, n0 = (idx & 15) << 2;
                pB[q] = *(const float4*)(Bf + (size_t)(kBeg + ktn + k) * ldb + bn + n0);
            }
        }

        #pragma unroll
        for (int ks = 0; ks < 4; ks++) {
            uint32_t koff = (ks << 3) << 2;
            uint32_t ah[4], al[4], bh[2][4];
            ldsm_x4(ah, aBase + koff);
            ldsm_x4(al, aBase + LO + koff);
            ldsm_x4(bh[0], bBase0 + koff);
            ldsm_x4(bh[1], bBase1 + koff);
            #pragma unroll
            for (int p = 0; p < 2; p++)
                #pragma unroll
                for (int half = 0; half < 2; half++) {
                    int ns = (p << 1) + half;
                    const uint32_t bfh[2] = {bh[p][half << 1], bh[p][(half << 1) + 1]};
                    mma_tf32(acc[ns], ah, bfh);
                    mma_tf32(acc[ns], al, bfh);
                }
        }
        __syncthreads();
    }

    float* Cp = C + (size_t)blockIdx.z * M * N;
    int r0 = bm + warpM + g;
    #pragma unroll
    for (int ns = 0; ns < 4; ns++) {
        int c0 = bn + warpN + (ns << 3) + (tig << 1);
        size_t o0 = (size_t)r0 * N + c0, o2 = (size_t)(r0 + 8) * N + c0;
        Cp[o0] = acc[ns][0]; Cp[o0 + 1] = acc[ns][1];
        Cp[o2] = acc[ns][2]; Cp[o2 + 1] = acc[ns][3];
    }
}

// =======================================================================
// Reduce split-K partials + bias (+relu)
// =======================================================================
__global__ __launch_bounds__(256)
void reduceSK(const float* __restrict__ part, int S, int plane,
              const float* __restrict__ bias, int act,
              float* __restrict__ out, int total, int N)
{
    int idx = blockIdx.x * 256 + threadIdx.x;
    if (idx >= total) return;
    float v = bias[idx % N];
    for (int s = 0; s < S; s++) v += part[(size_t)s * plane + idx];
    if (act) v = fmaxf(v, 0.f);
    out[idx] = v;
}

// =======================================================================
// GRU gates (hidden==0): reduce S split-K partials + bih + bhh; h=(1-z)n
// =======================================================================
__global__ __launch_bounds__(256)
void gru_gatesS(const float* __restrict__ gip, int S,
                const float* __restrict__ bih, const float* __restrict__ bhh,
                float* __restrict__ h)
{
    int idx = blockIdx.x * 256 + threadIdx.x;
    int b = idx >> 8, j = idx & 255;
    const float* g0 = gip + (size_t)b * G3;
    const size_t P = (size_t)BB * G3;
    float vr = bih[j], vz = bih[256 + j], vn = bih[512 + j];
    for (int s = 0; s < S; s++) {
        vr += g0[s * P + j];
        vz += g0[s * P + 256 + j];
        vn += g0[s * P + 512 + j];
    }
    float r = 1.f / (1.f + __expf(-(vr + bhh[j])));
    float z = 1.f / (1.f + __expf(-(vz + bhh[256 + j])));
    float n = tanhf(vn + r * bhh[512 + j]);
    h[idx] = (1.f - z) * n;
}

// =======================================================================
// LayerNorm over GRU dim
// =======================================================================
__global__ __launch_bounds__(256)
void ln1d_k(const float* __restrict__ h, const float* __restrict__ g,
            const float* __restrict__ b, float* __restrict__ o)
{
    __shared__ float s1[8], s2[8], mv[2];
    int row = blockIdx.x, tid = threadIdx.x;
    float v = h[(size_t)row * GRUU + tid];
    float s = v, q = v * v;
    #pragma unroll
    for (int off = 16; off; off >>= 1) {
        s += __shfl_xor_sync(0xffffffffu, s, off);
        q += __shfl_xor_sync(0xffffffffu, q, off);
    }
    if ((tid & 31) == 0) { s1[tid >> 5] = s; s2[tid >> 5] = q; }
    __syncthreads();
    if (tid == 0) {
        float S = 0.f, Q = 0.f;
        #pragma unroll
        for (int i = 0; i < 8; i++) { S += s1[i]; Q += s2[i]; }
        float m = S * (1.f / 256.f);
        float var = Q * (1.f / 256.f) - m * m;
        mv[0] = m; mv[1] = rsqrtf(var + 1e-5f);
    }
    __syncthreads();
    o[(size_t)row * GRUU + tid] = (v - mv[0]) * mv[1] * g[tid] + b[tid];
}

// =======================================================================
// host launcher
// =======================================================================
extern "C" void kernel_launch(void* const* d_in, const int* in_sizes, int n_in,
                              void* d_out, int out_size)
{
    const float* X    = (const float*)d_in[0];
    const int*   A    = (const int*)  d_in[1];
    const float* W1   = (const float*)d_in[2];
    const float* a1   = (const float*)d_in[3];
    const float* W2   = (const float*)d_in[4];
    const float* a2   = (const float*)d_in[5];
    const float* Wr   = (const float*)d_in[6];
    const float* br   = (const float*)d_in[7];
    const float* g1   = (const float*)d_in[8];
    const float* b1   = (const float*)d_in[9];
    const float* g2   = (const float*)d_in[10];
    const float* b2   = (const float*)d_in[11];
    const float* Wih0 = (const float*)d_in[12];
    const float* bih0 = (const float*)d_in[14];
    const float* bhh0 = (const float*)d_in[15];
    const float* Wih1 = (const float*)d_in[16];
    const float* bih1 = (const float*)d_in[18];
    const float* bhh1 = (const float*)d_in[19];
    const float* Wih2 = (const float*)d_in[20];
    const float* bih2 = (const float*)d_in[22];
    const float* bhh2 = (const float*)d_in[23];
    const float* gng  = (const float*)d_in[24];
    const float* gnb  = (const float*)d_in[25];
    const float* We   = (const float*)d_in[26];
    const float* be   = (const float*)d_in[27];
    const float* Wp   = (const float*)d_in[28];
    const float* bp   = (const float*)d_in[29];
    float* out = (float*)d_out;

    float *px, *pgip, *ph, *phln, *pemb;
    cudaGetSymbolAddress((void**)&px,   g_x);
    cudaGetSymbolAddress((void**)&pgip, g_gip);
    cudaGetSymbolAddress((void**)&ph,   g_h);
    cudaGetSymbolAddress((void**)&phln, g_hln);
    cudaGetSymbolAddress((void**)&pemb, g_emb);

    const int GAT_SMEM = GAT_WORDS * 4;
    cudaFuncSetAttribute(gat_kernel, cudaFuncAttributeMaxDynamicSharedMemorySize, GAT_SMEM);
    cudaFuncSetAttribute(gemm_nk, cudaFuncAttributeMaxDynamicSharedMemorySize, GEMM_SMEM);

    gat_kernel<<<BB, 256, GAT_SMEM>>>(X, A, W1, a1, W2, a2, Wr, br, g1, b1, g2, b2);

    // GRU layer 0: split-K x8 (chunk 768 -> 24 BK32 tiles, grid 1536)
    dim3 g0(G3 / 64, BB / 64, SK0);
    gemm_nk<<<g0, 256, GEMM_SMEM>>>(px, Wih0, pgip, BB, G3, XG, XG / SK0);
    gru_gatesS<<<BB, 256>>>(pgip, SK0, bih0, bhh0, ph);

    // GRU layers 1 & 2: split-K x2 (chunk 128 -> 4 tiles)
    dim3 g12(G3 / 64, BB / 64, 2);
    gemm_nk<<<g12, 256, GEMM_SMEM>>>(ph, Wih1, pgip, BB, G3, GRUU, GRUU / 2);
    gru_gatesS<<<BB, 256>>>(pgip, 2, bih1, bhh1, ph);
    gemm_nk<<<g12, 256, GEMM_SMEM>>>(ph, Wih2, pgip, BB, G3, GRUU, GRUU / 2);
    gru_gatesS<<<BB, 256>>>(pgip, 2, bih2, bhh2, ph);

    ln1d_k<<<BB, 256>>>(ph, gng, gnb, phln);

    float* embp = (out_size >= 2 * BB * EMBB) ? (out + (size_t)BB * EMBB) : pemb;

    // emb = relu(hln @ We + be): split-K x4 (K=256, chunk 64)
    dim3 gEmb(EMBB / 64, BB / 64, 4);
    gemm_t<<<gEmb, 256>>>(phln, We, pgip, BB, EMBB, GRUU, EMBB, GRUU / 4);
    reduceSK<<<(BB * EMBB + 255) / 256, 256>>>(pgip, 4, BB * EMBB, be, 1,
                                               embp, BB * EMBB, EMBB);

    // pred = emb @ Wp + bp: split-K x2 (K=128, chunk 64)
    dim3 gPred(NN / 64, BB / 64, 2);
    gemm_t<<<gPred, 256>>>(embp, Wp, pgip, BB, NN, EMBB, NN, EMBB / 2);
    reduceSK<<<(BB * NN + 255) / 256, 256>>>(pgip, 2, BB * NN, bp, 0,
                                             out, BB * NN, NN);
}

// round 10
// speedup vs baseline: 1.3496x; 1.0378x over previous
#include <cuda_runtime.h>
#include <cstdint>

// ---------------- problem constants ----------------
#define BB   1024
#define NN   128
#define FF   16
#define GG   48
#define HH   6
#define DD   8
#define GRUU 256
#define EMBB 128
#define XG   (NN*GG)       // 6144
#define G3   (3*GRUU)      // 768
#define SK0  8             // split-K for GRU0
#define TG   384           // GAT block size (12 warps)

// ---------------- scratch ----------------
__device__ float g_x  [BB*XG];
__device__ float g_gip[SK0*BB*G3];
__device__ float g_h  [BB*GRUU];
__device__ float g_hln[BB*GRUU];
__device__ float g_emb[BB*EMBB];

// ---------------- helpers ----------------
__device__ __forceinline__ void tf32split(float v, uint32_t& h, uint32_t& l) {
    uint32_t hb; asm("cvt.rna.tf32.f32 %0, %1;" : "=r"(hb) : "f"(v));
    float lv = v - __uint_as_float(hb);
    uint32_t lb; asm("cvt.rna.tf32.f32 %0, %1;" : "=r"(lb) : "f"(lv));
    h = hb; l = lb;
}

__device__ __forceinline__ uint32_t tf32rna(float v) {
    uint32_t r; asm("cvt.rna.tf32.f32 %0, %1;" : "=r"(r) : "f"(v));
    return r;
}

__device__ __forceinline__ uint32_t smem_u32(const void* p) {
    uint32_t a;
    asm("{ .reg .u64 t; cvta.to.shared.u64 t, %1; cvt.u32.u64 %0, t; }" : "=r"(a) : "l"(p));
    return a;
}

__device__ __forceinline__ void ldsm_x4(uint32_t* d, uint32_t addr) {
    asm volatile("ldmatrix.sync.aligned.m8n8.x4.shared.b16 {%0,%1,%2,%3}, [%4];"
        : "=r"(d[0]), "=r"(d[1]), "=r"(d[2]), "=r"(d[3]) : "r"(addr));
}

__device__ __forceinline__ void mma_tf32(float* c, const uint32_t* a, const uint32_t* b) {
    asm volatile("mma.sync.aligned.m16n8k8.row.col.f32.tf32.tf32.f32 "
        "{%0,%1,%2,%3}, {%4,%5,%6,%7}, {%8,%9}, {%0,%1,%2,%3};\n"
        : "+f"(c[0]), "+f"(c[1]), "+f"(c[2]), "+f"(c[3])
        : "r"(a[0]), "r"(a[1]), "r"(a[2]), "r"(a[3]), "r"(b[0]), "r"(b[1]));
}

// dummy kernel to shift ncu capture index onto gat_kernel
__global__ void noop_k() {}

// =======================================================================
// GAT attention via tensor cores. 12 warps -> 4 tasks/warp.
// =======================================================================
__device__ __forceinline__ void gat_attention_mma(
    const uint32_t* __restrict__ sh_hi, const uint32_t* __restrict__ sh_lo,
    const float* __restrict__ sei, const float* __restrict__ sej,
    const float* __restrict__ sPj, const float* __restrict__ sQj,
    const unsigned* __restrict__ smask, float* __restrict__ sy, int tid)
{
    int lane = tid & 31, wid = tid >> 5;
    int g = lane >> 2, tig = lane & 3;

    #pragma unroll 1
    for (int task = wid; task < 48; task += 12) {
        int hd = task >> 3, m0 = (task & 7) << 4;
        int r0 = m0 + g, r1 = r0 + 8;
        float ei0 = sei[(hd << 7) + r0], ei1 = sei[(hd << 7) + r1];
        float Pi0 = __expf(ei0), Qi0 = __expf(0.01f * ei0);
        float Pi1 = __expf(ei1), Qi1 = __expf(0.01f * ei1);
        const unsigned* mr0 = smask + (r0 << 2);
        const unsigned* mr1 = smask + (r1 << 2);
        const float* ejp = sej + (hd << 7);
        const float* Pjp = sPj + (hd << 7);
        const float* Qjp = sQj + (hd << 7);
        const uint32_t* hhi = sh_hi + (hd << 10);
        const uint32_t* hlo = sh_lo + (hd << 10);

        float c[4] = {0.f, 0.f, 0.f, 0.f};
        float ssum0 = 0.f, ssum1 = 0.f;

        #pragma unroll 1
        for (int jw = 0; jw < 4; jw++) {
            unsigned w0 = mr0[jw], w1 = mr1[jw];
            #pragma unroll
            for (int q = 0; q < 4; q++) {
                int j0 = (jw << 5) + (q << 3);
                unsigned mt0 = w0 >> ((q << 3) + tig);
                unsigned mt1 = w1 >> ((q << 3) + tig);
                int jA = j0 + tig, jB = jA + 4;
                float ejA = ejp[jA], ejB = ejp[jB];
                float PjA = Pjp[jA], PjB = Pjp[jB];
                float QjA = Qjp[jA], QjB = Qjp[jB];

                float wa0 = (ei0 + ejA > 0.f) ? (Pi0 * PjA) : (Qi0 * QjA);
                float wa1 = (ei1 + ejA > 0.f) ? (Pi1 * PjA) : (Qi1 * QjA);
                float wa2 = (ei0 + ejB > 0.f) ? (Pi0 * PjB) : (Qi0 * QjB);
                float wa3 = (ei1 + ejB > 0.f) ? (Pi1 * PjB) : (Qi1 * QjB);
                wa0 = (mt0 & 1u)  ? wa0 : 0.f;
                wa1 = (mt1 & 1u)  ? wa1 : 0.f;
                wa2 = (mt0 & 16u) ? wa2 : 0.f;
                wa3 = (mt1 & 16u) ? wa3 : 0.f;

                uint32_t a[4];
                a[0] = tf32rna(wa0); a[1] = tf32rna(wa1);
                a[2] = tf32rna(wa2); a[3] = tf32rna(wa3);
                ssum0 += __uint_as_float(a[0]) + __uint_as_float(a[2]);
                ssum1 += __uint_as_float(a[1]) + __uint_as_float(a[3]);

                uint32_t bh[2] = { hhi[(jA << 3) + g], hhi[(jB << 3) + g] };
                uint32_t bl[2] = { hlo[(jA << 3) + g], hlo[(jB << 3) + g] };
                mma_tf32(c, a, bh);
                mma_tf32(c, a, bl);
            }
        }
        ssum0 += __shfl_xor_sync(0xffffffffu, ssum0, 1);
        ssum0 += __shfl_xor_sync(0xffffffffu, ssum0, 2);
        ssum1 += __shfl_xor_sync(0xffffffffu, ssum1, 1);
        ssum1 += __shfl_xor_sync(0xffffffffu, ssum1, 2);
        float inv0 = 1.0f / ssum0, inv1 = 1.0f / ssum1;

        float* o0 = sy + r0 * 49 + (hd << 3) + (tig << 1);
        float* o1 = sy + r1 * 49 + (hd << 3) + (tig << 1);
        o0[0] = c[0] * inv0; o0[1] = c[1] * inv0;
        o1[0] = c[2] * inv1; o1[1] = c[3] * inv1;
    }
}

// LayerNorm over all [N,G] of one batch, + ReLU. sy row stride 49. 12 warps.
__device__ __forceinline__ void ln2d_apply(
    float* __restrict__ sy, const float* __restrict__ gamma,
    const float* __restrict__ beta, float* __restrict__ sred,
    int tid, float* __restrict__ gout)
{
    float s = 0.f, q = 0.f;
    for (int t = tid; t < XG; t += TG) {
        int n = t / 48, c = t - n * 48;
        float v = sy[n * 49 + c];
        s += v; q += v * v;
    }
    #pragma unroll
    for (int o = 16; o; o >>= 1) {
        s += __shfl_xor_sync(0xffffffffu, s, o);
        q += __shfl_xor_sync(0xffffffffu, q, o);
    }
    int wid = tid >> 5;
    if ((tid & 31) == 0) { sred[wid] = s; sred[12 + wid] = q; }
    __syncthreads();
    if (tid == 0) {
        float S = 0.f, Q = 0.f;
        #pragma unroll
        for (int i = 0; i < 12; i++) { S += sred[i]; Q += sred[12 + i]; }
        float m   = S * (1.f / (float)XG);
        float var = Q * (1.f / (float)XG) - m * m;
        sred[24] = m;
        sred[25] = rsqrtf(var + 1e-5f);
    }
    __syncthreads();
    float m = sred[24], rs = sred[25];
    for (int t = tid; t < XG; t += TG) {
        int n = t / 48, c = t - n * 48;
        float v = (sy[n * 49 + c] - m) * rs * gamma[t] + beta[t];
        v = fmaxf(v, 0.f);
        if (gout) gout[t] = v; else sy[n * 49 + c] = v;
    }
}

// GAT smem layout (words)
#define S_X    0
#define S_HHI  2176
#define S_HLO  (S_HHI + 6144)
#define S_Y    (S_HLO + 6144)
#define S_EI   (S_Y + 6272)
#define S_EJ   (S_EI + 768)
#define S_PJ   (S_EJ + 768)
#define S_QJ   (S_PJ + 768)
#define S_W    (S_QJ + 768)
#define S_A    (S_W + 2304)
#define S_RED  (S_A + 96)
#define S_MASK (S_RED + 32)
#define GAT_WORDS (S_MASK + 512)

__global__ __launch_bounds__(TG)
void gat_kernel(const float* __restrict__ X,  const int* __restrict__ A,
                const float* __restrict__ W1, const float* __restrict__ a1,
                const float* __restrict__ W2, const float* __restrict__ a2,
                const float* __restrict__ Wr, const float* __restrict__ br,
                const float* __restrict__ g1, const float* __restrict__ b1,
                const float* __restrict__ g2, const float* __restrict__ b2)
{
    extern __shared__ float sm[];
    float*    sX    = sm + S_X;
    uint32_t* sh_hi = (uint32_t*)(sm + S_HHI);
    uint32_t* sh_lo = (uint32_t*)(sm + S_HLO);
    float*    sy    = sm + S_Y;
    float*    sei   = sm + S_EI;
    float*    sej   = sm + S_EJ;
    float*    sPj   = sm + S_PJ;
    float*    sQj   = sm + S_QJ;
    float*    sW    = sm + S_W;
    float*    sa    = sm + S_A;
    float*    sred  = sm + S_RED;
    unsigned* smask = (unsigned*)(sm + S_MASK);

    int b = blockIdx.x, tid = threadIdx.x;

    const float* Xb = X + (size_t)b * (NN * FF);
    for (int t = tid; t < NN * FF; t += TG)
        sX[(t >> 4) * 17 + (t & 15)] = Xb[t];

    {
        const int* Ab = A + (size_t)b * (NN * NN);
        int lane = tid & 31, wid = tid >> 5;
        for (int w = wid; w < 512; w += 12) {
            int i = w >> 2, j0 = (w & 3) << 5;
            unsigned bits = __ballot_sync(0xffffffffu, Ab[(i << 7) + j0 + lane] != 0);
            if (lane == 0) smask[w] = bits;
        }
    }
    for (int t = tid; t < HH * FF * DD; t += TG) sW[t] = W1[t];
    if (tid < HH * 2 * DD) sa[tid] = a1[tid];
    __syncthreads();

    // ---- layer 1: h = X@W1 (split to hi/lo), scores, per-node exps ----
    for (int t = tid; t < HH * NN; t += TG) {
        int hd = t >> 7, n = t & 127;
        float acc[8];
        #pragma unroll
        for (int d = 0; d < 8; d++) acc[d] = 0.f;
        const float* w = sW + hd * (FF * DD);
        const float* x = sX + n * 17;
        #pragma unroll
        for (int f = 0; f < FF; f++) {
            float xv = x[f];
            #pragma unroll
            for (int d = 0; d < 8; d++) acc[d] = fmaf(xv, w[(f << 3) + d], acc[d]);
        }
        const float* av = sa + (hd << 4);
        float ei = 0.f, ej = 0.f;
        #pragma unroll
        for (int d = 0; d < 8; d++) { ei = fmaf(acc[d], av[d], ei); ej = fmaf(acc[d], av[8 + d], ej); }
        #pragma unroll
        for (int d = 0; d < 8; d++) {
            uint32_t hb, lb; tf32split(acc[d], hb, lb);
            sh_hi[(t << 3) + d] = hb; sh_lo[(t << 3) + d] = lb;
        }
        sei[t] = ei; sej[t] = ej;
        sPj[t] = __expf(ej); sQj[t] = __expf(0.01f * ej);
    }
    __syncthreads();
    gat_attention_mma(sh_hi, sh_lo, sei, sej, sPj, sQj, smask, sy, tid);
    __syncthreads();
    ln2d_apply(sy, g1, b1, sred, tid, nullptr);
    __syncthreads();

    // ---- layer 2 weights ----
    for (int t = tid; t < HH * GG * DD; t += TG) sW[t] = W2[t];
    if (tid < HH * 2 * DD) sa[tid] = a2[tid];
    __syncthreads();

    // ---- layer 2: h2 = y@W2 ----
    for (int t = tid; t < HH * NN; t += TG) {
        int hd = t >> 7, n = t & 127;
        float acc[8];
        #pragma unroll
        for (int d = 0; d < 8; d++) acc[d] = 0.f;
        const float* w = sW + hd * (GG * DD);
        const float* x = sy + n * 49;
        #pragma unroll
        for (int f = 0; f < GG; f++) {
            float xv = x[f];
            #pragma unroll
            for (int d = 0; d < 8; d++) acc[d] = fmaf(xv, w[(f << 3) + d], acc[d]);
        }
        const float* av = sa + (hd << 4);
        float ei = 0.f, ej = 0.f;
        #pragma unroll
        for (int d = 0; d < 8; d++) { ei = fmaf(acc[d], av[d], ei); ej = fmaf(acc[d], av[8 + d], ej); }
        #pragma unroll
        for (int d = 0; d < 8; d++) {
            uint32_t hb, lb; tf32split(acc[d], hb, lb);
            sh_hi[(t << 3) + d] = hb; sh_lo[(t << 3) + d] = lb;
        }
        sei[t] = ei; sej[t] = ej;
        sPj[t] = __expf(ej); sQj[t] = __expf(0.01f * ej);
    }
    __syncthreads();
    gat_attention_mma(sh_hi, sh_lo, sei, sej, sPj, sQj, smask, sy, tid);
    __syncthreads();

    // ---- residual: sy += X@Wr + br ----
    for (int t = tid; t < FF * GG; t += TG) sW[t] = Wr[t];
    if (tid < GG) sa[tid] = br[tid];
    __syncthreads();
    for (int t = tid; t < XG; t += TG) {
        int n = t / 48, c = t - n * 48;
        float accv = sa[c];
        const float* x = sX + n * 17;
        #pragma unroll
        for (int f = 0; f < FF; f++) accv = fmaf(x[f], sW[f * 48 + c], accv);
        sy[n * 49 + c] += accv;
    }
    __syncthreads();
    ln2d_apply(sy, g2, b2, sred, tid, g_x + (size_t)b * XG);
}

// =======================================================================
// Double-buffered 2xTF32 GEMM, BK=32. A split hi/lo; B hi-only.
// B row-major [N,K]. Split-K via grid.z -> partial C at z*M*N.
// =======================================================================
#define PLANE_W     (64*36)
#define LO_BYTES    (PLANE_W*4)
#define A_BUF_W     (2*PLANE_W)
#define A_BUF_BYTES (A_BUF_W*4)
#define B_BUF_BYTES (PLANE_W*4)
#define GEMM_SMEM   (6*PLANE_W*4)   // 55296

__global__ __launch_bounds__(256)
void gemm_nk(const float* __restrict__ Af, const float* __restrict__ Bf,
             float* __restrict__ C, int M, int N, int K, int kChunk)
{
    extern __shared__ uint32_t smem[];
    uint32_t* sA = smem;
    uint32_t* sB = smem + 2 * A_BUF_W;

    int tid  = threadIdx.x;
    int lane = tid & 31, wid = tid >> 5;
    int warpM = (wid >> 1) << 4;
    int warpN = (wid & 1) << 5;
    int g = lane >> 2, tig = lane & 3;
    int bm = blockIdx.y << 6, bn = blockIdx.x << 6;
    int kBeg = blockIdx.z * kChunk;
    int nt   = kChunk >> 5;

    uint32_t aOff = (((warpM + (lane & 15)) * 36 + ((lane >> 4) << 2)) << 2);
    uint32_t bOff = (((warpN + ((lane >> 4) << 3) + (lane & 7)) * 36 + (((lane >> 3) & 1) << 2)) << 2);
    uint32_t aBaseS = smem_u32(sA);
    uint32_t bBaseS = smem_u32(sB);

    int frow = tid >> 3;
    int fkc  = (tid & 7) << 2;

    float acc[4][4];
    #pragma unroll
    for (int ns = 0; ns < 4; ns++)
        #pragma unroll
        for (int r = 0; r < 4; r++) acc[ns][r] = 0.f;

    float4 pA[2], pB[2];

    auto FETCH = [&](int kt) {
        #pragma unroll
        for (int q = 0; q < 2; q++) {
            int row = frow + (q << 5);
            pA[q] = *(const float4*)(Af + (size_t)(bm + row) * K + kBeg + kt + fkc);
            pB[q] = *(const float4*)(Bf + (size_t)(bn + row) * K + kBeg + kt + fkc);
        }
    };
    auto STORE = [&](int buf) {
        uint32_t* dA = sA + buf * A_BUF_W;
        uint32_t* dB = sB + buf * PLANE_W;
        #pragma unroll
        for (int q = 0; q < 2; q++) {
            int row = frow + (q << 5);
            uint4 hi, lo;
            tf32split(pA[q].x, hi.x, lo.x); tf32split(pA[q].y, hi.y, lo.y);
            tf32split(pA[q].z, hi.z, lo.z); tf32split(pA[q].w, hi.w, lo.w);
            *(uint4*)(dA + row * 36 + fkc)           = hi;
            *(uint4*)(dA + PLANE_W + row * 36 + fkc) = lo;
            uint4 bh;
            bh.x = tf32rna(pB[q].x); bh.y = tf32rna(pB[q].y);
            bh.z = tf32rna(pB[q].z); bh.w = tf32rna(pB[q].w);
            *(uint4*)(dB + row * 36 + fkc) = bh;
        }
    };

    FETCH(0);
    STORE(0);
    __syncthreads();

    for (int t = 0; t < nt; t++) {
        int cur = t & 1;
        bool more = (t + 1 < nt);
        if (more) FETCH((t + 1) << 5);

        uint32_t aB  = aBaseS + cur * A_BUF_BYTES + aOff;
        uint32_t bB0 = bBaseS + cur * B_BUF_BYTES + bOff;
        uint32_t bB1 = bB0 + ((16 * 36) << 2);
        #pragma unroll
        for (int ks = 0; ks < 4; ks++) {
            uint32_t koff = (ks << 3) << 2;
            uint32_t ah[4], al[4], bh[2][4];
            ldsm_x4(ah, aB + koff);
            ldsm_x4(al, aB + LO_BYTES + koff);
            ldsm_x4(bh[0], bB0 + koff);
            ldsm_x4(bh[1], bB1 + koff);
            #pragma unroll
            for (int p = 0; p < 2; p++)
                #pragma unroll
                for (int half = 0; half < 2; half++) {
                    int ns = (p << 1) + half;
                    const uint32_t bfh[2] = {bh[p][half << 1], bh[p][(half << 1) + 1]};
                    mma_tf32(acc[ns], ah, bfh);
                    mma_tf32(acc[ns], al, bfh);
                }
        }
        if (more) STORE(cur ^ 1);
        __syncthreads();
    }

    float* Cp = C + (size_t)blockIdx.z * M * N;
    int r0 = bm + warpM + g;
    #pragma unroll
    for (int ns = 0; ns < 4; ns++) {
        int c0 = bn + warpN + (ns << 3) + (tig << 1);
        size_t o0 = (size_t)r0 * N + c0, o2 = (size_t)(r0 + 8) * N + c0;
        Cp[o0] = acc[ns][0]; Cp[o0 + 1] = acc[ns][1];
        Cp[o2] = acc[ns][2]; Cp[o2 + 1] = acc[ns][3];
    }
}

// =======================================================================
// 3xTF32 GEMM for transposed-B (B row-major [K,N]); full accuracy for the
// output-path head GEMMs; split-K; partial out.
// =======================================================================
__global__ __launch_bounds__(256)
void gemm_t(const float* __restrict__ Af, const float* __restrict__ Bf,
            float* __restrict__ C, int M, int N, int K, int ldb, int kChunk)
{
    __shared__ uint32_t sA[2][64][36];
    __shared__ uint32_t sB[2][64][36];

    int tid  = threadIdx.x;
    int lane = tid & 31, wid = tid >> 5;
    int warpM = (wid >> 1) << 4;
    int warpN = (wid & 1) << 5;
    int g = lane >> 2, tig = lane & 3;
    int bm = blockIdx.y << 6, bn = blockIdx.x << 6;
    int kBeg = blockIdx.z * kChunk;

    uint32_t aBase = smem_u32(&sA[0][0][0]) +
        (((warpM + (lane & 15)) * 36 + ((lane >> 4) << 2)) << 2);
    uint32_t bBase0 = smem_u32(&sB[0][0][0]) +
        (((warpN + ((lane >> 4) << 3) + (lane & 7)) * 36 + (((lane >> 3) & 1) << 2)) << 2);
    uint32_t bBase1 = bBase0 + (16 * 36 << 2);
    const uint32_t LO = (64 * 36) << 2;

    float acc[4][4];
    #pragma unroll
    for (int ns = 0; ns < 4; ns++)
        #pragma unroll
        for (int r = 0; r < 4; r++) acc[ns][r] = 0.f;

    float4 pA[2], pB[2];
    #pragma unroll
    for (int q = 0; q < 2; q++) {
        int idx = tid + (q << 8);
        int row = idx >> 3, kc = (idx & 7) << 2;
        pA[q] = *(const float4*)(Af + (size_t)(bm + row) * K + kBeg + kc);
        int k = idx >> 4, n0 = (idx & 15) << 2;
        pB[q] = *(const float4*)(Bf + (size_t)(kBeg + k) * ldb + bn + n0);
    }

    for (int kt = 0; kt < kChunk; kt += 32) {
        #pragma unroll
        for (int q = 0; q < 2; q++) {
            int idx = tid + (q << 8);
            {
                int row = idx >> 3, kc = (idx & 7) << 2;
                uint4 hi, lo;
                tf32split(pA[q].x, hi.x, lo.x); tf32split(pA[q].y, hi.y, lo.y);
                tf32split(pA[q].z, hi.z, lo.z); tf32split(pA[q].w, hi.w, lo.w);
                *(uint4*)&sA[0][row][kc] = hi;
                *(uint4*)&sA[1][row][kc] = lo;
            }
            {
                int k = idx >> 4, n0 = (idx & 15) << 2;
                float v[4] = {pB[q].x, pB[q].y, pB[q].z, pB[q].w};
                #pragma unroll
                for (int j = 0; j < 4; j++) {
                    uint32_t hb, lb; tf32split(v[j], hb, lb);
                    sB[0][n0 + j][k] = hb; sB[1][n0 + j][k] = lb;
                }
            }
        }
        __syncthreads();

        int ktn = kt + 32;
        if (ktn < kChunk) {
            #pragma unroll
            for (int q = 0; q < 2; q++) {
                int idx = tid + (q << 8);
                int row = idx >> 3, kc = (idx & 7) << 2;
                pA[q] = *(const float4*)(Af + (size_t)(bm + row) * K + kBeg + ktn + kc);
                int k = idx >> 4, n0 = (idx & 15) << 2;
                pB[q] = *(const float4*)(Bf + (size_t)(kBeg + ktn + k) * ldb + bn + n0);
            }
        }

        #pragma unroll
        for (int ks = 0; ks < 4; ks++) {
            uint32_t koff = (ks << 3) << 2;
            uint32_t ah[4], al[4], bh[2][4], bl[2][4];
            ldsm_x4(ah, aBase + koff);
            ldsm_x4(al, aBase + LO + koff);
            ldsm_x4(bh[0], bBase0 + koff);
            ldsm_x4(bl[0], bBase0 + LO + koff);
            ldsm_x4(bh[1], bBase1 + koff);
            ldsm_x4(bl[1], bBase1 + LO + koff);
            #pragma unroll
            for (int p = 0; p < 2; p++)
                #pragma unroll
                for (int half = 0; half < 2; half++) {
                    int ns = (p << 1) + half;
                    const uint32_t bfh[2] = {bh[p][half << 1], bh[p][(half << 1) + 1]};
                    const uint32_t bfl[2] = {bl[p][half << 1], bl[p][(half << 1) + 1]};
                    mma_tf32(acc[ns], ah, bfh);
                    mma_tf32(acc[ns], ah, bfl);
                    mma_tf32(acc[ns], al, bfh);
                }
        }
        __syncthreads();
    }

    float* Cp = C + (size_t)blockIdx.z * M * N;
    int r0 = bm + warpM + g;
    #pragma unroll
    for (int ns = 0; ns < 4; ns++) {
        int c0 = bn + warpN + (ns << 3) + (tig << 1);
        size_t o0 = (size_t)r0 * N + c0, o2 = (size_t)(r0 + 8) * N + c0;
        Cp[o0] = acc[ns][0]; Cp[o0 + 1] = acc[ns][1];
        Cp[o2] = acc[ns][2]; Cp[o2 + 1] = acc[ns][3];
    }
}

// =======================================================================
// Reduce split-K partials + bias (+relu)
// =======================================================================
__global__ __launch_bounds__(256)
void reduceSK(const float* __restrict__ part, int S, int plane,
              const float* __restrict__ bias, int act,
              float* __restrict__ out, int total, int N)
{
    int idx = blockIdx.x * 256 + threadIdx.x;
    if (idx >= total) return;
    float v = bias[idx % N];
    for (int s = 0; s < S; s++) v += part[(size_t)s * plane + idx];
    if (act) v = fmaxf(v, 0.f);
    out[idx] = v;
}

// =======================================================================
// GRU gates (hidden==0): reduce S split-K partials + bih + bhh; h=(1-z)n
// =======================================================================
__global__ __launch_bounds__(256)
void gru_gatesS(const float* __restrict__ gip, int S,
                const float* __restrict__ bih, const float* __restrict__ bhh,
                float* __restrict__ h)
{
    int idx = blockIdx.x * 256 + threadIdx.x;
    int b = idx >> 8, j = idx & 255;
    const float* g0 = gip + (size_t)b * G3;
    const size_t P = (size_t)BB * G3;
    float vr = bih[j], vz = bih[256 + j], vn = bih[512 + j];
    for (int s = 0; s < S; s++) {
        vr += g0[s * P + j];
        vz += g0[s * P + 256 + j];
        vn += g0[s * P + 512 + j];
    }
    float r = 1.f / (1.f + __expf(-(vr + bhh[j])));
    float z = 1.f / (1.f + __expf(-(vz + bhh[256 + j])));
    float n = tanhf(vn + r * bhh[512 + j]);
    h[idx] = (1.f - z) * n;
}

// =======================================================================
// LayerNorm over GRU dim
// =======================================================================
__global__ __launch_bounds__(256)
void ln1d_k(const float* __restrict__ h, const float* __restrict__ g,
            const float* __restrict__ b, float* __restrict__ o)
{
    __shared__ float s1[8], s2[8], mv[2];
    int row = blockIdx.x, tid = threadIdx.x;
    float v = h[(size_t)row * GRUU + tid];
    float s = v, q = v * v;
    #pragma unroll
    for (int off = 16; off; off >>= 1) {
        s += __shfl_xor_sync(0xffffffffu, s, off);
        q += __shfl_xor_sync(0xffffffffu, q, off);
    }
    if ((tid & 31) == 0) { s1[tid >> 5] = s; s2[tid >> 5] = q; }
    __syncthreads();
    if (tid == 0) {
        float S = 0.f, Q = 0.f;
        #pragma unroll
        for (int i = 0; i < 8; i++) { S += s1[i]; Q += s2[i]; }
        float m = S * (1.f / 256.f);
        float var = Q * (1.f / 256.f) - m * m;
        mv[0] = m; mv[1] = rsqrtf(var + 1e-5f);
    }
    __syncthreads();
    o[(size_t)row * GRUU + tid] = (v - mv[0]) * mv[1] * g[tid] + b[tid];
}

// =======================================================================
// host launcher
// =======================================================================
extern "C" void kernel_launch(void* const* d_in, const int* in_sizes, int n_in,
                              void* d_out, int out_size)
{
    const float* X    = (const float*)d_in[0];
    const int*   A    = (const int*)  d_in[1];
    const float* W1   = (const float*)d_in[2];
    const float* a1   = (const float*)d_in[3];
    const float* W2   = (const float*)d_in[4];
    const float* a2   = (const float*)d_in[5];
    const float* Wr   = (const float*)d_in[6];
    const float* br   = (const float*)d_in[7];
    const float* g1   = (const float*)d_in[8];
    const float* b1   = (const float*)d_in[9];
    const float* g2   = (const float*)d_in[10];
    const float* b2   = (const float*)d_in[11];
    const float* Wih0 = (const float*)d_in[12];
    const float* bih0 = (const float*)d_in[14];
    const float* bhh0 = (const float*)d_in[15];
    const float* Wih1 = (const float*)d_in[16];
    const float* bih1 = (const float*)d_in[18];
    const float* bhh1 = (const float*)d_in[19];
    const float* Wih2 = (const float*)d_in[20];
    const float* bih2 = (const float*)d_in[22];
    const float* bhh2 = (const float*)d_in[23];
    const float* gng  = (const float*)d_in[24];
    const float* gnb  = (const float*)d_in[25];
    const float* We   = (const float*)d_in[26];
    const float* be   = (const float*)d_in[27];
    const float* Wp   = (const float*)d_in[28];
    const float* bp   = (const float*)d_in[29];
    float* out = (float*)d_out;

    float *px, *pgip, *ph, *phln, *pemb;
    cudaGetSymbolAddress((void**)&px,   g_x);
    cudaGetSymbolAddress((void**)&pgip, g_gip);
    cudaGetSymbolAddress((void**)&ph,   g_h);
    cudaGetSymbolAddress((void**)&phln, g_hln);
    cudaGetSymbolAddress((void**)&pemb, g_emb);

    const int GAT_SMEM = GAT_WORDS * 4;
    cudaFuncSetAttribute(gat_kernel, cudaFuncAttributeMaxDynamicSharedMemorySize, GAT_SMEM);
    cudaFuncSetAttribute(gemm_nk, cudaFuncAttributeMaxDynamicSharedMemorySize, GEMM_SMEM);

    // 5 no-op launches so ncu's "-s 5 -c 1" capture lands on gat_kernel
    for (int i = 0; i < 5; i++) noop_k<<<1, 32>>>();

    gat_kernel<<<BB, TG, GAT_SMEM>>>(X, A, W1, a1, W2, a2, Wr, br, g1, b1, g2, b2);

    // GRU layer 0: split-K x8 (chunk 768 -> 24 BK32 tiles, grid 1536)
    dim3 g0(G3 / 64, BB / 64, SK0);
    gemm_nk<<<g0, 256, GEMM_SMEM>>>(px, Wih0, pgip, BB, G3, XG, XG / SK0);
    gru_gatesS<<<BB, 256>>>(pgip, SK0, bih0, bhh0, ph);

    // GRU layers 1 & 2: split-K x2 (chunk 128 -> 4 tiles)
    dim3 g12(G3 / 64, BB / 64, 2);
    gemm_nk<<<g12, 256, GEMM_SMEM>>>(ph, Wih1, pgip, BB, G3, GRUU, GRUU / 2);
    gru_gatesS<<<BB, 256>>>(pgip, 2, bih1, bhh1, ph);
    gemm_nk<<<g12, 256, GEMM_SMEM>>>(ph, Wih2, pgip, BB, G3, GRUU, GRUU / 2);
    gru_gatesS<<<BB, 256>>>(pgip, 2, bih2, bhh2, ph);

    ln1d_k<<<BB, 256>>>(ph, gng, gnb, phln);

    float* embp = (out_size >= 2 * BB * EMBB) ? (out + (size_t)BB * EMBB) : pemb;

    // emb = relu(hln @ We + be): split-K x4 (K=256, chunk 64)
    dim3 gEmb(EMBB / 64, BB / 64, 4);
    gemm_t<<<gEmb, 256>>>(phln, We, pgip, BB, EMBB, GRUU, EMBB, GRUU / 4);
    reduceSK<<<(BB * EMBB + 255) / 256, 256>>>(pgip, 4, BB * EMBB, be, 1,
                                               embp, BB * EMBB, EMBB);

    // pred = emb @ Wp + bp: split-K x2 (K=128, chunk 64)
    dim3 gPred(NN / 64, BB / 64, 2);
    gemm_t<<<gPred, 256>>>(embp, Wp, pgip, BB, NN, EMBB, NN, EMBB / 2);
    reduceSK<<<(BB * NN + 255) / 256, 256>>>(pgip, 2, BB * NN, bp, 0,
                                             out, BB * NN, NN);
}

// round 13
// speedup vs baseline: 1.4072x; 1.0427x over previous
#include <cuda_runtime.h>
#include <cstdint>

// ---------------- problem constants ----------------
#define BB   1024
#define NN   128
#define FF   16
#define GG   48
#define HH   6
#define DD   8
#define GRUU 256
#define EMBB 128
#define XG   (NN*GG)       // 6144
#define G3   (3*GRUU)      // 768
#define SK0  8             // split-K for GRU0
#define TG   384           // GAT block size (12 warps)

// ---------------- scratch ----------------
__device__ float g_x  [BB*XG];
__device__ float g_gip[SK0*BB*G3];
__device__ float g_h  [BB*GRUU];
__device__ float g_hln[BB*GRUU];
__device__ float g_emb[BB*EMBB];

// ---------------- helpers ----------------
__device__ __forceinline__ void tf32split(float v, uint32_t& h, uint32_t& l) {
    uint32_t hb; asm("cvt.rna.tf32.f32 %0, %1;" : "=r"(hb) : "f"(v));
    float lv = v - __uint_as_float(hb);
    uint32_t lb; asm("cvt.rna.tf32.f32 %0, %1;" : "=r"(lb) : "f"(lv));
    h = hb; l = lb;
}

__device__ __forceinline__ uint32_t tf32rna(float v) {
    uint32_t r; asm("cvt.rna.tf32.f32 %0, %1;" : "=r"(r) : "f"(v));
    return r;
}

__device__ __forceinline__ uint32_t smem_u32(const void* p) {
    uint32_t a;
    asm("{ .reg .u64 t; cvta.to.shared.u64 t, %1; cvt.u32.u64 %0, t; }" : "=r"(a) : "l"(p));
    return a;
}

__device__ __forceinline__ void ldsm_x4(uint32_t* d, uint32_t addr) {
    asm volatile("ldmatrix.sync.aligned.m8n8.x4.shared.b16 {%0,%1,%2,%3}, [%4];"
        : "=r"(d[0]), "=r"(d[1]), "=r"(d[2]), "=r"(d[3]) : "r"(addr));
}

__device__ __forceinline__ void mma_tf32(float* c, const uint32_t* a, const uint32_t* b) {
    asm volatile("mma.sync.aligned.m16n8k8.row.col.f32.tf32.tf32.f32 "
        "{%0,%1,%2,%3}, {%4,%5,%6,%7}, {%8,%9}, {%0,%1,%2,%3};\n"
        : "+f"(c[0]), "+f"(c[1]), "+f"(c[2]), "+f"(c[3])
        : "r"(a[0]), "r"(a[1]), "r"(a[2]), "r"(a[3]), "r"(b[0]), "r"(b[1]));
}

// =======================================================================
// GAT attention via tensor cores. 12 warps -> 4 tasks/warp.
// No explicit cvt: mma hw truncates fp32->tf32 identically for the w@h
// MMAs and the w@ones row-sum MMA, so softmax stays exactly normalized.
// All-ones B puts the row sum in every lane's own accumulator (no shfl).
// =======================================================================
__device__ __forceinline__ void gat_attention_mma(
    const uint32_t* __restrict__ sh_hi, const uint32_t* __restrict__ sh_lo,
    const float* __restrict__ sei, const float* __restrict__ sej,
    const float* __restrict__ sPj, const float* __restrict__ sQj,
    const unsigned* __restrict__ smask, float* __restrict__ sy, int tid)
{
    int lane = tid & 31, wid = tid >> 5;
    int g = lane >> 2, tig = lane & 3;
    const uint32_t ONES[2] = {0x3F800000u, 0x3F800000u};

    #pragma unroll 1
    for (int task = wid; task < 48; task += 12) {
        int hd = task >> 3, m0 = (task & 7) << 4;
        int r0 = m0 + g, r1 = r0 + 8;
        float ei0 = sei[(hd << 7) + r0], ei1 = sei[(hd << 7) + r1];
        float Pi0 = __expf(ei0), Qi0 = __expf(0.01f * ei0);
        float Pi1 = __expf(ei1), Qi1 = __expf(0.01f * ei1);
        const unsigned* mr0 = smask + (r0 << 2);
        const unsigned* mr1 = smask + (r1 << 2);
        const float* ejp = sej + (hd << 7);
        const float* Pjp = sPj + (hd << 7);
        const float* Qjp = sQj + (hd << 7);
        const uint32_t* hhi = sh_hi + (hd << 10);
        const uint32_t* hlo = sh_lo + (hd << 10);

        float c[4]  = {0.f, 0.f, 0.f, 0.f};
        float cs[4] = {0.f, 0.f, 0.f, 0.f};

        #pragma unroll 1
        for (int jw = 0; jw < 4; jw++) {
            unsigned w0 = mr0[jw], w1 = mr1[jw];
            #pragma unroll
            for (int q = 0; q < 4; q++) {
                int j0 = (jw << 5) + (q << 3);
                unsigned mt0 = w0 >> ((q << 3) + tig);
                unsigned mt1 = w1 >> ((q << 3) + tig);
                int jA = j0 + tig, jB = jA + 4;
                float ejA = ejp[jA], ejB = ejp[jB];
                float PjA = Pjp[jA], PjB = Pjp[jB];
                float QjA = Qjp[jA], QjB = Qjp[jB];

                float wa0 = (ei0 + ejA > 0.f) ? (Pi0 * PjA) : (Qi0 * QjA);
                float wa1 = (ei1 + ejA > 0.f) ? (Pi1 * PjA) : (Qi1 * QjA);
                float wa2 = (ei0 + ejB > 0.f) ? (Pi0 * PjB) : (Qi0 * QjB);
                float wa3 = (ei1 + ejB > 0.f) ? (Pi1 * PjB) : (Qi1 * QjB);
                wa0 = (mt0 & 1u)  ? wa0 : 0.f;
                wa1 = (mt1 & 1u)  ? wa1 : 0.f;
                wa2 = (mt0 & 16u) ? wa2 : 0.f;
                wa3 = (mt1 & 16u) ? wa3 : 0.f;

                uint32_t a[4];
                a[0] = __float_as_uint(wa0); a[1] = __float_as_uint(wa1);
                a[2] = __float_as_uint(wa2); a[3] = __float_as_uint(wa3);

                uint32_t bh[2] = { hhi[(jA << 3) + g], hhi[(jB << 3) + g] };
                uint32_t bl[2] = { hlo[(jA << 3) + g], hlo[(jB << 3) + g] };
                mma_tf32(c, a, bh);
                mma_tf32(c, a, bl);
                mma_tf32(cs, a, ONES);   // row sums of truncated w
            }
        }
        float inv0 = 1.0f / cs[0], inv1 = 1.0f / cs[2];

        float* o0 = sy + r0 * 49 + (hd << 3) + (tig << 1);
        float* o1 = sy + r1 * 49 + (hd << 3) + (tig << 1);
        o0[0] = c[0] * inv0; o0[1] = c[1] * inv0;
        o1[0] = c[2] * inv1; o1[1] = c[3] * inv1;
    }
}

// LayerNorm over all [N,G] of one batch, + ReLU. sy row stride 49. 12 warps.
__device__ __forceinline__ void ln2d_apply(
    float* __restrict__ sy, const float* __restrict__ gamma,
    const float* __restrict__ beta, float* __restrict__ sred,
    int tid, float* __restrict__ gout)
{
    float s = 0.f, q = 0.f;
    for (int t = tid; t < XG; t += TG) {
        int n = t / 48, c = t - n * 48;
        float v = sy[n * 49 + c];
        s += v; q += v * v;
    }
    #pragma unroll
    for (int o = 16; o; o >>= 1) {
        s += __shfl_xor_sync(0xffffffffu, s, o);
        q += __shfl_xor_sync(0xffffffffu, q, o);
    }
    int wid = tid >> 5;
    if ((tid & 31) == 0) { sred[wid] = s; sred[12 + wid] = q; }
    __syncthreads();
    if (tid == 0) {
        float S = 0.f, Q = 0.f;
        #pragma unroll
        for (int i = 0; i < 12; i++) { S += sred[i]; Q += sred[12 + i]; }
        float m   = S * (1.f / (float)XG);
        float var = Q * (1.f / (float)XG) - m * m;
        sred[24] = m;
        sred[25] = rsqrtf(var + 1e-5f);
    }
    __syncthreads();
    float m = sred[24], rs = sred[25];
    for (int t = tid; t < XG; t += TG) {
        int n = t / 48, c = t - n * 48;
        float v = (sy[n * 49 + c] - m) * rs * gamma[t] + beta[t];
        v = fmaxf(v, 0.f);
        if (gout) gout[t] = v; else sy[n * 49 + c] = v;
    }
}

// GAT smem layout (words)
#define S_X    0
#define S_HHI  2176
#define S_HLO  (S_HHI + 6144)
#define S_Y    (S_HLO + 6144)
#define S_EI   (S_Y + 6272)
#define S_EJ   (S_EI + 768)
#define S_PJ   (S_EJ + 768)
#define S_QJ   (S_PJ + 768)
#define S_W    (S_QJ + 768)
#define S_A    (S_W + 2304)
#define S_RED  (S_A + 96)
#define S_MASK (S_RED + 32)
#define GAT_WORDS (S_MASK + 512)

__global__ __launch_bounds__(TG)
void gat_kernel(const float* __restrict__ X,  const int* __restrict__ A,
                const float* __restrict__ W1, const float* __restrict__ a1,
                const float* __restrict__ W2, const float* __restrict__ a2,
                const float* __restrict__ Wr, const float* __restrict__ br,
                const float* __restrict__ g1, const float* __restrict__ b1,
                const float* __restrict__ g2, const float* __restrict__ b2)
{
    extern __shared__ float sm[];
    float*    sX    = sm + S_X;
    uint32_t* sh_hi = (uint32_t*)(sm + S_HHI);
    uint32_t* sh_lo = (uint32_t*)(sm + S_HLO);
    float*    sy    = sm + S_Y;
    float*    sei   = sm + S_EI;
    float*    sej   = sm + S_EJ;
    float*    sPj   = sm + S_PJ;
    float*    sQj   = sm + S_QJ;
    float*    sW    = sm + S_W;
    float*    sa    = sm + S_A;
    float*    sred  = sm + S_RED;
    unsigned* smask = (unsigned*)(sm + S_MASK);

    int b = blockIdx.x, tid = threadIdx.x;

    const float* Xb = X + (size_t)b * (NN * FF);
    for (int t = tid; t < NN * FF; t += TG)
        sX[(t >> 4) * 17 + (t & 15)] = Xb[t];

    {
        const int* Ab = A + (size_t)b * (NN * NN);
        int lane = tid & 31, wid = tid >> 5;
        for (int w = wid; w < 512; w += 12) {
            int i = w >> 2, j0 = (w & 3) << 5;
            unsigned bits = __ballot_sync(0xffffffffu, Ab[(i << 7) + j0 + lane] != 0);
            if (lane == 0) smask[w] = bits;
        }
    }
    for (int t = tid; t < HH * FF * DD; t += TG) sW[t] = W1[t];
    if (tid < HH * 2 * DD) sa[tid] = a1[tid];
    __syncthreads();

    // ---- layer 1: h = X@W1 (split to hi/lo), scores, per-node exps ----
    for (int t = tid; t < HH * NN; t += TG) {
        int hd = t >> 7, n = t & 127;
        float acc[8];
        #pragma unroll
        for (int d = 0; d < 8; d++) acc[d] = 0.f;
        const float* w = sW + hd * (FF * DD);
        const float* x = sX + n * 17;
        #pragma unroll
        for (int f = 0; f < FF; f++) {
            float xv = x[f];
            #pragma unroll
            for (int d = 0; d < 8; d++) acc[d] = fmaf(xv, w[(f << 3) + d], acc[d]);
        }
        const float* av = sa + (hd << 4);
        float ei = 0.f, ej = 0.f;
        #pragma unroll
        for (int d = 0; d < 8; d++) { ei = fmaf(acc[d], av[d], ei); ej = fmaf(acc[d], av[8 + d], ej); }
        #pragma unroll
        for (int d = 0; d < 8; d++) {
            uint32_t hb, lb; tf32split(acc[d], hb, lb);
            sh_hi[(t << 3) + d] = hb; sh_lo[(t << 3) + d] = lb;
        }
        sei[t] = ei; sej[t] = ej;
        sPj[t] = __expf(ej); sQj[t] = __expf(0.01f * ej);
    }
    __syncthreads();
    gat_attention_mma(sh_hi, sh_lo, sei, sej, sPj, sQj, smask, sy, tid);
    __syncthreads();
    ln2d_apply(sy, g1, b1, sred, tid, nullptr);
    __syncthreads();

    // ---- layer 2 weights ----
    for (int t = tid; t < HH * GG * DD; t += TG) sW[t] = W2[t];
    if (tid < HH * 2 * DD) sa[tid] = a2[tid];
    __syncthreads();

    // ---- layer 2: h2 = y@W2 ----
    for (int t = tid; t < HH * NN; t += TG) {
        int hd = t >> 7, n = t & 127;
        float acc[8];
        #pragma unroll
        for (int d = 0; d < 8; d++) acc[d] = 0.f;
        const float* w = sW + hd * (GG * DD);
        const float* x = sy + n * 49;
        #pragma unroll
        for (int f = 0; f < GG; f++) {
            float xv = x[f];
            #pragma unroll
            for (int d = 0; d < 8; d++) acc[d] = fmaf(xv, w[(f << 3) + d], acc[d]);
        }
        const float* av = sa + (hd << 4);
        float ei = 0.f, ej = 0.f;
        #pragma unroll
        for (int d = 0; d < 8; d++) { ei = fmaf(acc[d], av[d], ei); ej = fmaf(acc[d], av[8 + d], ej); }
        #pragma unroll
        for (int d = 0; d < 8; d++) {
            uint32_t hb, lb; tf32split(acc[d], hb, lb);
            sh_hi[(t << 3) + d] = hb; sh_lo[(t << 3) + d] = lb;
        }
        sei[t] = ei; sej[t] = ej;
        sPj[t] = __expf(ej); sQj[t] = __expf(0.01f * ej);
    }
    __syncthreads();
    gat_attention_mma(sh_hi, sh_lo, sei, sej, sPj, sQj, smask, sy, tid);
    __syncthreads();

    // ---- residual: sy += X@Wr + br ----
    for (int t = tid; t < FF * GG; t += TG) sW[t] = Wr[t];
    if (tid < GG) sa[tid] = br[tid];
    __syncthreads();
    for (int t = tid; t < XG; t += TG) {
        int n = t / 48, c = t - n * 48;
        float accv = sa[c];
        const float* x = sX + n * 17;
        #pragma unroll
        for (int f = 0; f < FF; f++) accv = fmaf(x[f], sW[f * 48 + c], accv);
        sy[n * 49 + c] += accv;
    }
    __syncthreads();
    ln2d_apply(sy, g2, b2, sred, tid, g_x + (size_t)b * XG);
}

// =======================================================================
// Double-buffered 2xTF32 GEMM, BK=32. A split hi/lo; B hi-only.
// B row-major [N,K]. Split-K via grid.z -> partial C at z*M*N.
// =======================================================================
#define PLANE_W     (64*36)
#define LO_BYTES    (PLANE_W*4)
#define A_BUF_W     (2*PLANE_W)
#define A_BUF_BYTES (A_BUF_W*4)
#define B_BUF_BYTES (PLANE_W*4)
#define GEMM_SMEM   (6*PLANE_W*4)   // 55296

__global__ __launch_bounds__(256)
void gemm_nk(const float* __restrict__ Af, const float* __restrict__ Bf,
             float* __restrict__ C, int M, int N, int K, int kChunk)
{
    extern __shared__ uint32_t smem[];
    uint32_t* sA = smem;
    uint32_t* sB = smem + 2 * A_BUF_W;

    int tid  = threadIdx.x;
    int lane = tid & 31, wid = tid >> 5;
    int warpM = (wid >> 1) << 4;
    int warpN = (wid & 1) << 5;
    int g = lane >> 2, tig = lane & 3;
    int bm = blockIdx.y << 6, bn = blockIdx.x << 6;
    int kBeg = blockIdx.z * kChunk;
    int nt   = kChunk >> 5;

    uint32_t aOff = (((warpM + (lane & 15)) * 36 + ((lane >> 4) << 2)) << 2);
    uint32_t bOff = (((warpN + ((lane >> 4) << 3) + (lane & 7)) * 36 + (((lane >> 3) & 1) << 2)) << 2);
    uint32_t aBaseS = smem_u32(sA);
    uint32_t bBaseS = smem_u32(sB);

    int frow = tid >> 3;
    int fkc  = (tid & 7) << 2;

    float acc[4][4];
    #pragma unroll
    for (int ns = 0; ns < 4; ns++)
        #pragma unroll
        for (int r = 0; r < 4; r++) acc[ns][r] = 0.f;

    float4 pA[2], pB[2];

    auto FETCH = [&](int kt) {
        #pragma unroll
        for (int q = 0; q < 2; q++) {
            int row = frow + (q << 5);
            pA[q] = *(const float4*)(Af + (size_t)(bm + row) * K + kBeg + kt + fkc);
            pB[q] = *(const float4*)(Bf + (size_t)(bn + row) * K + kBeg + kt + fkc);
        }
    };
    auto STORE = [&](int buf) {
        uint32_t* dA = sA + buf * A_BUF_W;
        uint32_t* dB = sB + buf * PLANE_W;
        #pragma unroll
        for (int q = 0; q < 2; q++) {
            int row = frow + (q << 5);
            uint4 hi, lo;
            tf32split(pA[q].x, hi.x, lo.x); tf32split(pA[q].y, hi.y, lo.y);
            tf32split(pA[q].z, hi.z, lo.z); tf32split(pA[q].w, hi.w, lo.w);
            *(uint4*)(dA + row * 36 + fkc)           = hi;
            *(uint4*)(dA + PLANE_W + row * 36 + fkc) = lo;
            uint4 bh;
            bh.x = tf32rna(pB[q].x); bh.y = tf32rna(pB[q].y);
            bh.z = tf32rna(pB[q].z); bh.w = tf32rna(pB[q].w);
            *(uint4*)(dB + row * 36 + fkc) = bh;
        }
    };

    FETCH(0);
    STORE(0);
    __syncthreads();

    for (int t = 0; t < nt; t++) {
        int cur = t & 1;
        bool more = (t + 1 < nt);
        if (more) FETCH((t + 1) << 5);

        uint32_t aB  = aBaseS + cur * A_BUF_BYTES + aOff;
        uint32_t bB0 = bBaseS + cur * B_BUF_BYTES + bOff;
        uint32_t bB1 = bB0 + ((16 * 36) << 2);
        #pragma unroll
        for (int ks = 0; ks < 4; ks++) {
            uint32_t koff = (ks << 3) << 2;
            uint32_t ah[4], al[4], bh[2][4];
            ldsm_x4(ah, aB + koff);
            ldsm_x4(al, aB + LO_BYTES + koff);
            ldsm_x4(bh[0], bB0 + koff);
            ldsm_x4(bh[1], bB1 + koff);
            #pragma unroll
            for (int p = 0; p < 2; p++)
                #pragma unroll
                for (int half = 0; half < 2; half++) {
                    int ns = (p << 1) + half;
                    const uint32_t bfh[2] = {bh[p][half << 1], bh[p][(half << 1) + 1]};
                    mma_tf32(acc[ns], ah, bfh);
                    mma_tf32(acc[ns], al, bfh);
                }
        }
        if (more) STORE(cur ^ 1);
        __syncthreads();
    }

    float* Cp = C + (size_t)blockIdx.z * M * N;
    int r0 = bm + warpM + g;
    #pragma unroll
    for (int ns = 0; ns < 4; ns++) {
        int c0 = bn + warpN + (ns << 3) + (tig << 1);
        size_t o0 = (size_t)r0 * N + c0, o2 = (size_t)(r0 + 8) * N + c0;
        Cp[o0] = acc[ns][0]; Cp[o0 + 1] = acc[ns][1];
        Cp[o2] = acc[ns][2]; Cp[o2 + 1] = acc[ns][3];
    }
}

// =======================================================================
// 3xTF32 GEMM for transposed-B (B row-major [K,N]); full accuracy for the
// output-path head GEMMs; split-K; partial out.
// =======================================================================
__global__ __launch_bounds__(256)
void gemm_t(const float* __restrict__ Af, const float* __restrict__ Bf,
            float* __restrict__ C, int M, int N, int K, int ldb, int kChunk)
{
    __shared__ uint32_t sA[2][64][36];
    __shared__ uint32_t sB[2][64][36];

    int tid  = threadIdx.x;
    int lane = tid & 31, wid = tid >> 5;
    int warpM = (wid >> 1) << 4;
    int warpN = (wid & 1) << 5;
    int g = lane >> 2, tig = lane & 3;
    int bm = blockIdx.y << 6, bn = blockIdx.x << 6;
    int kBeg = blockIdx.z * kChunk;

    uint32_t aBase = smem_u32(&sA[0][0][0]) +
        (((warpM + (lane & 15)) * 36 + ((lane >> 4) << 2)) << 2);
    uint32_t bBase0 = smem_u32(&sB[0][0][0]) +
        (((warpN + ((lane >> 4) << 3) + (lane & 7)) * 36 + (((lane >> 3) & 1) << 2)) << 2);
    uint32_t bBase1 = bBase0 + (16 * 36 << 2);
    const uint32_t LO = (64 * 36) << 2;

    float acc[4][4];
    #pragma unroll
    for (int ns = 0; ns < 4; ns++)
        #pragma unroll
        for (int r = 0; r < 4; r++) acc[ns][r] = 0.f;

    float4 pA[2], pB[2];
    #pragma unroll
    for (int q = 0; q < 2; q++) {
        int idx = tid + (q << 8);
        int row = idx >> 3, kc = (idx & 7) << 2;
        pA[q] = *(const float4*)(Af + (size_t)(bm + row) * K + kBeg + kc);
        int k = idx >> 4, n0 = (idx & 15) << 2;
        pB[q] = *(const float4*)(Bf + (size_t)(kBeg + k) * ldb + bn + n0);
    }

    for (int kt = 0; kt < kChunk; kt += 32) {
        #pragma unroll
        for (int q = 0; q < 2; q++) {
            int idx = tid + (q << 8);
            {
                int row = idx >> 3, kc = (idx & 7) << 2;
                uint4 hi, lo;
                tf32split(pA[q].x, hi.x, lo.x); tf32split(pA[q].y, hi.y, lo.y);
                tf32split(pA[q].z, hi.z, lo.z); tf32split(pA[q].w, hi.w, lo.w);
                *(uint4*)&sA[0][row][kc] = hi;
                *(uint4*)&sA[1][row][kc] = lo;
            }
            {
                int k = idx >> 4, n0 = (idx & 15) << 2;
                float v[4] = {pB[q].x, pB[q].y, pB[q].z, pB[q].w};
                #pragma unroll
                for (int j = 0; j < 4; j++) {
                    uint32_t hb, lb; tf32split(v[j], hb, lb);
                    sB[0][n0 + j][k] = hb; sB[1][n0 + j][k] = lb;
                }
            }
        }
        __syncthreads();

        int ktn = kt + 32;
        if (ktn < kChunk) {
            #pragma unroll
            for (int q = 0; q < 2; q++) {
                int idx = tid + (q << 8);
                int row = idx >> 3, kc = (idx & 7) << 2;
                pA[q] = *(const float4*)(Af + (size_t)(bm + row) * K + kBeg + ktn + kc);
                int k = idx >> 4, n0 = (idx & 15) << 2;
                pB[q] = *(const float4*)(Bf + (size_t)(kBeg + ktn + k) * ldb + bn + n0);
            }
        }

        #pragma unroll
        for (int ks = 0; ks < 4; ks++) {
            uint32_t koff = (ks << 3) << 2;
            uint32_t ah[4], al[4], bh[2][4], bl[2][4];
            ldsm_x4(ah, aBase + koff);
            ldsm_x4(al, aBase + LO + koff);
            ldsm_x4(bh[0], bBase0 + koff);
            ldsm_x4(bl[0], bBase0 + LO + koff);
            ldsm_x4(bh[1], bBase1 + koff);
            ldsm_x4(bl[1], bBase1 + LO + koff);
            #pragma unroll
            for (int p = 0; p < 2; p++)
                #pragma unroll
                for (int half = 0; half < 2; half++) {
                    int ns = (p << 1) + half;
                    const uint32_t bfh[2] = {bh[p][half << 1], bh[p][(half << 1) + 1]};
                    const uint32_t bfl[2] = {bl[p][half << 1], bl[p][(half << 1) + 1]};
                    mma_tf32(acc[ns], ah, bfh);
                    mma_tf32(acc[ns], ah, bfl);
                    mma_tf32(acc[ns], al, bfh);
                }
        }
        __syncthreads();
    }

    float* Cp = C + (size_t)blockIdx.z * M * N;
    int r0 = bm + warpM + g;
    #pragma unroll
    for (int ns = 0; ns < 4; ns++) {
        int c0 = bn + warpN + (ns << 3) + (tig << 1);
        size_t o0 = (size_t)r0 * N + c0, o2 = (size_t)(r0 + 8) * N + c0;
        Cp[o0] = acc[ns][0]; Cp[o0 + 1] = acc[ns][1];
        Cp[o2] = acc[ns][2]; Cp[o2 + 1] = acc[ns][3];
    }
}

// =======================================================================
// Reduce split-K partials + bias (+relu)
// =======================================================================
__global__ __launch_bounds__(256)
void reduceSK(const float* __restrict__ part, int S, int plane,
              const float* __restrict__ bias, int act,
              float* __restrict__ out, int total, int N)
{
    int idx = blockIdx.x * 256 + threadIdx.x;
    if (idx >= total) return;
    float v = bias[idx % N];
    for (int s = 0; s < S; s++) v += part[(size_t)s * plane + idx];
    if (act) v = fmaxf(v, 0.f);
    out[idx] = v;
}

// =======================================================================
// GRU gates (hidden==0): reduce S split-K partials + bih + bhh; h=(1-z)n
// =======================================================================
__global__ __launch_bounds__(256)
void gru_gatesS(const float* __restrict__ gip, int S,
                const float* __restrict__ bih, const float* __restrict__ bhh,
                float* __restrict__ h)
{
    int idx = blockIdx.x * 256 + threadIdx.x;
    int b = idx >> 8, j = idx & 255;
    const float* g0 = gip + (size_t)b * G3;
    const size_t P = (size_t)BB * G3;
    float vr = bih[j], vz = bih[256 + j], vn = bih[512 + j];
    for (int s = 0; s < S; s++) {
        vr += g0[s * P + j];
        vz += g0[s * P + 256 + j];
        vn += g0[s * P + 512 + j];
    }
    float r = 1.f / (1.f + __expf(-(vr + bhh[j])));
    float z = 1.f / (1.f + __expf(-(vz + bhh[256 + j])));
    float n = tanhf(vn + r * bhh[512 + j]);
    h[idx] = (1.f - z) * n;
}

// =======================================================================
// LayerNorm over GRU dim
// =======================================================================
__global__ __launch_bounds__(256)
void ln1d_k(const float* __restrict__ h, const float* __restrict__ g,
            const float* __restrict__ b, float* __restrict__ o)
{
    __shared__ float s1[8], s2[8], mv[2];
    int row = blockIdx.x, tid = threadIdx.x;
    float v = h[(size_t)row * GRUU + tid];
    float s = v, q = v * v;
    #pragma unroll
    for (int off = 16; off; off >>= 1) {
        s += __shfl_xor_sync(0xffffffffu, s, off);
        q += __shfl_xor_sync(0xffffffffu, q, off);
    }
    if ((tid & 31) == 0) { s1[tid >> 5] = s; s2[tid >> 5] = q; }
    __syncthreads();
    if (tid == 0) {
        float S = 0.f, Q = 0.f;
        #pragma unroll
        for (int i = 0; i < 8; i++) { S += s1[i]; Q += s2[i]; }
        float m = S * (1.f / 256.f);
        float var = Q * (1.f / 256.f) - m * m;
        mv[0] = m; mv[1] = rsqrtf(var + 1e-5f);
    }
    __syncthreads();
    o[(size_t)row * GRUU + tid] = (v - mv[0]) * mv[1] * g[tid] + b[tid];
}

// =======================================================================
// host launcher
// =======================================================================
extern "C" void kernel_launch(void* const* d_in, const int* in_sizes, int n_in,
                              void* d_out, int out_size)
{
    const float* X    = (const float*)d_in[0];
    const int*   A    = (const int*)  d_in[1];
    const float* W1   = (const float*)d_in[2];
    const float* a1   = (const float*)d_in[3];
    const float* W2   = (const float*)d_in[4];
    const float* a2   = (const float*)d_in[5];
    const float* Wr   = (const float*)d_in[6];
    const float* br   = (const float*)d_in[7];
    const float* g1   = (const float*)d_in[8];
    const float* b1   = (const float*)d_in[9];
    const float* g2   = (const float*)d_in[10];
    const float* b2   = (const float*)d_in[11];
    const float* Wih0 = (const float*)d_in[12];
    const float* bih0 = (const float*)d_in[14];
    const float* bhh0 = (const float*)d_in[15];
    const float* Wih1 = (const float*)d_in[16];
    const float* bih1 = (const float*)d_in[18];
    const float* bhh1 = (const float*)d_in[19];
    const float* Wih2 = (const float*)d_in[20];
    const float* bih2 = (const float*)d_in[22];
    const float* bhh2 = (const float*)d_in[23];
    const float* gng  = (const float*)d_in[24];
    const float* gnb  = (const float*)d_in[25];
    const float* We   = (const float*)d_in[26];
    const float* be   = (const float*)d_in[27];
    const float* Wp   = (const float*)d_in[28];
    const float* bp   = (const float*)d_in[29];
    float* out = (float*)d_out;

    float *px, *pgip, *ph, *phln, *pemb;
    cudaGetSymbolAddress((void**)&px,   g_x);
    cudaGetSymbolAddress((void**)&pgip, g_gip);
    cudaGetSymbolAddress((void**)&ph,   g_h);
    cudaGetSymbolAddress((void**)&phln, g_hln);
    cudaGetSymbolAddress((void**)&pemb, g_emb);

    const int GAT_SMEM = GAT_WORDS * 4;
    cudaFuncSetAttribute(gat_kernel, cudaFuncAttributeMaxDynamicSharedMemorySize, GAT_SMEM);
    cudaFuncSetAttribute(gemm_nk, cudaFuncAttributeMaxDynamicSharedMemorySize, GEMM_SMEM);

    gat_kernel<<<BB, TG, GAT_SMEM>>>(X, A, W1, a1, W2, a2, Wr, br, g1, b1, g2, b2);

    // GRU layer 0: split-K x8 (chunk 768 -> 24 BK32 tiles, grid 1536)
    dim3 g0(G3 / 64, BB / 64, SK0);
    gemm_nk<<<g0, 256, GEMM_SMEM>>>(px, Wih0, pgip, BB, G3, XG, XG / SK0);
    gru_gatesS<<<BB, 256>>>(pgip, SK0, bih0, bhh0, ph);

    // GRU layers 1 & 2: split-K x2 (chunk 128 -> 4 tiles)
    dim3 g12(G3 / 64, BB / 64, 2);
    gemm_nk<<<g12, 256, GEMM_SMEM>>>(ph, Wih1, pgip, BB, G3, GRUU, GRUU / 2);
    gru_gatesS<<<BB, 256>>>(pgip, 2, bih1, bhh1, ph);
    gemm_nk<<<g12, 256, GEMM_SMEM>>>(ph, Wih2, pgip, BB, G3, GRUU, GRUU / 2);
    gru_gatesS<<<BB, 256>>>(pgip, 2, bih2, bhh2, ph);

    ln1d_k<<<BB, 256>>>(ph, gng, gnb, phln);

    float* embp = (out_size >= 2 * BB * EMBB) ? (out + (size_t)BB * EMBB) : pemb;

    // emb = relu(hln @ We + be): split-K x4 (K=256, chunk 64)
    dim3 gEmb(EMBB / 64, BB / 64, 4);
    gemm_t<<<gEmb, 256>>>(phln, We, pgip, BB, EMBB, GRUU, EMBB, GRUU / 4);
    reduceSK<<<(BB * EMBB + 255) / 256, 256>>>(pgip, 4, BB * EMBB, be, 1,
                                               embp, BB * EMBB, EMBB);

    // pred = emb @ Wp + bp: split-K x2 (K=128, chunk 64)
    dim3 gPred(NN / 64, BB / 64, 2);
    gemm_t<<<gPred, 256>>>(embp, Wp, pgip, BB, NN, EMBB, NN, EMBB / 2);
    reduceSK<<<(BB * NN + 255) / 256, 256>>>(pgip, 2, BB * NN, bp, 0,
                                             out, BB * NN, NN);
}

// round 14
// speedup vs baseline: 1.5095x; 1.0727x over previous
#include <cuda_runtime.h>
#include <cstdint>

// ---------------- problem constants ----------------
#define BB   1024
#define NN   128
#define FF   16
#define GG   48
#define HH   6
#define DD   8
#define GRUU 256
#define EMBB 128
#define XG   (NN*GG)       // 6144
#define G3   (3*GRUU)      // 768
#define SK0  8             // split-K for GRU0
#define TG   384           // GAT block size (12 warps)

// ---------------- scratch ----------------
__device__ float g_x  [BB*XG];
__device__ float g_gip[SK0*BB*G3];
__device__ float g_h  [BB*GRUU];
__device__ float g_hln[BB*GRUU];
__device__ float g_emb[BB*EMBB];

// ---------------- helpers ----------------
__device__ __forceinline__ void tf32split(float v, uint32_t& h, uint32_t& l) {
    uint32_t hb; asm("cvt.rna.tf32.f32 %0, %1;" : "=r"(hb) : "f"(v));
    float lv = v - __uint_as_float(hb);
    uint32_t lb; asm("cvt.rna.tf32.f32 %0, %1;" : "=r"(lb) : "f"(lv));
    h = hb; l = lb;
}

__device__ __forceinline__ uint32_t tf32rna(float v) {
    uint32_t r; asm("cvt.rna.tf32.f32 %0, %1;" : "=r"(r) : "f"(v));
    return r;
}

__device__ __forceinline__ uint32_t smem_u32(const void* p) {
    uint32_t a;
    asm("{ .reg .u64 t; cvta.to.shared.u64 t, %1; cvt.u32.u64 %0, t; }" : "=r"(a) : "l"(p));
    return a;
}

__device__ __forceinline__ void ldsm_x4(uint32_t* d, uint32_t addr) {
    asm volatile("ldmatrix.sync.aligned.m8n8.x4.shared.b16 {%0,%1,%2,%3}, [%4];"
        : "=r"(d[0]), "=r"(d[1]), "=r"(d[2]), "=r"(d[3]) : "r"(addr));
}

__device__ __forceinline__ void mma_tf32(float* c, const uint32_t* a, const uint32_t* b) {
    asm volatile("mma.sync.aligned.m16n8k8.row.col.f32.tf32.tf32.f32 "
        "{%0,%1,%2,%3}, {%4,%5,%6,%7}, {%8,%9}, {%0,%1,%2,%3};\n"
        : "+f"(c[0]), "+f"(c[1]), "+f"(c[2]), "+f"(c[3])
        : "r"(a[0]), "r"(a[1]), "r"(a[2]), "r"(a[3]), "r"(b[0]), "r"(b[1]));
}

// =======================================================================
// GAT attention via tensor cores. 12 warps -> 4 tasks/warp.
// h kept as raw fp32 (hw truncates to tf32 in the MMA); softmax stays
// exactly normalized because numerator and w@ones denominator see the
// same truncated w. Single h plane: 2 MMAs per 16x8 tile.
// =======================================================================
__device__ __forceinline__ void gat_attention_mma(
    const uint32_t* __restrict__ shv,
    const float* __restrict__ sei, const float* __restrict__ sej,
    const float* __restrict__ sPj, const float* __restrict__ sQj,
    const unsigned* __restrict__ smask, float* __restrict__ sy, int tid)
{
    int lane = tid & 31, wid = tid >> 5;
    int g = lane >> 2, tig = lane & 3;
    const uint32_t ONES[2] = {0x3F800000u, 0x3F800000u};

    #pragma unroll 1
    for (int task = wid; task < 48; task += 12) {
        int hd = task >> 3, m0 = (task & 7) << 4;
        int r0 = m0 + g, r1 = r0 + 8;
        float ei0 = sei[(hd << 7) + r0], ei1 = sei[(hd << 7) + r1];
        float Pi0 = __expf(ei0), Qi0 = __expf(0.01f * ei0);
        float Pi1 = __expf(ei1), Qi1 = __expf(0.01f * ei1);
        const unsigned* mr0 = smask + (r0 << 2);
        const unsigned* mr1 = smask + (r1 << 2);
        const float* ejp = sej + (hd << 7);
        const float* Pjp = sPj + (hd << 7);
        const float* Qjp = sQj + (hd << 7);
        const uint32_t* hv = shv + (hd << 10);

        float c[4]  = {0.f, 0.f, 0.f, 0.f};
        float cs[4] = {0.f, 0.f, 0.f, 0.f};

        #pragma unroll 1
        for (int jw = 0; jw < 4; jw++) {
            unsigned w0 = mr0[jw], w1 = mr1[jw];
            #pragma unroll
            for (int q = 0; q < 4; q++) {
                int j0 = (jw << 5) + (q << 3);
                unsigned mt0 = w0 >> ((q << 3) + tig);
                unsigned mt1 = w1 >> ((q << 3) + tig);
                int jA = j0 + tig, jB = jA + 4;
                float ejA = ejp[jA], ejB = ejp[jB];
                float PjA = Pjp[jA], PjB = Pjp[jB];
                float QjA = Qjp[jA], QjB = Qjp[jB];

                float wa0 = (ei0 + ejA > 0.f) ? (Pi0 * PjA) : (Qi0 * QjA);
                float wa1 = (ei1 + ejA > 0.f) ? (Pi1 * PjA) : (Qi1 * QjA);
                float wa2 = (ei0 + ejB > 0.f) ? (Pi0 * PjB) : (Qi0 * QjB);
                float wa3 = (ei1 + ejB > 0.f) ? (Pi1 * PjB) : (Qi1 * QjB);
                wa0 = (mt0 & 1u)  ? wa0 : 0.f;
                wa1 = (mt1 & 1u)  ? wa1 : 0.f;
                wa2 = (mt0 & 16u) ? wa2 : 0.f;
                wa3 = (mt1 & 16u) ? wa3 : 0.f;

                uint32_t a[4];
                a[0] = __float_as_uint(wa0); a[1] = __float_as_uint(wa1);
                a[2] = __float_as_uint(wa2); a[3] = __float_as_uint(wa3);

                uint32_t bh[2] = { hv[(jA << 3) + g], hv[(jB << 3) + g] };
                mma_tf32(c, a, bh);
                mma_tf32(cs, a, ONES);   // row sums of truncated w
            }
        }
        float inv0 = 1.0f / cs[0], inv1 = 1.0f / cs[2];

        float* o0 = sy + r0 * 49 + (hd << 3) + (tig << 1);
        float* o1 = sy + r1 * 49 + (hd << 3) + (tig << 1);
        o0[0] = c[0] * inv0; o0[1] = c[1] * inv0;
        o1[0] = c[2] * inv1; o1[1] = c[3] * inv1;
    }
}

// LayerNorm over all [N,G] of one batch, + ReLU. sy row stride 49. 12 warps.
__device__ __forceinline__ void ln2d_apply(
    float* __restrict__ sy, const float* __restrict__ gamma,
    const float* __restrict__ beta, float* __restrict__ sred,
    int tid, float* __restrict__ gout)
{
    float s = 0.f, q = 0.f;
    for (int t = tid; t < XG; t += TG) {
        int n = t / 48, c = t - n * 48;
        float v = sy[n * 49 + c];
        s += v; q += v * v;
    }
    #pragma unroll
    for (int o = 16; o; o >>= 1) {
        s += __shfl_xor_sync(0xffffffffu, s, o);
        q += __shfl_xor_sync(0xffffffffu, q, o);
    }
    int wid = tid >> 5;
    if ((tid & 31) == 0) { sred[wid] = s; sred[12 + wid] = q; }
    __syncthreads();
    if (tid == 0) {
        float S = 0.f, Q = 0.f;
        #pragma unroll
        for (int i = 0; i < 12; i++) { S += sred[i]; Q += sred[12 + i]; }
        float m   = S * (1.f / (float)XG);
        float var = Q * (1.f / (float)XG) - m * m;
        sred[24] = m;
        sred[25] = rsqrtf(var + 1e-5f);
    }
    __syncthreads();
    float m = sred[24], rs = sred[25];
    for (int t = tid; t < XG; t += TG) {
        int n = t / 48, c = t - n * 48;
        float v = (sy[n * 49 + c] - m) * rs * gamma[t] + beta[t];
        v = fmaxf(v, 0.f);
        if (gout) gout[t] = v; else sy[n * 49 + c] = v;
    }
}

// GAT smem layout (words). sX (2176, stride 17) is OVERLAID on the sy
// region: it is only live before the first attention call overwrites sy.
// Residual re-reads X from global.
#define S_H    0
#define S_Y    (S_H + 6144)
#define S_EI   (S_Y + 6272)
#define S_EJ   (S_EI + 768)
#define S_PJ   (S_EJ + 768)
#define S_QJ   (S_PJ + 768)
#define S_W    (S_QJ + 768)
#define S_A    (S_W + 2304)
#define S_RED  (S_A + 96)
#define S_MASK (S_RED + 32)
#define GAT_WORDS (S_MASK + 512)   // 18432 words = 73728 B -> 3 CTA/SM

__global__ __launch_bounds__(TG, 3)
void gat_kernel(const float* __restrict__ X,  const int* __restrict__ A,
                const float* __restrict__ W1, const float* __restrict__ a1,
                const float* __restrict__ W2, const float* __restrict__ a2,
                const float* __restrict__ Wr, const float* __restrict__ br,
                const float* __restrict__ g1, const float* __restrict__ b1,
                const float* __restrict__ g2, const float* __restrict__ b2)
{
    extern __shared__ float sm[];
    float*    sh    = sm + S_H;               // h as fp32 [6][128][8]
    uint32_t* shv   = (uint32_t*)(sm + S_H);  // bit view for MMA fragments
    float*    sy    = sm + S_Y;               // stride-49 tile; sX overlay
    float*    sX    = sm + S_Y;               // stride-17, live pre-attention
    float*    sei   = sm + S_EI;
    float*    sej   = sm + S_EJ;
    float*    sPj   = sm + S_PJ;
    float*    sQj   = sm + S_QJ;
    float*    sW    = sm + S_W;
    float*    sa    = sm + S_A;
    float*    sred  = sm + S_RED;
    unsigned* smask = (unsigned*)(sm + S_MASK);

    int b = blockIdx.x, tid = threadIdx.x;
    const float* Xb = X + (size_t)b * (NN * FF);

    for (int t = tid; t < NN * FF; t += TG)
        sX[(t >> 4) * 17 + (t & 15)] = Xb[t];

    {
        const int* Ab = A + (size_t)b * (NN * NN);
        int lane = tid & 31, wid = tid >> 5;
        for (int w = wid; w < 512; w += 12) {
            int i = w >> 2, j0 = (w & 3) << 5;
            unsigned bits = __ballot_sync(0xffffffffu, Ab[(i << 7) + j0 + lane] != 0);
            if (lane == 0) smask[w] = bits;
        }
    }
    for (int t = tid; t < HH * FF * DD; t += TG) sW[t] = W1[t];
    if (tid < HH * 2 * DD) sa[tid] = a1[tid];
    __syncthreads();

    // ---- layer 1: h = X@W1 (fp32), scores, per-node exps ----
    for (int t = tid; t < HH * NN; t += TG) {
        int hd = t >> 7, n = t & 127;
        float acc[8];
        #pragma unroll
        for (int d = 0; d < 8; d++) acc[d] = 0.f;
        const float* w = sW + hd * (FF * DD);
        const float* x = sX + n * 17;
        #pragma unroll
        for (int f = 0; f < FF; f++) {
            float xv = x[f];
            #pragma unroll
            for (int d = 0; d < 8; d++) acc[d] = fmaf(xv, w[(f << 3) + d], acc[d]);
        }
        const float* av = sa + (hd << 4);
        float ei = 0.f, ej = 0.f;
        #pragma unroll
        for (int d = 0; d < 8; d++) { ei = fmaf(acc[d], av[d], ei); ej = fmaf(acc[d], av[8 + d], ej); }
        #pragma unroll
        for (int d = 0; d < 8; d++) sh[(t << 3) + d] = acc[d];
        sei[t] = ei; sej[t] = ej;
        sPj[t] = __expf(ej); sQj[t] = __expf(0.01f * ej);
    }
    __syncthreads();
    gat_attention_mma(shv, sei, sej, sPj, sQj, smask, sy, tid);  // overwrites sX
    __syncthreads();
    ln2d_apply(sy, g1, b1, sred, tid, nullptr);
    __syncthreads();

    // ---- layer 2 weights ----
    for (int t = tid; t < HH * GG * DD; t += TG) sW[t] = W2[t];
    if (tid < HH * 2 * DD) sa[tid] = a2[tid];
    __syncthreads();

    // ---- layer 2: h2 = y@W2 ----
    for (int t = tid; t < HH * NN; t += TG) {
        int hd = t >> 7, n = t & 127;
        float acc[8];
        #pragma unroll
        for (int d = 0; d < 8; d++) acc[d] = 0.f;
        const float* w = sW + hd * (GG * DD);
        const float* x = sy + n * 49;
        #pragma unroll
        for (int f = 0; f < GG; f++) {
            float xv = x[f];
            #pragma unroll
            for (int d = 0; d < 8; d++) acc[d] = fmaf(xv, w[(f << 3) + d], acc[d]);
        }
        const float* av = sa + (hd << 4);
        float ei = 0.f, ej = 0.f;
        #pragma unroll
        for (int d = 0; d < 8; d++) { ei = fmaf(acc[d], av[d], ei); ej = fmaf(acc[d], av[8 + d], ej); }
        #pragma unroll
        for (int d = 0; d < 8; d++) sh[(t << 3) + d] = acc[d];
        sei[t] = ei; sej[t] = ej;
        sPj[t] = __expf(ej); sQj[t] = __expf(0.01f * ej);
    }
    __syncthreads();
    gat_attention_mma(shv, sei, sej, sPj, sQj, smask, sy, tid);
    __syncthreads();

    // ---- residual: sy += X@Wr + br (X re-read from global) ----
    for (int t = tid; t < FF * GG; t += TG) sW[t] = Wr[t];
    if (tid < GG) sa[tid] = br[tid];
    __syncthreads();
    for (int t = tid; t < XG; t += TG) {
        int n = t / 48, c = t - n * 48;
        float accv = sa[c];
        const float* x = Xb + n * FF;
        #pragma unroll
        for (int f = 0; f < FF; f++) accv = fmaf(x[f], sW[f * 48 + c], accv);
        sy[n * 49 + c] += accv;
    }
    __syncthreads();
    ln2d_apply(sy, g2, b2, sred, tid, g_x + (size_t)b * XG);
}

// =======================================================================
// Double-buffered 2xTF32 GEMM, BK=32. A split hi/lo; B hi-only.
// B row-major [N,K]. Split-K via grid.z -> partial C at z*M*N.
// =======================================================================
#define PLANE_W     (64*36)
#define LO_BYTES    (PLANE_W*4)
#define A_BUF_W     (2*PLANE_W)
#define A_BUF_BYTES (A_BUF_W*4)
#define B_BUF_BYTES (PLANE_W*4)
#define GEMM_SMEM   (6*PLANE_W*4)   // 55296

__global__ __launch_bounds__(256)
void gemm_nk(const float* __restrict__ Af, const float* __restrict__ Bf,
             float* __restrict__ C, int M, int N, int K, int kChunk)
{
    extern __shared__ uint32_t smem[];
    uint32_t* sA = smem;
    uint32_t* sB = smem + 2 * A_BUF_W;

    int tid  = threadIdx.x;
    int lane = tid & 31, wid = tid >> 5;
    int warpM = (wid >> 1) << 4;
    int warpN = (wid & 1) << 5;
    int g = lane >> 2, tig = lane & 3;
    int bm = blockIdx.y << 6, bn = blockIdx.x << 6;
    int kBeg = blockIdx.z * kChunk;
    int nt   = kChunk >> 5;

    uint32_t aOff = (((warpM + (lane & 15)) * 36 + ((lane >> 4) << 2)) << 2);
    uint32_t bOff = (((warpN + ((lane >> 4) << 3) + (lane & 7)) * 36 + (((lane >> 3) & 1) << 2)) << 2);
    uint32_t aBaseS = smem_u32(sA);
    uint32_t bBaseS = smem_u32(sB);

    int frow = tid >> 3;
    int fkc  = (tid & 7) << 2;

    float acc[4][4];
    #pragma unroll
    for (int ns = 0; ns < 4; ns++)
        #pragma unroll
        for (int r = 0; r < 4; r++) acc[ns][r] = 0.f;

    float4 pA[2], pB[2];

    auto FETCH = [&](int kt) {
        #pragma unroll
        for (int q = 0; q < 2; q++) {
            int row = frow + (q << 5);
            pA[q] = *(const float4*)(Af + (size_t)(bm + row) * K + kBeg + kt + fkc);
            pB[q] = *(const float4*)(Bf + (size_t)(bn + row) * K + kBeg + kt + fkc);
        }
    };
    auto STORE = [&](int buf) {
        uint32_t* dA = sA + buf * A_BUF_W;
        uint32_t* dB = sB + buf * PLANE_W;
        #pragma unroll
        for (int q = 0; q < 2; q++) {
            int row = frow + (q << 5);
            uint4 hi, lo;
            tf32split(pA[q].x, hi.x, lo.x); tf32split(pA[q].y, hi.y, lo.y);
            tf32split(pA[q].z, hi.z, lo.z); tf32split(pA[q].w, hi.w, lo.w);
            *(uint4*)(dA + row * 36 + fkc)           = hi;
            *(uint4*)(dA + PLANE_W + row * 36 + fkc) = lo;
            uint4 bh;
            bh.x = tf32rna(pB[q].x); bh.y = tf32rna(pB[q].y);
            bh.z = tf32rna(pB[q].z); bh.w = tf32rna(pB[q].w);
            *(uint4*)(dB + row * 36 + fkc) = bh;
        }
    };

    FETCH(0);
    STORE(0);
    __syncthreads();

    for (int t = 0; t < nt; t++) {
        int cur = t & 1;
        bool more = (t + 1 < nt);
        if (more) FETCH((t + 1) << 5);

        uint32_t aB  = aBaseS + cur * A_BUF_BYTES + aOff;
        uint32_t bB0 = bBaseS + cur * B_BUF_BYTES + bOff;
        uint32_t bB1 = bB0 + ((16 * 36) << 2);
        #pragma unroll
        for (int ks = 0; ks < 4; ks++) {
            uint32_t koff = (ks << 3) << 2;
            uint32_t ah[4], al[4], bh[2][4];
            ldsm_x4(ah, aB + koff);
            ldsm_x4(al, aB + LO_BYTES + koff);
            ldsm_x4(bh[0], bB0 + koff);
            ldsm_x4(bh[1], bB1 + koff);
            #pragma unroll
            for (int p = 0; p < 2; p++)
                #pragma unroll
                for (int half = 0; half < 2; half++) {
                    int ns = (p << 1) + half;
                    const uint32_t bfh[2] = {bh[p][half << 1], bh[p][(half << 1) + 1]};
                    mma_tf32(acc[ns], ah, bfh);
                    mma_tf32(acc[ns], al, bfh);
                }
        }
        if (more) STORE(cur ^ 1);
        __syncthreads();
    }

    float* Cp = C + (size_t)blockIdx.z * M * N;
    int r0 = bm + warpM + g;
    #pragma unroll
    for (int ns = 0; ns < 4; ns++) {
        int c0 = bn + warpN + (ns << 3) + (tig << 1);
        size_t o0 = (size_t)r0 * N + c0, o2 = (size_t)(r0 + 8) * N + c0;
        Cp[o0] = acc[ns][0]; Cp[o0 + 1] = acc[ns][1];
        Cp[o2] = acc[ns][2]; Cp[o2 + 1] = acc[ns][3];
    }
}

// =======================================================================
// 3xTF32 GEMM for transposed-B (B row-major [K,N]); full accuracy for the
// output-path head GEMMs; split-K; partial out.
// =======================================================================
__global__ __launch_bounds__(256)
void gemm_t(const float* __restrict__ Af, const float* __restrict__ Bf,
            float* __restrict__ C, int M, int N, int K, int ldb, int kChunk)
{
    __shared__ uint32_t sA[2][64][36];
    __shared__ uint32_t sB[2][64][36];

    int tid  = threadIdx.x;
    int lane = tid & 31, wid = tid >> 5;
    int warpM = (wid >> 1) << 4;
    int warpN = (wid & 1) << 5;
    int g = lane >> 2, tig = lane & 3;
    int bm = blockIdx.y << 6, bn = blockIdx.x << 6;
    int kBeg = blockIdx.z * kChunk;

    uint32_t aBase = smem_u32(&sA[0][0][0]) +
        (((warpM + (lane & 15)) * 36 + ((lane >> 4) << 2)) << 2);
    uint32_t bBase0 = smem_u32(&sB[0][0][0]) +
        (((warpN + ((lane >> 4) << 3) + (lane & 7)) * 36 + (((lane >> 3) & 1) << 2)) << 2);
    uint32_t bBase1 = bBase0 + (16 * 36 << 2);
    const uint32_t LO = (64 * 36) << 2;

    float acc[4][4];
    #pragma unroll
    for (int ns = 0; ns < 4; ns++)
        #pragma unroll
        for (int r = 0; r < 4; r++) acc[ns][r] = 0.f;

    float4 pA[2], pB[2];
    #pragma unroll
    for (int q = 0; q < 2; q++) {
        int idx = tid + (q << 8);
        int row = idx >> 3, kc = (idx & 7) << 2;
        pA[q] = *(const float4*)(Af + (size_t)(bm + row) * K + kBeg + kc);
        int k = idx >> 4, n0 = (idx & 15) << 2;
        pB[q] = *(const float4*)(Bf + (size_t)(kBeg + k) * ldb + bn + n0);
    }

    for (int kt = 0; kt < kChunk; kt += 32) {
        #pragma unroll
        for (int q = 0; q < 2; q++) {
            int idx = tid + (q << 8);
            {
                int row = idx >> 3, kc = (idx & 7) << 2;
                uint4 hi, lo;
                tf32split(pA[q].x, hi.x, lo.x); tf32split(pA[q].y, hi.y, lo.y);
                tf32split(pA[q].z, hi.z, lo.z); tf32split(pA[q].w, hi.w, lo.w);
                *(uint4*)&sA[0][row][kc] = hi;
                *(uint4*)&sA[1][row][kc] = lo;
            }
            {
                int k = idx >> 4, n0 = (idx & 15) << 2;
                float v[4] = {pB[q].x, pB[q].y, pB[q].z, pB[q].w};
                #pragma unroll
                for (int j = 0; j < 4; j++) {
                    uint32_t hb, lb; tf32split(v[j], hb, lb);
                    sB[0][n0 + j][k] = hb; sB[1][n0 + j][k] = lb;
                }
            }
        }
        __syncthreads();

        int ktn = kt + 32;
        if (ktn < kChunk) {
            #pragma unroll
            for (int q = 0; q < 2; q++) {
                int idx = tid + (q << 8);
                int row = idx >> 3, kc = (idx & 7) << 2;
                pA[q] = *(const float4*)(Af + (size_t)(bm + row) * K + kBeg + ktn + kc);
                int k = idx >> 4, n0 = (idx & 15) << 2;
                pB[q] = *(const float4*)(Bf + (size_t)(kBeg + ktn + k) * ldb + bn + n0);
            }
        }

        #pragma unroll
        for (int ks = 0; ks < 4; ks++) {
            uint32_t koff = (ks << 3) << 2;
            uint32_t ah[4], al[4], bh[2][4], bl[2][4];
            ldsm_x4(ah, aBase + koff);
            ldsm_x4(al, aBase + LO + koff);
            ldsm_x4(bh[0], bBase0 + koff);
            ldsm_x4(bl[0], bBase0 + LO + koff);
            ldsm_x4(bh[1], bBase1 + koff);
            ldsm_x4(bl[1], bBase1 + LO + koff);
            #pragma unroll
            for (int p = 0; p < 2; p++)
                #pragma unroll
                for (int half = 0; half < 2; half++) {
                    int ns = (p << 1) + half;
                    const uint32_t bfh[2] = {bh[p][half << 1], bh[p][(half << 1) + 1]};
                    const uint32_t bfl[2] = {bl[p][half << 1], bl[p][(half << 1) + 1]};
                    mma_tf32(acc[ns], ah, bfh);
                    mma_tf32(acc[ns], ah, bfl);
                    mma_tf32(acc[ns], al, bfh);
                }
        }
        __syncthreads();
    }

    float* Cp = C + (size_t)blockIdx.z * M * N;
    int r0 = bm + warpM + g;
    #pragma unroll
    for (int ns = 0; ns < 4; ns++) {
        int c0 = bn + warpN + (ns << 3) + (tig << 1);
        size_t o0 = (size_t)r0 * N + c0, o2 = (size_t)(r0 + 8) * N + c0;
        Cp[o0] = acc[ns][0]; Cp[o0 + 1] = acc[ns][1];
        Cp[o2] = acc[ns][2]; Cp[o2 + 1] = acc[ns][3];
    }
}

// =======================================================================
// Reduce split-K partials + bias (+relu)
// =======================================================================
__global__ __launch_bounds__(256)
void reduceSK(const float* __restrict__ part, int S, int plane,
              const float* __restrict__ bias, int act,
              float* __restrict__ out, int total, int N)
{
    int idx = blockIdx.x * 256 + threadIdx.x;
    if (idx >= total) return;
    float v = bias[idx % N];
    for (int s = 0; s < S; s++) v += part[(size_t)s * plane + idx];
    if (act) v = fmaxf(v, 0.f);
    out[idx] = v;
}

// =======================================================================
// GRU gates (hidden==0): reduce S split-K partials + bih + bhh; h=(1-z)n
// =======================================================================
__global__ __launch_bounds__(256)
void gru_gatesS(const float* __restrict__ gip, int S,
                const float* __restrict__ bih, const float* __restrict__ bhh,
                float* __restrict__ h)
{
    int idx = blockIdx.x * 256 + threadIdx.x;
    int b = idx >> 8, j = idx & 255;
    const float* g0 = gip + (size_t)b * G3;
    const size_t P = (size_t)BB * G3;
    float vr = bih[j], vz = bih[256 + j], vn = bih[512 + j];
    for (int s = 0; s < S; s++) {
        vr += g0[s * P + j];
        vz += g0[s * P + 256 + j];
        vn += g0[s * P + 512 + j];
    }
    float r = 1.f / (1.f + __expf(-(vr + bhh[j])));
    float z = 1.f / (1.f + __expf(-(vz + bhh[256 + j])));
    float n = tanhf(vn + r * bhh[512 + j]);
    h[idx] = (1.f - z) * n;
}

// =======================================================================
// LayerNorm over GRU dim
// =======================================================================
__global__ __launch_bounds__(256)
void ln1d_k(const float* __restrict__ h, const float* __restrict__ g,
            const float* __restrict__ b, float* __restrict__ o)
{
    __shared__ float s1[8], s2[8], mv[2];
    int row = blockIdx.x, tid = threadIdx.x;
    float v = h[(size_t)row * GRUU + tid];
    float s = v, q = v * v;
    #pragma unroll
    for (int off = 16; off; off >>= 1) {
        s += __shfl_xor_sync(0xffffffffu, s, off);
        q += __shfl_xor_sync(0xffffffffu, q, off);
    }
    if ((tid & 31) == 0) { s1[tid >> 5] = s; s2[tid >> 5] = q; }
    __syncthreads();
    if (tid == 0) {
        float S = 0.f, Q = 0.f;
        #pragma unroll
        for (int i = 0; i < 8; i++) { S += s1[i]; Q += s2[i]; }
        float m = S * (1.f / 256.f);
        float var = Q * (1.f / 256.f) - m * m;
        mv[0] = m; mv[1] = rsqrtf(var + 1e-5f);
    }
    __syncthreads();
    o[(size_t)row * GRUU + tid] = (v - mv[0]) * mv[1] * g[tid] + b[tid];
}

// =======================================================================
// host launcher
// =======================================================================
extern "C" void kernel_launch(void* const* d_in, const int* in_sizes, int n_in,
                              void* d_out, int out_size)
{
    const float* X    = (const float*)d_in[0];
    const int*   A    = (const int*)  d_in[1];
    const float* W1   = (const float*)d_in[2];
    const float* a1   = (const float*)d_in[3];
    const float* W2   = (const float*)d_in[4];
    const float* a2   = (const float*)d_in[5];
    const float* Wr   = (const float*)d_in[6];
    const float* br   = (const float*)d_in[7];
    const float* g1   = (const float*)d_in[8];
    const float* b1   = (const float*)d_in[9];
    const float* g2   = (const float*)d_in[10];
    const float* b2   = (const float*)d_in[11];
    const float* Wih0 = (const float*)d_in[12];
    const float* bih0 = (const float*)d_in[14];
    const float* bhh0 = (const float*)d_in[15];
    const float* Wih1 = (const float*)d_in[16];
    const float* bih1 = (const float*)d_in[18];
    const float* bhh1 = (const float*)d_in[19];
    const float* Wih2 = (const float*)d_in[20];
    const float* bih2 = (const float*)d_in[22];
    const float* bhh2 = (const float*)d_in[23];
    const float* gng  = (const float*)d_in[24];
    const float* gnb  = (const float*)d_in[25];
    const float* We   = (const float*)d_in[26];
    const float* be   = (const float*)d_in[27];
    const float* Wp   = (const float*)d_in[28];
    const float* bp   = (const float*)d_in[29];
    float* out = (float*)d_out;

    float *px, *pgip, *ph, *phln, *pemb;
    cudaGetSymbolAddress((void**)&px,   g_x);
    cudaGetSymbolAddress((void**)&pgip, g_gip);
    cudaGetSymbolAddress((void**)&ph,   g_h);
    cudaGetSymbolAddress((void**)&phln, g_hln);
    cudaGetSymbolAddress((void**)&pemb, g_emb);

    const int GAT_SMEM = GAT_WORDS * 4;   // 73728
    cudaFuncSetAttribute(gat_kernel, cudaFuncAttributeMaxDynamicSharedMemorySize, GAT_SMEM);
    cudaFuncSetAttribute(gemm_nk, cudaFuncAttributeMaxDynamicSharedMemorySize, GEMM_SMEM);

    gat_kernel<<<BB, TG, GAT_SMEM>>>(X, A, W1, a1, W2, a2, Wr, br, g1, b1, g2, b2);

    // GRU layer 0: split-K x8 (chunk 768 -> 24 BK32 tiles, grid 1536)
    dim3 g0(G3 / 64, BB / 64, SK0);
    gemm_nk<<<g0, 256, GEMM_SMEM>>>(px, Wih0, pgip, BB, G3, XG, XG / SK0);
    gru_gatesS<<<BB, 256>>>(pgip, SK0, bih0, bhh0, ph);

    // GRU layers 1 & 2: split-K x2 (chunk 128 -> 4 tiles)
    dim3 g12(G3 / 64, BB / 64, 2);
    gemm_nk<<<g12, 256, GEMM_SMEM>>>(ph, Wih1, pgip, BB, G3, GRUU, GRUU / 2);
    gru_gatesS<<<BB, 256>>>(pgip, 2, bih1, bhh1, ph);
    gemm_nk<<<g12, 256, GEMM_SMEM>>>(ph, Wih2, pgip, BB, G3, GRUU, GRUU / 2);
    gru_gatesS<<<BB, 256>>>(pgip, 2, bih2, bhh2, ph);

    ln1d_k<<<BB, 256>>>(ph, gng, gnb, phln);

    float* embp = (out_size >= 2 * BB * EMBB) ? (out + (size_t)BB * EMBB) : pemb;

    // emb = relu(hln @ We + be): split-K x4 (K=256, chunk 64)
    dim3 gEmb(EMBB / 64, BB / 64, 4);
    gemm_t<<<gEmb, 256>>>(phln, We, pgip, BB, EMBB, GRUU, EMBB, GRUU / 4);
    reduceSK<<<(BB * EMBB + 255) / 256, 256>>>(pgip, 4, BB * EMBB, be, 1,
                                               embp, BB * EMBB, EMBB);

    // pred = emb @ Wp + bp: split-K x2 (K=128, chunk 64)
    dim3 gPred(NN / 64, BB / 64, 2);
    gemm_t<<<gPred, 256>>>(embp, Wp, pgip, BB, NN, EMBB, NN, EMBB / 2);
    reduceSK<<<(BB * NN + 255) / 256, 256>>>(pgip, 2, BB * NN, bp, 0,
                                             out, BB * NN, NN);
}

// round 15
// speedup vs baseline: 1.5252x; 1.0104x over previous
#include <cuda_runtime.h>
#include <cstdint>

// ---------------- problem constants ----------------
#define BB   1024
#define NN   128
#define FF   16
#define GG   48
#define HH   6
#define DD   8
#define GRUU 256
#define EMBB 128
#define XG   (NN*GG)       // 6144
#define G3   (3*GRUU)      // 768
#define SK0  8             // split-K for GRU0
#define TG   384           // GAT block size (12 warps)

// ---------------- scratch ----------------
__device__ float g_x  [BB*XG];
__device__ float g_gip[SK0*BB*G3];
__device__ float g_h  [BB*GRUU];
__device__ float g_hln[BB*GRUU];
__device__ float g_emb[BB*EMBB];

// ---------------- helpers ----------------
__device__ __forceinline__ void tf32split(float v, uint32_t& h, uint32_t& l) {
    uint32_t hb; asm("cvt.rna.tf32.f32 %0, %1;" : "=r"(hb) : "f"(v));
    float lv = v - __uint_as_float(hb);
    uint32_t lb; asm("cvt.rna.tf32.f32 %0, %1;" : "=r"(lb) : "f"(lv));
    h = hb; l = lb;
}

__device__ __forceinline__ uint32_t tf32rna(float v) {
    uint32_t r; asm("cvt.rna.tf32.f32 %0, %1;" : "=r"(r) : "f"(v));
    return r;
}

__device__ __forceinline__ uint32_t smem_u32(const void* p) {
    uint32_t a;
    asm("{ .reg .u64 t; cvta.to.shared.u64 t, %1; cvt.u32.u64 %0, t; }" : "=r"(a) : "l"(p));
    return a;
}

__device__ __forceinline__ void ldsm_x4(uint32_t* d, uint32_t addr) {
    asm volatile("ldmatrix.sync.aligned.m8n8.x4.shared.b16 {%0,%1,%2,%3}, [%4];"
        : "=r"(d[0]), "=r"(d[1]), "=r"(d[2]), "=r"(d[3]) : "r"(addr));
}

__device__ __forceinline__ void mma_tf32(float* c, const uint32_t* a, const uint32_t* b) {
    asm volatile("mma.sync.aligned.m16n8k8.row.col.f32.tf32.tf32.f32 "
        "{%0,%1,%2,%3}, {%4,%5,%6,%7}, {%8,%9}, {%0,%1,%2,%3};\n"
        : "+f"(c[0]), "+f"(c[1]), "+f"(c[2]), "+f"(c[3])
        : "r"(a[0]), "r"(a[1]), "r"(a[2]), "r"(a[3]), "r"(b[0]), "r"(b[1]));
}

// =======================================================================
// GAT attention via tensor cores. 12 warps -> 4 tasks/warp.
// Mask layout: smask[i*4 + k], k = j%4, bit l = j/4. Each thread (tig)
// needs only word k=tig per task row -> 1 LDS per row for all 128 j's.
// (P,Q) packed as float2. h raw fp32 (hw tf32-truncates in MMA); w@ones
// MMA gives exactly-normalized row sums.
// =======================================================================
__device__ __forceinline__ void gat_attention_mma(
    const uint32_t* __restrict__ shv,
    const float* __restrict__ sei, const float* __restrict__ sej,
    const float2* __restrict__ sPQ,
    const unsigned* __restrict__ smask, float* __restrict__ sy, int tid)
{
    int lane = tid & 31, wid = tid >> 5;
    int g = lane >> 2, tig = lane & 3;
    const uint32_t ONES[2] = {0x3F800000u, 0x3F800000u};

    #pragma unroll 1
    for (int task = wid; task < 48; task += 12) {
        int hd = task >> 3, m0 = (task & 7) << 4;
        int r0 = m0 + g, r1 = r0 + 8;
        float ei0 = sei[(hd << 7) + r0], ei1 = sei[(hd << 7) + r1];
        float Pi0 = __expf(ei0), Qi0 = __expf(0.01f * ei0);
        float Pi1 = __expf(ei1), Qi1 = __expf(0.01f * ei1);
        unsigned w0m = smask[(r0 << 2) + tig];
        unsigned w1m = smask[(r1 << 2) + tig];
        const float*  ejp = sej + (hd << 7);
        const float2* pqp = sPQ + (hd << 7);
        const uint32_t* hv = shv + (hd << 10);

        float c[4]  = {0.f, 0.f, 0.f, 0.f};
        float cs[4] = {0.f, 0.f, 0.f, 0.f};

        #pragma unroll 1
        for (int jw = 0; jw < 4; jw++) {
            #pragma unroll
            for (int q = 0; q < 4; q++) {
                int j0 = (jw << 5) + (q << 3);
                int sh2 = (jw << 3) + (q << 1);
                unsigned mt0 = w0m >> sh2;
                unsigned mt1 = w1m >> sh2;
                int jA = j0 + tig, jB = jA + 4;
                float ejA = ejp[jA], ejB = ejp[jB];
                float2 pqA = pqp[jA], pqB = pqp[jB];

                float wa0 = (ei0 + ejA > 0.f) ? (Pi0 * pqA.x) : (Qi0 * pqA.y);
                float wa1 = (ei1 + ejA > 0.f) ? (Pi1 * pqA.x) : (Qi1 * pqA.y);
                float wa2 = (ei0 + ejB > 0.f) ? (Pi0 * pqB.x) : (Qi0 * pqB.y);
                float wa3 = (ei1 + ejB > 0.f) ? (Pi1 * pqB.x) : (Qi1 * pqB.y);
                wa0 = (mt0 & 1u) ? wa0 : 0.f;
                wa1 = (mt1 & 1u) ? wa1 : 0.f;
                wa2 = (mt0 & 2u) ? wa2 : 0.f;
                wa3 = (mt1 & 2u) ? wa3 : 0.f;

                uint32_t a[4];
                a[0] = __float_as_uint(wa0); a[1] = __float_as_uint(wa1);
                a[2] = __float_as_uint(wa2); a[3] = __float_as_uint(wa3);

                uint32_t bh[2] = { hv[(jA << 3) + g], hv[(jB << 3) + g] };
                mma_tf32(c, a, bh);
                mma_tf32(cs, a, ONES);
            }
        }
        float inv0 = 1.0f / cs[0], inv1 = 1.0f / cs[2];

        float* o0 = sy + r0 * 49 + (hd << 3) + (tig << 1);
        float* o1 = sy + r1 * 49 + (hd << 3) + (tig << 1);
        o0[0] = c[0] * inv0; o0[1] = c[1] * inv0;
        o1[0] = c[2] * inv1; o1[1] = c[3] * inv1;
    }
}

// LayerNorm over [N,G] + ReLU; row/col loops (no divisions). 12 warps.
__device__ __forceinline__ void ln2d_apply(
    float* __restrict__ sy, const float* __restrict__ gamma,
    const float* __restrict__ beta, float* __restrict__ sred,
    int tid, float* __restrict__ gout)
{
    int lane = tid & 31, wid = tid >> 5;
    float s = 0.f, q = 0.f;
    for (int n = wid; n < NN; n += 12) {
        const float* row = sy + n * 49;
        for (int c = lane; c < GG; c += 32) {
            float v = row[c];
            s += v; q += v * v;
        }
    }
    #pragma unroll
    for (int o = 16; o; o >>= 1) {
        s += __shfl_xor_sync(0xffffffffu, s, o);
        q += __shfl_xor_sync(0xffffffffu, q, o);
    }
    if (lane == 0) { sred[wid] = s; sred[12 + wid] = q; }
    __syncthreads();
    if (tid == 0) {
        float S = 0.f, Q = 0.f;
        #pragma unroll
        for (int i = 0; i < 12; i++) { S += sred[i]; Q += sred[12 + i]; }
        float m   = S * (1.f / (float)XG);
        float var = Q * (1.f / (float)XG) - m * m;
        sred[24] = m;
        sred[25] = rsqrtf(var + 1e-5f);
    }
    __syncthreads();
    float m = sred[24], rs = sred[25];
    for (int n = wid; n < NN; n += 12) {
        float* row = sy + n * 49;
        for (int c = lane; c < GG; c += 32) {
            float v = (row[c] - m) * rs * gamma[n * 48 + c] + beta[n * 48 + c];
            v = fmaxf(v, 0.f);
            if (gout) gout[n * 48 + c] = v; else row[c] = v;
        }
    }
}

// GAT smem layout (words). sX overlaid on sy (dead after first attention).
#define S_H    0
#define S_Y    (S_H + 6144)
#define S_EI   (S_Y + 6272)
#define S_EJ   (S_EI + 768)
#define S_PQ   (S_EJ + 768)
#define S_W    (S_PQ + 1536)
#define S_A    (S_W + 2304)
#define S_RED  (S_A + 96)
#define S_MASK (S_RED + 32)
#define GAT_WORDS (S_MASK + 512)   // 18432 words = 73728 B -> 3 CTA/SM

__global__ __launch_bounds__(TG, 3)
void gat_kernel(const float* __restrict__ X,  const int* __restrict__ A,
                const float* __restrict__ W1, const float* __restrict__ a1,
                const float* __restrict__ W2, const float* __restrict__ a2,
                const float* __restrict__ Wr, const float* __restrict__ br,
                const float* __restrict__ g1, const float* __restrict__ b1,
                const float* __restrict__ g2, const float* __restrict__ b2)
{
    extern __shared__ float sm[];
    float*    sh    = sm + S_H;
    uint32_t* shv   = (uint32_t*)(sm + S_H);
    float*    sy    = sm + S_Y;
    float*    sX    = sm + S_Y;               // overlay, stride 17
    float*    sei   = sm + S_EI;
    float*    sej   = sm + S_EJ;
    float2*   sPQ   = (float2*)(sm + S_PQ);   // (P,Q) interleaved
    float*    sW    = sm + S_W;
    float*    sa    = sm + S_A;
    float*    sred  = sm + S_RED;
    unsigned* smask = (unsigned*)(sm + S_MASK);

    int b = blockIdx.x, tid = threadIdx.x;
    int lane = tid & 31, wid = tid >> 5;
    const float* Xb = X + (size_t)b * (NN * FF);

    for (int t = tid; t < NN * FF; t += TG)
        sX[(t >> 4) * 17 + (t & 15)] = Xb[t];

    // adjacency -> transposed-nibble bitmask: word k=j%4, bit l=j/4
    {
        const int* Ab = A + (size_t)b * (NN * NN);
        for (int i = wid; i < NN; i += 12) {
            int4 v = ((const int4*)(Ab + (i << 7)))[lane];
            unsigned b0 = __ballot_sync(0xffffffffu, v.x != 0);
            unsigned b1 = __ballot_sync(0xffffffffu, v.y != 0);
            unsigned b2 = __ballot_sync(0xffffffffu, v.z != 0);
            unsigned b3 = __ballot_sync(0xffffffffu, v.w != 0);
            if (lane == 0) {
                smask[(i << 2)]     = b0;
                smask[(i << 2) + 1] = b1;
                smask[(i << 2) + 2] = b2;
                smask[(i << 2) + 3] = b3;
            }
        }
    }
    for (int t = tid; t < HH * FF * DD; t += TG) sW[t] = W1[t];
    if (tid < HH * 2 * DD) sa[tid] = a1[tid];
    __syncthreads();

    // ---- layer 1: h = X@W1, scores, per-node exps ----
    for (int t = tid; t < HH * NN; t += TG) {
        int hd = t >> 7, n = t & 127;
        float acc[8];
        #pragma unroll
        for (int d = 0; d < 8; d++) acc[d] = 0.f;
        const float* w = sW + hd * (FF * DD);
        const float* x = sX + n * 17;
        #pragma unroll
        for (int f = 0; f < FF; f++) {
            float xv = x[f];
            #pragma unroll
            for (int d = 0; d < 8; d++) acc[d] = fmaf(xv, w[(f << 3) + d], acc[d]);
        }
        const float* av = sa + (hd << 4);
        float ei = 0.f, ej = 0.f;
        #pragma unroll
        for (int d = 0; d < 8; d++) { ei = fmaf(acc[d], av[d], ei); ej = fmaf(acc[d], av[8 + d], ej); }
        #pragma unroll
        for (int d = 0; d < 8; d++) sh[(t << 3) + d] = acc[d];
        sei[t] = ei; sej[t] = ej;
        sPQ[t] = make_float2(__expf(ej), __expf(0.01f * ej));
    }
    __syncthreads();
    gat_attention_mma(shv, sei, sej, sPQ, smask, sy, tid);  // overwrites sX
    __syncthreads();
    ln2d_apply(sy, g1, b1, sred, tid, nullptr);
    __syncthreads();

    // ---- layer 2 weights ----
    for (int t = tid; t < HH * GG * DD; t += TG) sW[t] = W2[t];
    if (tid < HH * 2 * DD) sa[tid] = a2[tid];
    __syncthreads();

    // ---- layer 2: h2 = y@W2 ----
    for (int t = tid; t < HH * NN; t += TG) {
        int hd = t >> 7, n = t & 127;
        float acc[8];
        #pragma unroll
        for (int d = 0; d < 8; d++) acc[d] = 0.f;
        const float* w = sW + hd * (GG * DD);
        const float* x = sy + n * 49;
        #pragma unroll
        for (int f = 0; f < GG; f++) {
            float xv = x[f];
            #pragma unroll
            for (int d = 0; d < 8; d++) acc[d] = fmaf(xv, w[(f << 3) + d], acc[d]);
        }
        const float* av = sa + (hd << 4);
        float ei = 0.f, ej = 0.f;
        #pragma unroll
        for (int d = 0; d < 8; d++) { ei = fmaf(acc[d], av[d], ei); ej = fmaf(acc[d], av[8 + d], ej); }
        #pragma unroll
        for (int d = 0; d < 8; d++) sh[(t << 3) + d] = acc[d];
        sei[t] = ei; sej[t] = ej;
        sPQ[t] = make_float2(__expf(ej), __expf(0.01f * ej));
    }
    __syncthreads();
    gat_attention_mma(shv, sei, sej, sPQ, smask, sy, tid);
    __syncthreads();

    // ---- residual: sy += X@Wr + br (X re-read from global) ----
    for (int t = tid; t < FF * GG; t += TG) sW[t] = Wr[t];
    if (tid < GG) sa[tid] = br[tid];
    __syncthreads();
    for (int n = wid; n < NN; n += 12) {
        const float* x = Xb + n * FF;
        float* row = sy + n * 49;
        for (int c = lane; c < GG; c += 32) {
            float accv = sa[c];
            #pragma unroll
            for (int f = 0; f < FF; f++) accv = fmaf(x[f], sW[f * 48 + c], accv);
            row[c] += accv;
        }
    }
    __syncthreads();
    ln2d_apply(sy, g2, b2, sred, tid, g_x + (size_t)b * XG);
}

// =======================================================================
// Double-buffered 2xTF32 GEMM, BK=32. A split hi/lo; B hi-only.
// B row-major [N,K]. Split-K via grid.z -> partial C at z*M*N.
// =======================================================================
#define PLANE_W     (64*36)
#define LO_BYTES    (PLANE_W*4)
#define A_BUF_W     (2*PLANE_W)
#define A_BUF_BYTES (A_BUF_W*4)
#define B_BUF_BYTES (PLANE_W*4)
#define GEMM_SMEM   (6*PLANE_W*4)   // 55296

__global__ __launch_bounds__(256)
void gemm_nk(const float* __restrict__ Af, const float* __restrict__ Bf,
             float* __restrict__ C, int M, int N, int K, int kChunk)
{
    extern __shared__ uint32_t smem[];
    uint32_t* sA = smem;
    uint32_t* sB = smem + 2 * A_BUF_W;

    int tid  = threadIdx.x;
    int lane = tid & 31, wid = tid >> 5;
    int warpM = (wid >> 1) << 4;
    int warpN = (wid & 1) << 5;
    int g = lane >> 2, tig = lane & 3;
    int bm = blockIdx.y << 6, bn = blockIdx.x << 6;
    int kBeg = blockIdx.z * kChunk;
    int nt   = kChunk >> 5;

    uint32_t aOff = (((warpM + (lane & 15)) * 36 + ((lane >> 4) << 2)) << 2);
    uint32_t bOff = (((warpN + ((lane >> 4) << 3) + (lane & 7)) * 36 + (((lane >> 3) & 1) << 2)) << 2);
    uint32_t aBaseS = smem_u32(sA);
    uint32_t bBaseS = smem_u32(sB);

    int frow = tid >> 3;
    int fkc  = (tid & 7) << 2;

    float acc[4][4];
    #pragma unroll
    for (int ns = 0; ns < 4; ns++)
        #pragma unroll
        for (int r = 0; r < 4; r++) acc[ns][r] = 0.f;

    float4 pA[2], pB[2];

    auto FETCH = [&](int kt) {
        #pragma unroll
        for (int q = 0; q < 2; q++) {
            int row = frow + (q << 5);
            pA[q] = *(const float4*)(Af + (size_t)(bm + row) * K + kBeg + kt + fkc);
            pB[q] = *(const float4*)(Bf + (size_t)(bn + row) * K + kBeg + kt + fkc);
        }
    };
    auto STORE = [&](int buf) {
        uint32_t* dA = sA + buf * A_BUF_W;
        uint32_t* dB = sB + buf * PLANE_W;
        #pragma unroll
        for (int q = 0; q < 2; q++) {
            int row = frow + (q << 5);
            uint4 hi, lo;
            tf32split(pA[q].x, hi.x, lo.x); tf32split(pA[q].y, hi.y, lo.y);
            tf32split(pA[q].z, hi.z, lo.z); tf32split(pA[q].w, hi.w, lo.w);
            *(uint4*)(dA + row * 36 + fkc)           = hi;
            *(uint4*)(dA + PLANE_W + row * 36 + fkc) = lo;
            uint4 bh;
            bh.x = tf32rna(pB[q].x); bh.y = tf32rna(pB[q].y);
            bh.z = tf32rna(pB[q].z); bh.w = tf32rna(pB[q].w);
            *(uint4*)(dB + row * 36 + fkc) = bh;
        }
    };

    FETCH(0);
    STORE(0);
    __syncthreads();

    for (int t = 0; t < nt; t++) {
        int cur = t & 1;
        bool more = (t + 1 < nt);
        if (more) FETCH((t + 1) << 5);

        uint32_t aB  = aBaseS + cur * A_BUF_BYTES + aOff;
        uint32_t bB0 = bBaseS + cur * B_BUF_BYTES + bOff;
        uint32_t bB1 = bB0 + ((16 * 36) << 2);
        #pragma unroll
        for (int ks = 0; ks < 4; ks++) {
            uint32_t koff = (ks << 3) << 2;
            uint32_t ah[4], al[4], bh[2][4];
            ldsm_x4(ah, aB + koff);
            ldsm_x4(al, aB + LO_BYTES + koff);
            ldsm_x4(bh[0], bB0 + koff);
            ldsm_x4(bh[1], bB1 + koff);
            #pragma unroll
            for (int p = 0; p < 2; p++)
                #pragma unroll
                for (int half = 0; half < 2; half++) {
                    int ns = (p << 1) + half;
                    const uint32_t bfh[2] = {bh[p][half << 1], bh[p][(half << 1) + 1]};
                    mma_tf32(acc[ns], ah, bfh);
                    mma_tf32(acc[ns], al, bfh);
                }
        }
        if (more) STORE(cur ^ 1);
        __syncthreads();
    }

    float* Cp = C + (size_t)blockIdx.z * M * N;
    int r0 = bm + warpM + g;
    #pragma unroll
    for (int ns = 0; ns < 4; ns++) {
        int c0 = bn + warpN + (ns << 3) + (tig << 1);
        size_t o0 = (size_t)r0 * N + c0, o2 = (size_t)(r0 + 8) * N + c0;
        Cp[o0] = acc[ns][0]; Cp[o0 + 1] = acc[ns][1];
        Cp[o2] = acc[ns][2]; Cp[o2 + 1] = acc[ns][3];
    }
}

// =======================================================================
// 3xTF32 GEMM for transposed-B (B row-major [K,N]); split-K; partial out.
// =======================================================================
__global__ __launch_bounds__(256)
void gemm_t(const float* __restrict__ Af, const float* __restrict__ Bf,
            float* __restrict__ C, int M, int N, int K, int ldb, int kChunk)
{
    __shared__ uint32_t sA[2][64][36];
    __shared__ uint32_t sB[2][64][36];

    int tid  = threadIdx.x;
    int lane = tid & 31, wid = tid >> 5;
    int warpM = (wid >> 1) << 4;
    int warpN = (wid & 1) << 5;
    int g = lane >> 2, tig = lane & 3;
    int bm = blockIdx.y << 6, bn = blockIdx.x << 6;
    int kBeg = blockIdx.z * kChunk;

    uint32_t aBase = smem_u32(&sA[0][0][0]) +
        (((warpM + (lane & 15)) * 36 + ((lane >> 4) << 2)) << 2);
    uint32_t bBase0 = smem_u32(&sB[0][0][0]) +
        (((warpN + ((lane >> 4) << 3) + (lane & 7)) * 36 + (((lane >> 3) & 1) << 2)) << 2);
    uint32_t bBase1 = bBase0 + (16 * 36 << 2);
    const uint32_t LO = (64 * 36) << 2;

    float acc[4][4];
    #pragma unroll
    for (int ns = 0; ns < 4; ns++)
        #pragma unroll
        for (int r = 0; r < 4; r++) acc[ns][r] = 0.f;

    float4 pA[2], pB[2];
    #pragma unroll
    for (int q = 0; q < 2; q++) {
        int idx = tid + (q << 8);
        int row = idx >> 3, kc = (idx & 7) << 2;
        pA[q] = *(const float4*)(Af + (size_t)(bm + row) * K + kBeg + kc);
        int k = idx >> 4, n0 = (idx & 15) << 2;
        pB[q] = *(const float4*)(Bf + (size_t)(kBeg + k) * ldb + bn + n0);
    }

    for (int kt = 0; kt < kChunk; kt += 32) {
        #pragma unroll
        for (int q = 0; q < 2; q++) {
            int idx = tid + (q << 8);
            {
                int row = idx >> 3, kc = (idx & 7) << 2;
                uint4 hi, lo;
                tf32split(pA[q].x, hi.x, lo.x); tf32split(pA[q].y, hi.y, lo.y);
                tf32split(pA[q].z, hi.z, lo.z); tf32split(pA[q].w, hi.w, lo.w);
                *(uint4*)&sA[0][row][kc] = hi;
                *(uint4*)&sA[1][row][kc] = lo;
            }
            {
                int k = idx >> 4, n0 = (idx & 15) << 2;
                float v[4] = {pB[q].x, pB[q].y, pB[q].z, pB[q].w};
                #pragma unroll
                for (int j = 0; j < 4; j++) {
                    uint32_t hb, lb; tf32split(v[j], hb, lb);
                    sB[0][n0 + j][k] = hb; sB[1][n0 + j][k] = lb;
                }
            }
        }
        __syncthreads();

        int ktn = kt + 32;
        if (ktn < kChunk) {
            #pragma unroll
            for (int q = 0; q < 2; q++) {
                int idx = tid + (q << 8);
                int row = idx >> 3, kc = (idx & 7) << 2;
                pA[q] = *(const float4*)(Af + (size_t)(bm + row) * K + kBeg + ktn + kc);
                int k = idx >> 4, n0 = (idx & 15) << 2;
                pB[q] = *(const float4*)(Bf + (size_t)(kBeg + ktn + k) * ldb + bn + n0);
            }
        }

        #pragma unroll
        for (int ks = 0; ks < 4; ks++) {
            uint32_t koff = (ks << 3) << 2;
            uint32_t ah[4], al[4], bh[2][4], bl[2][4];
            ldsm_x4(ah, aBase + koff);
            ldsm_x4(al, aBase + LO + koff);
            ldsm_x4(bh[0], bBase0 + koff);
            ldsm_x4(bl[0], bBase0 + LO + koff);
            ldsm_x4(bh[1], bBase1 + koff);
            ldsm_x4(bl[1], bBase1 + LO + koff);
            #pragma unroll
            for (int p = 0; p < 2; p++)
                #pragma unroll
                for (int half = 0; half < 2; half++) {
                    int ns = (p << 1) + half;
                    const uint32_t bfh[2] = {bh[p][half << 1], bh[p][(half << 1) + 1]};
                    const uint32_t bfl[2] = {bl[p][half << 1], bl[p][(half << 1) + 1]};
                    mma_tf32(acc[ns], ah, bfh);
                    mma_tf32(acc[ns], ah, bfl);
                    mma_tf32(acc[ns], al, bfh);
                }
        }
        __syncthreads();
    }

    float* Cp = C + (size_t)blockIdx.z * M * N;
    int r0 = bm + warpM + g;
    #pragma unroll
    for (int ns = 0; ns < 4; ns++) {
        int c0 = bn + warpN + (ns << 3) + (tig << 1);
        size_t o0 = (size_t)r0 * N + c0, o2 = (size_t)(r0 + 8) * N + c0;
        Cp[o0] = acc[ns][0]; Cp[o0 + 1] = acc[ns][1];
        Cp[o2] = acc[ns][2]; Cp[o2 + 1] = acc[ns][3];
    }
}

// =======================================================================
// Reduce split-K partials + bias (+relu)
// =======================================================================
__global__ __launch_bounds__(256)
void reduceSK(const float* __restrict__ part, int S, int plane,
              const float* __restrict__ bias, int act,
              float* __restrict__ out, int total, int N)
{
    int idx = blockIdx.x * 256 + threadIdx.x;
    if (idx >= total) return;
    float v = bias[idx % N];
    for (int s = 0; s < S; s++) v += part[(size_t)s * plane + idx];
    if (act) v = fmaxf(v, 0.f);
    out[idx] = v;
}

// =======================================================================
// GRU gates (hidden==0): reduce S split-K partials + bih + bhh; h=(1-z)n
// =======================================================================
__global__ __launch_bounds__(256)
void gru_gatesS(const float* __restrict__ gip, int S,
                const float* __restrict__ bih, const float* __restrict__ bhh,
                float* __restrict__ h)
{
    int idx = blockIdx.x * 256 + threadIdx.x;
    int b = idx >> 8, j = idx & 255;
    const float* g0 = gip + (size_t)b * G3;
    const size_t P = (size_t)BB * G3;
    float vr = bih[j], vz = bih[256 + j], vn = bih[512 + j];
    for (int s = 0; s < S; s++) {
        vr += g0[s * P + j];
        vz += g0[s * P + 256 + j];
        vn += g0[s * P + 512 + j];
    }
    float r = 1.f / (1.f + __expf(-(vr + bhh[j])));
    float z = 1.f / (1.f + __expf(-(vz + bhh[256 + j])));
    float n = tanhf(vn + r * bhh[512 + j]);
    h[idx] = (1.f - z) * n;
}

// =======================================================================
// LayerNorm over GRU dim
// =======================================================================
__global__ __launch_bounds__(256)
void ln1d_k(const float* __restrict__ h, const float* __restrict__ g,
            const float* __restrict__ b, float* __restrict__ o)
{
    __shared__ float s1[8], s2[8], mv[2];
    int row = blockIdx.x, tid = threadIdx.x;
    float v = h[(size_t)row * GRUU + tid];
    float s = v, q = v * v;
    #pragma unroll
    for (int off = 16; off; off >>= 1) {
        s += __shfl_xor_sync(0xffffffffu, s, off);
        q += __shfl_xor_sync(0xffffffffu, q, off);
    }
    if ((tid & 31) == 0) { s1[tid >> 5] = s; s2[tid >> 5] = q; }
    __syncthreads();
    if (tid == 0) {
        float S = 0.f, Q = 0.f;
        #pragma unroll
        for (int i = 0; i < 8; i++) { S += s1[i]; Q += s2[i]; }
        float m = S * (1.f / 256.f);
        float var = Q * (1.f / 256.f) - m * m;
        mv[0] = m; mv[1] = rsqrtf(var + 1e-5f);
    }
    __syncthreads();
    o[(size_t)row * GRUU + tid] = (v - mv[0]) * mv[1] * g[tid] + b[tid];
}

// =======================================================================
// host launcher
// =======================================================================
extern "C" void kernel_launch(void* const* d_in, const int* in_sizes, int n_in,
                              void* d_out, int out_size)
{
    const float* X    = (const float*)d_in[0];
    const int*   A    = (const int*)  d_in[1];
    const float* W1   = (const float*)d_in[2];
    const float* a1   = (const float*)d_in[3];
    const float* W2   = (const float*)d_in[4];
    const float* a2   = (const float*)d_in[5];
    const float* Wr   = (const float*)d_in[6];
    const float* br   = (const float*)d_in[7];
    const float* g1   = (const float*)d_in[8];
    const float* b1   = (const float*)d_in[9];
    const float* g2   = (const float*)d_in[10];
    const float* b2   = (const float*)d_in[11];
    const float* Wih0 = (const float*)d_in[12];
    const float* bih0 = (const float*)d_in[14];
    const float* bhh0 = (const float*)d_in[15];
    const float* Wih1 = (const float*)d_in[16];
    const float* bih1 = (const float*)d_in[18];
    const float* bhh1 = (const float*)d_in[19];
    const float* Wih2 = (const float*)d_in[20];
    const float* bih2 = (const float*)d_in[22];
    const float* bhh2 = (const float*)d_in[23];
    const float* gng  = (const float*)d_in[24];
    const float* gnb  = (const float*)d_in[25];
    const float* We   = (const float*)d_in[26];
    const float* be   = (const float*)d_in[27];
    const float* Wp   = (const float*)d_in[28];
    const float* bp   = (const float*)d_in[29];
    float* out = (float*)d_out;

    float *px, *pgip, *ph, *phln, *pemb;
    cudaGetSymbolAddress((void**)&px,   g_x);
    cudaGetSymbolAddress((void**)&pgip, g_gip);
    cudaGetSymbolAddress((void**)&ph,   g_h);
    cudaGetSymbolAddress((void**)&phln, g_hln);
    cudaGetSymbolAddress((void**)&pemb, g_emb);

    const int GAT_SMEM = GAT_WORDS * 4;   // 73728
    cudaFuncSetAttribute(gat_kernel, cudaFuncAttributeMaxDynamicSharedMemorySize, GAT_SMEM);
    cudaFuncSetAttribute(gemm_nk, cudaFuncAttributeMaxDynamicSharedMemorySize, GEMM_SMEM);

    gat_kernel<<<BB, TG, GAT_SMEM>>>(X, A, W1, a1, W2, a2, Wr, br, g1, b1, g2, b2);

    // GRU layer 0: split-K x8 (chunk 768 -> 24 BK32 tiles, grid 1536)
    dim3 g0(G3 / 64, BB / 64, SK0);
    gemm_nk<<<g0, 256, GEMM_SMEM>>>(px, Wih0, pgip, BB, G3, XG, XG / SK0);
    gru_gatesS<<<BB, 256>>>(pgip, SK0, bih0, bhh0, ph);

    // GRU layers 1 & 2: split-K x4 (chunk 64 -> 2 tiles, grid 768)
    dim3 g12(G3 / 64, BB / 64, 4);
    gemm_nk<<<g12, 256, GEMM_SMEM>>>(ph, Wih1, pgip, BB, G3, GRUU, GRUU / 4);
    gru_gatesS<<<BB, 256>>>(pgip, 4, bih1, bhh1, ph);
    gemm_nk<<<g12, 256, GEMM_SMEM>>>(ph, Wih2, pgip, BB, G3, GRUU, GRUU / 4);
    gru_gatesS<<<BB, 256>>>(pgip, 4, bih2, bhh2, ph);

    ln1d_k<<<BB, 256>>>(ph, gng, gnb, phln);

    float* embp = (out_size >= 2 * BB * EMBB) ? (out + (size_t)BB * EMBB) : pemb;

    // emb = relu(hln @ We + be): split-K x8 (K=256, chunk 32 -> 1 tile)
    dim3 gEmb(EMBB / 64, BB / 64, 8);
    gemm_t<<<gEmb, 256>>>(phln, We, pgip, BB, EMBB, GRUU, EMBB, GRUU / 8);
    reduceSK<<<(BB * EMBB + 255) / 256, 256>>>(pgip, 8, BB * EMBB, be, 1,
                                               embp, BB * EMBB, EMBB);

    // pred = emb @ Wp + bp: split-K x4 (K=128, chunk 32 -> 1 tile)
    dim3 gPred(NN / 64, BB / 64, 4);
    gemm_t<<<gPred, 256>>>(embp, Wp, pgip, BB, NN, EMBB, NN, EMBB / 4);
    reduceSK<<<(BB * NN + 255) / 256, 256>>>(pgip, 4, BB * NN, bp, 0,
                                             out, BB * NN, NN);
}

// round 16
// speedup vs baseline: 1.6286x; 1.0678x over previous
#include <cuda_runtime.h>
#include <cstdint>

// ---------------- problem constants ----------------
#define BB   1024
#define NN   128
#define FF   16
#define GG   48
#define HH   6
#define DD   8
#define GRUU 256
#define EMBB 128
#define XG   (NN*GG)       // 6144
#define G3   (3*GRUU)      // 768
#define SK0  8             // split-K for GRU0
#define TG   384           // GAT block size (12 warps)

// ---------------- scratch ----------------
__device__ float g_x  [BB*XG];
__device__ float g_gip[SK0*BB*G3];
__device__ float g_h  [BB*GRUU];
__device__ float g_hln[BB*GRUU];
__device__ float g_emb[BB*EMBB];

// ---------------- helpers ----------------
__device__ __forceinline__ void tf32split(float v, uint32_t& h, uint32_t& l) {
    uint32_t hb; asm("cvt.rna.tf32.f32 %0, %1;" : "=r"(hb) : "f"(v));
    float lv = v - __uint_as_float(hb);
    uint32_t lb; asm("cvt.rna.tf32.f32 %0, %1;" : "=r"(lb) : "f"(lv));
    h = hb; l = lb;
}

__device__ __forceinline__ uint32_t tf32rna(float v) {
    uint32_t r; asm("cvt.rna.tf32.f32 %0, %1;" : "=r"(r) : "f"(v));
    return r;
}

__device__ __forceinline__ uint32_t smem_u32(const void* p) {
    uint32_t a;
    asm("{ .reg .u64 t; cvta.to.shared.u64 t, %1; cvt.u32.u64 %0, t; }" : "=r"(a) : "l"(p));
    return a;
}

__device__ __forceinline__ void ldsm_x4(uint32_t* d, uint32_t addr) {
    asm volatile("ldmatrix.sync.aligned.m8n8.x4.shared.b16 {%0,%1,%2,%3}, [%4];"
        : "=r"(d[0]), "=r"(d[1]), "=r"(d[2]), "=r"(d[3]) : "r"(addr));
}

__device__ __forceinline__ void mma_tf32(float* c, const uint32_t* a, const uint32_t* b) {
    asm volatile("mma.sync.aligned.m16n8k8.row.col.f32.tf32.tf32.f32 "
        "{%0,%1,%2,%3}, {%4,%5,%6,%7}, {%8,%9}, {%0,%1,%2,%3};\n"
        : "+f"(c[0]), "+f"(c[1]), "+f"(c[2]), "+f"(c[3])
        : "r"(a[0]), "r"(a[1]), "r"(a[2]), "r"(a[3]), "r"(b[0]), "r"(b[1]));
}

// =======================================================================
// GAT layer GEMM via MMA: sh[hd][n][d] = x[n][:Kf] @ W[hd][:Kf][d]
// 48 warp-tasks (6 heads x 8 m-tiles of 16 rows), K-tiles of 8.
// A fragments gathered by scalar LDS (fp32, hw-truncated to tf32);
// B fragments read directly from [f][d]-layout weight smem.
// =======================================================================
__device__ __forceinline__ void layer_mma(
    const float* __restrict__ sx, int xs, int Kf,
    const uint32_t* __restrict__ sWv, float* __restrict__ shf, int tid)
{
    int lane = tid & 31, wid = tid >> 5;
    int g = lane >> 2, tig = lane & 3;

    #pragma unroll 1
    for (int task = wid; task < 48; task += 12) {
        int hd = task >> 3, m0 = (task & 7) << 4;
        const float* x0 = sx + (m0 + g) * xs;
        const float* x1 = x0 + (xs << 3);
        const uint32_t* wv = sWv + hd * Kf * 8 + g;
        float c[4] = {0.f, 0.f, 0.f, 0.f};
        #pragma unroll 1
        for (int kt = 0; kt < Kf; kt += 8) {
            uint32_t a[4], b[2];
            a[0] = __float_as_uint(x0[kt + tig]);
            a[1] = __float_as_uint(x1[kt + tig]);
            a[2] = __float_as_uint(x0[kt + tig + 4]);
            a[3] = __float_as_uint(x1[kt + tig + 4]);
            b[0] = wv[(kt + tig) << 3];
            b[1] = wv[(kt + tig + 4) << 3];
            mma_tf32(c, a, b);
        }
        float* o0 = shf + (hd << 10) + ((m0 + g) << 3) + (tig << 1);
        float* o1 = o0 + 64;   // +8 rows * 8 cols
        *(float2*)o0 = make_float2(c[0], c[1]);
        *(float2*)o1 = make_float2(c[2], c[3]);
    }
}

// =======================================================================
// GAT attention via tensor cores (R15 form).
// =======================================================================
__device__ __forceinline__ void gat_attention_mma(
    const uint32_t* __restrict__ shv,
    const float* __restrict__ sei, const float* __restrict__ sej,
    const float2* __restrict__ sPQ,
    const unsigned* __restrict__ smask, float* __restrict__ sy, int tid)
{
    int lane = tid & 31, wid = tid >> 5;
    int g = lane >> 2, tig = lane & 3;
    const uint32_t ONES[2] = {0x3F800000u, 0x3F800000u};

    #pragma unroll 1
    for (int task = wid; task < 48; task += 12) {
        int hd = task >> 3, m0 = (task & 7) << 4;
        int r0 = m0 + g, r1 = r0 + 8;
        float ei0 = sei[(hd << 7) + r0], ei1 = sei[(hd << 7) + r1];
        float Pi0 = __expf(ei0), Qi0 = __expf(0.01f * ei0);
        float Pi1 = __expf(ei1), Qi1 = __expf(0.01f * ei1);
        unsigned w0m = smask[(r0 << 2) + tig];
        unsigned w1m = smask[(r1 << 2) + tig];
        const float*  ejp = sej + (hd << 7);
        const float2* pqp = sPQ + (hd << 7);
        const uint32_t* hv = shv + (hd << 10);

        float c[4]  = {0.f, 0.f, 0.f, 0.f};
        float cs[4] = {0.f, 0.f, 0.f, 0.f};

        #pragma unroll 1
        for (int jw = 0; jw < 4; jw++) {
            #pragma unroll
            for (int q = 0; q < 4; q++) {
                int j0 = (jw << 5) + (q << 3);
                int sh2 = (jw << 3) + (q << 1);
                unsigned mt0 = w0m >> sh2;
                unsigned mt1 = w1m >> sh2;
                int jA = j0 + tig, jB = jA + 4;
                float ejA = ejp[jA], ejB = ejp[jB];
                float2 pqA = pqp[jA], pqB = pqp[jB];

                float wa0 = (ei0 + ejA > 0.f) ? (Pi0 * pqA.x) : (Qi0 * pqA.y);
                float wa1 = (ei1 + ejA > 0.f) ? (Pi1 * pqA.x) : (Qi1 * pqA.y);
                float wa2 = (ei0 + ejB > 0.f) ? (Pi0 * pqB.x) : (Qi0 * pqB.y);
                float wa3 = (ei1 + ejB > 0.f) ? (Pi1 * pqB.x) : (Qi1 * pqB.y);
                wa0 = (mt0 & 1u) ? wa0 : 0.f;
                wa1 = (mt1 & 1u) ? wa1 : 0.f;
                wa2 = (mt0 & 2u) ? wa2 : 0.f;
                wa3 = (mt1 & 2u) ? wa3 : 0.f;

                uint32_t a[4];
                a[0] = __float_as_uint(wa0); a[1] = __float_as_uint(wa1);
                a[2] = __float_as_uint(wa2); a[3] = __float_as_uint(wa3);

                uint32_t bh[2] = { hv[(jA << 3) + g], hv[(jB << 3) + g] };
                mma_tf32(c, a, bh);
                mma_tf32(cs, a, ONES);
            }
        }
        float inv0 = 1.0f / cs[0], inv1 = 1.0f / cs[2];

        float* o0 = sy + r0 * 49 + (hd << 3) + (tig << 1);
        float* o1 = sy + r1 * 49 + (hd << 3) + (tig << 1);
        o0[0] = c[0] * inv0; o0[1] = c[1] * inv0;
        o1[0] = c[2] * inv1; o1[1] = c[3] * inv1;
    }
}

// LayerNorm over [N,G] + ReLU; row/col loops. 12 warps.
__device__ __forceinline__ void ln2d_apply(
    float* __restrict__ sy, const float* __restrict__ gamma,
    const float* __restrict__ beta, float* __restrict__ sred,
    int tid, float* __restrict__ gout)
{
    int lane = tid & 31, wid = tid >> 5;
    float s = 0.f, q = 0.f;
    for (int n = wid; n < NN; n += 12) {
        const float* row = sy + n * 49;
        for (int c = lane; c < GG; c += 32) {
            float v = row[c];
            s += v; q += v * v;
        }
    }
    #pragma unroll
    for (int o = 16; o; o >>= 1) {
        s += __shfl_xor_sync(0xffffffffu, s, o);
        q += __shfl_xor_sync(0xffffffffu, q, o);
    }
    if (lane == 0) { sred[wid] = s; sred[12 + wid] = q; }
    __syncthreads();
    if (tid == 0) {
        float S = 0.f, Q = 0.f;
        #pragma unroll
        for (int i = 0; i < 12; i++) { S += sred[i]; Q += sred[12 + i]; }
        float m   = S * (1.f / (float)XG);
        float var = Q * (1.f / (float)XG) - m * m;
        sred[24] = m;
        sred[25] = rsqrtf(var + 1e-5f);
    }
    __syncthreads();
    float m = sred[24], rs = sred[25];
    for (int n = wid; n < NN; n += 12) {
        float* row = sy + n * 49;
        for (int c = lane; c < GG; c += 32) {
            float v = (row[c] - m) * rs * gamma[n * 48 + c] + beta[n * 48 + c];
            v = fmaxf(v, 0.f);
            if (gout) gout[n * 48 + c] = v; else row[c] = v;
        }
    }
}

// GAT smem layout (words). sX overlaid on sy (dead after first attention).
#define S_H    0
#define S_Y    (S_H + 6144)
#define S_EI   (S_Y + 6272)
#define S_EJ   (S_EI + 768)
#define S_PQ   (S_EJ + 768)
#define S_W    (S_PQ + 1536)
#define S_A    (S_W + 2304)
#define S_RED  (S_A + 96)
#define S_MASK (S_RED + 32)
#define GAT_WORDS (S_MASK + 512)   // 18432 words = 73728 B -> 3 CTA/SM

__global__ __launch_bounds__(TG, 3)
void gat_kernel(const float* __restrict__ X,  const int* __restrict__ A,
                const float* __restrict__ W1, const float* __restrict__ a1,
                const float* __restrict__ W2, const float* __restrict__ a2,
                const float* __restrict__ Wr, const float* __restrict__ br,
                const float* __restrict__ g1, const float* __restrict__ b1,
                const float* __restrict__ g2, const float* __restrict__ b2)
{
    extern __shared__ float sm[];
    float*    sh    = sm + S_H;
    uint32_t* shv   = (uint32_t*)(sm + S_H);
    float*    sy    = sm + S_Y;
    float*    sX    = sm + S_Y;               // overlay, stride 17
    float*    sei   = sm + S_EI;
    float*    sej   = sm + S_EJ;
    float2*   sPQ   = (float2*)(sm + S_PQ);
    float*    sW    = sm + S_W;
    uint32_t* sWv   = (uint32_t*)(sm + S_W);
    float*    sa    = sm + S_A;
    float*    sred  = sm + S_RED;
    unsigned* smask = (unsigned*)(sm + S_MASK);

    int b = blockIdx.x, tid = threadIdx.x;
    int lane = tid & 31, wid = tid >> 5;
    const float* Xb = X + (size_t)b * (NN * FF);

    for (int t = tid; t < NN * FF; t += TG)
        sX[(t >> 4) * 17 + (t & 15)] = Xb[t];

    // adjacency -> transposed-nibble bitmask: word k=j%4, bit l=j/4
    {
        const int* Ab = A + (size_t)b * (NN * NN);
        for (int i = wid; i < NN; i += 12) {
            int4 v = ((const int4*)(Ab + (i << 7)))[lane];
            unsigned b0 = __ballot_sync(0xffffffffu, v.x != 0);
            unsigned b1 = __ballot_sync(0xffffffffu, v.y != 0);
            unsigned b2 = __ballot_sync(0xffffffffu, v.z != 0);
            unsigned b3 = __ballot_sync(0xffffffffu, v.w != 0);
            if (lane == 0) {
                smask[(i << 2)]     = b0;
                smask[(i << 2) + 1] = b1;
                smask[(i << 2) + 2] = b2;
                smask[(i << 2) + 3] = b3;
            }
        }
    }
    for (int t = tid; t < HH * FF * DD; t += TG) sW[t] = W1[t];
    if (tid < HH * 2 * DD) sa[tid] = a1[tid];
    __syncthreads();

    // ---- layer 1: h = X@W1 via MMA ----
    layer_mma(sX, 17, FF, sWv, sh, tid);
    __syncthreads();
    // scores from sh
    for (int t = tid; t < HH * NN; t += TG) {
        int hd = t >> 7;
        const float* av = sa + (hd << 4);
        float4 h0 = *(const float4*)(sh + (t << 3));
        float4 h1 = *(const float4*)(sh + (t << 3) + 4);
        float ei = h0.x*av[0] + h0.y*av[1] + h0.z*av[2] + h0.w*av[3]
                 + h1.x*av[4] + h1.y*av[5] + h1.z*av[6] + h1.w*av[7];
        float ej = h0.x*av[8] + h0.y*av[9] + h0.z*av[10] + h0.w*av[11]
                 + h1.x*av[12] + h1.y*av[13] + h1.z*av[14] + h1.w*av[15];
        sei[t] = ei; sej[t] = ej;
        sPQ[t] = make_float2(__expf(ej), __expf(0.01f * ej));
    }
    __syncthreads();
    gat_attention_mma(shv, sei, sej, sPQ, smask, sy, tid);  // overwrites sX
    __syncthreads();
    ln2d_apply(sy, g1, b1, sred, tid, nullptr);
    __syncthreads();

    // ---- layer 2 weights ----
    for (int t = tid; t < HH * GG * DD; t += TG) sW[t] = W2[t];
    if (tid < HH * 2 * DD) sa[tid] = a2[tid];
    __syncthreads();

    // ---- layer 2: h2 = y@W2 via MMA ----
    layer_mma(sy, 49, GG, sWv, sh, tid);
    __syncthreads();
    for (int t = tid; t < HH * NN; t += TG) {
        int hd = t >> 7;
        const float* av = sa + (hd << 4);
        float4 h0 = *(const float4*)(sh + (t << 3));
        float4 h1 = *(const float4*)(sh + (t << 3) + 4);
        float ei = h0.x*av[0] + h0.y*av[1] + h0.z*av[2] + h0.w*av[3]
                 + h1.x*av[4] + h1.y*av[5] + h1.z*av[6] + h1.w*av[7];
        float ej = h0.x*av[8] + h0.y*av[9] + h0.z*av[10] + h0.w*av[11]
                 + h1.x*av[12] + h1.y*av[13] + h1.z*av[14] + h1.w*av[15];
        sei[t] = ei; sej[t] = ej;
        sPQ[t] = make_float2(__expf(ej), __expf(0.01f * ej));
    }
    __syncthreads();
    gat_attention_mma(shv, sei, sej, sPQ, smask, sy, tid);
    __syncthreads();

    // ---- residual: sy += X@Wr + br (X re-read from global) ----
    for (int t = tid; t < FF * GG; t += TG) sW[t] = Wr[t];
    if (tid < GG) sa[tid] = br[tid];
    __syncthreads();
    for (int n = wid; n < NN; n += 12) {
        const float* x = Xb + n * FF;
        float* row = sy + n * 49;
        for (int c = lane; c < GG; c += 32) {
            float accv = sa[c];
            #pragma unroll
            for (int f = 0; f < FF; f++) accv = fmaf(x[f], sW[f * 48 + c], accv);
            row[c] += accv;
        }
    }
    __syncthreads();
    ln2d_apply(sy, g2, b2, sred, tid, g_x + (size_t)b * XG);
}

// =======================================================================
// Double-buffered 2xTF32 GEMM, BK=32. A split hi/lo; B hi-only.
// =======================================================================
#define PLANE_W     (64*36)
#define LO_BYTES    (PLANE_W*4)
#define A_BUF_W     (2*PLANE_W)
#define A_BUF_BYTES (A_BUF_W*4)
#define B_BUF_BYTES (PLANE_W*4)
#define GEMM_SMEM   (6*PLANE_W*4)   // 55296

__global__ __launch_bounds__(256)
void gemm_nk(const float* __restrict__ Af, const float* __restrict__ Bf,
             float* __restrict__ C, int M, int N, int K, int kChunk)
{
    extern __shared__ uint32_t smem[];
    uint32_t* sA = smem;
    uint32_t* sB = smem + 2 * A_BUF_W;

    int tid  = threadIdx.x;
    int lane = tid & 31, wid = tid >> 5;
    int warpM = (wid >> 1) << 4;
    int warpN = (wid & 1) << 5;
    int g = lane >> 2, tig = lane & 3;
    int bm = blockIdx.y << 6, bn = blockIdx.x << 6;
    int kBeg = blockIdx.z * kChunk;
    int nt   = kChunk >> 5;

    uint32_t aOff = (((warpM + (lane & 15)) * 36 + ((lane >> 4) << 2)) << 2);
    uint32_t bOff = (((warpN + ((lane >> 4) << 3) + (lane & 7)) * 36 + (((lane >> 3) & 1) << 2)) << 2);
    uint32_t aBaseS = smem_u32(sA);
    uint32_t bBaseS = smem_u32(sB);

    int frow = tid >> 3;
    int fkc  = (tid & 7) << 2;

    float acc[4][4];
    #pragma unroll
    for (int ns = 0; ns < 4; ns++)
        #pragma unroll
        for (int r = 0; r < 4; r++) acc[ns][r] = 0.f;

    float4 pA[2], pB[2];

    auto FETCH = [&](int kt) {
        #pragma unroll
        for (int q = 0; q < 2; q++) {
            int row = frow + (q << 5);
            pA[q] = *(const float4*)(Af + (size_t)(bm + row) * K + kBeg + kt + fkc);
            pB[q] = *(const float4*)(Bf + (size_t)(bn + row) * K + kBeg + kt + fkc);
        }
    };
    auto STORE = [&](int buf) {
        uint32_t* dA = sA + buf * A_BUF_W;
        uint32_t* dB = sB + buf * PLANE_W;
        #pragma unroll
        for (int q = 0; q < 2; q++) {
            int row = frow + (q << 5);
            uint4 hi, lo;
            tf32split(pA[q].x, hi.x, lo.x); tf32split(pA[q].y, hi.y, lo.y);
            tf32split(pA[q].z, hi.z, lo.z); tf32split(pA[q].w, hi.w, lo.w);
            *(uint4*)(dA + row * 36 + fkc)           = hi;
            *(uint4*)(dA + PLANE_W + row * 36 + fkc) = lo;
            uint4 bh;
            bh.x = tf32rna(pB[q].x); bh.y = tf32rna(pB[q].y);
            bh.z = tf32rna(pB[q].z); bh.w = tf32rna(pB[q].w);
            *(uint4*)(dB + row * 36 + fkc) = bh;
        }
    };

    FETCH(0);
    STORE(0);
    __syncthreads();

    for (int t = 0; t < nt; t++) {
        int cur = t & 1;
        bool more = (t + 1 < nt);
        if (more) FETCH((t + 1) << 5);

        uint32_t aB  = aBaseS + cur * A_BUF_BYTES + aOff;
        uint32_t bB0 = bBaseS + cur * B_BUF_BYTES + bOff;
        uint32_t bB1 = bB0 + ((16 * 36) << 2);
        #pragma unroll
        for (int ks = 0; ks < 4; ks++) {
            uint32_t koff = (ks << 3) << 2;
            uint32_t ah[4], al[4], bh[2][4];
            ldsm_x4(ah, aB + koff);
            ldsm_x4(al, aB + LO_BYTES + koff);
            ldsm_x4(bh[0], bB0 + koff);
            ldsm_x4(bh[1], bB1 + koff);
            #pragma unroll
            for (int p = 0; p < 2; p++)
                #pragma unroll
                for (int half = 0; half < 2; half++) {
                    int ns = (p << 1) + half;
                    const uint32_t bfh[2] = {bh[p][half << 1], bh[p][(half << 1) + 1]};
                    mma_tf32(acc[ns], ah, bfh);
                    mma_tf32(acc[ns], al, bfh);
                }
        }
        if (more) STORE(cur ^ 1);
        __syncthreads();
    }

    float* Cp = C + (size_t)blockIdx.z * M * N;
    int r0 = bm + warpM + g;
    #pragma unroll
    for (int ns = 0; ns < 4; ns++) {
        int c0 = bn + warpN + (ns << 3) + (tig << 1);
        size_t o0 = (size_t)r0 * N + c0, o2 = (size_t)(r0 + 8) * N + c0;
        Cp[o0] = acc[ns][0]; Cp[o0 + 1] = acc[ns][1];
        Cp[o2] = acc[ns][2]; Cp[o2 + 1] = acc[ns][3];
    }
}

// =======================================================================
// 3xTF32 GEMM for transposed-B (B row-major [K,N]); split-K; partial out.
// =======================================================================
__global__ __launch_bounds__(256)
void gemm_t(const float* __restrict__ Af, const float* __restrict__ Bf,
            float* __restrict__ C, int M, int N, int K, int ldb, int kChunk)
{
    __shared__ uint32_t sA[2][64][36];
    __shared__ uint32_t sB[2][64][36];

    int tid  = threadIdx.x;
    int lane = tid & 31, wid = tid >> 5;
    int warpM = (wid >> 1) << 4;
    int warpN = (wid & 1) << 5;
    int g = lane >> 2, tig = lane & 3;
    int bm = blockIdx.y << 6, bn = blockIdx.x << 6;
    int kBeg = blockIdx.z * kChunk;

    uint32_t aBase = smem_u32(&sA[0][0][0]) +
        (((warpM + (lane & 15)) * 36 + ((lane >> 4) << 2)) << 2);
    uint32_t bBase0 = smem_u32(&sB[0][0][0]) +
        (((warpN + ((lane >> 4) << 3) + (lane & 7)) * 36 + (((lane >> 3) & 1) << 2)) << 2);
    uint32_t bBase1 = bBase0 + (16 * 36 << 2);
    const uint32_t LO = (64 * 36) << 2;

    float acc[4][4];
    #pragma unroll
    for (int ns = 0; ns < 4; ns++)
        #pragma unroll
        for (int r = 0; r < 4; r++) acc[ns][r] = 0.f;

    float4 pA[2], pB[2];
    #pragma unroll
    for (int q = 0; q < 2; q++) {
        int idx = tid + (q << 8);
        int row = idx >> 3, kc = (idx & 7) << 2;
        pA[q] = *(const float4*)(Af + (size_t)(bm + row) * K + kBeg + kc);
        int k = idx >> 4, n0 = (idx & 15) << 2;
        pB[q] = *(const float4*)(Bf + (size_t)(kBeg + k) * ldb + bn + n0);
    }

    for (int kt = 0; kt < kChunk; kt += 32) {
        #pragma unroll
        for (int q = 0; q < 2; q++) {
            int idx = tid + (q << 8);
            {
                int row = idx >> 3, kc = (idx & 7) << 2;
                uint4 hi, lo;
                tf32split(pA[q].x, hi.x, lo.x); tf32split(pA[q].y, hi.y, lo.y);
                tf32split(pA[q].z, hi.z, lo.z); tf32split(pA[q].w, hi.w, lo.w);
                *(uint4*)&sA[0][row][kc] = hi;
                *(uint4*)&sA[1][row][kc] = lo;
            }
            {
                int k = idx >> 4, n0 = (idx & 15) << 2;
                float v[4] = {pB[q].x, pB[q].y, pB[q].z, pB[q].w};
                #pragma unroll
                for (int j = 0; j < 4; j++) {
                    uint32_t hb, lb; tf32split(v[j], hb, lb);
                    sB[0][n0 + j][k] = hb; sB[1][n0 + j][k] = lb;
                }
            }
        }
        __syncthreads();

        int ktn = kt + 32;
        if (ktn < kChunk) {
            #pragma unroll
            for (int q = 0; q < 2; q++) {
                int idx = tid + (q << 8);
                int row = idx >> 3, kc = (idx & 7) << 2;
                pA[q] = *(const float4*)(Af + (size_t)(bm + row) * K + kBeg + ktn + kc);
                int k = idx >> 4, n0 = (idx & 15) << 2;
                pB[q] = *(const float4*)(Bf + (size_t)(kBeg + ktn + k) * ldb + bn + n0);
            }
        }

        #pragma unroll
        for (int ks = 0; ks < 4; ks++) {
            uint32_t koff = (ks << 3) << 2;
            uint32_t ah[4], al[4], bh[2][4], bl[2][4];
            ldsm_x4(ah, aBase + koff);
            ldsm_x4(al, aBase + LO + koff);
            ldsm_x4(bh[0], bBase0 + koff);
            ldsm_x4(bl[0], bBase0 + LO + koff);
            ldsm_x4(bh[1], bBase1 + koff);
            ldsm_x4(bl[1], bBase1 + LO + koff);
            #pragma unroll
            for (int p = 0; p < 2; p++)
                #pragma unroll
                for (int half = 0; half < 2; half++) {
                    int ns = (p << 1) + half;
                    const uint32_t bfh[2] = {bh[p][half << 1], bh[p][(half << 1) + 1]};
                    const uint32_t bfl[2] = {bl[p][half << 1], bl[p][(half << 1) + 1]};
                    mma_tf32(acc[ns], ah, bfh);
                    mma_tf32(acc[ns], ah, bfl);
                    mma_tf32(acc[ns], al, bfh);
                }
        }
        __syncthreads();
    }

    float* Cp = C + (size_t)blockIdx.z * M * N;
    int r0 = bm + warpM + g;
    #pragma unroll
    for (int ns = 0; ns < 4; ns++) {
        int c0 = bn + warpN + (ns << 3) + (tig << 1);
        size_t o0 = (size_t)r0 * N + c0, o2 = (size_t)(r0 + 8) * N + c0;
        Cp[o0] = acc[ns][0]; Cp[o0 + 1] = acc[ns][1];
        Cp[o2] = acc[ns][2]; Cp[o2 + 1] = acc[ns][3];
    }
}

// =======================================================================
// Reduce split-K partials + bias (+relu)
// =======================================================================
__global__ __launch_bounds__(256)
void reduceSK(const float* __restrict__ part, int S, int plane,
              const float* __restrict__ bias, int act,
              float* __restrict__ out, int total, int N)
{
    int idx = blockIdx.x * 256 + threadIdx.x;
    if (idx >= total) return;
    float v = bias[idx % N];
    for (int s = 0; s < S; s++) v += part[(size_t)s * plane + idx];
    if (act) v = fmaxf(v, 0.f);
    out[idx] = v;
}

// =======================================================================
// GRU gates (hidden==0): reduce S split-K partials + bih + bhh; h=(1-z)n
// =======================================================================
__global__ __launch_bounds__(256)
void gru_gatesS(const float* __restrict__ gip, int S,
                const float* __restrict__ bih, const float* __restrict__ bhh,
                float* __restrict__ h)
{
    int idx = blockIdx.x * 256 + threadIdx.x;
    int b = idx >> 8, j = idx & 255;
    const float* g0 = gip + (size_t)b * G3;
    const size_t P = (size_t)BB * G3;
    float vr = bih[j], vz = bih[256 + j], vn = bih[512 + j];
    for (int s = 0; s < S; s++) {
        vr += g0[s * P + j];
        vz += g0[s * P + 256 + j];
        vn += g0[s * P + 512 + j];
    }
    float r = 1.f / (1.f + __expf(-(vr + bhh[j])));
    float z = 1.f / (1.f + __expf(-(vz + bhh[256 + j])));
    float n = tanhf(vn + r * bhh[512 + j]);
    h[idx] = (1.f - z) * n;
}

// Last GRU layer: gates + LayerNorm fused (one block per batch row)
__global__ __launch_bounds__(256)
void gru_gates_ln(const float* __restrict__ gip, int S,
                  const float* __restrict__ bih, const float* __restrict__ bhh,
                  const float* __restrict__ gam, const float* __restrict__ bet,
                  float* __restrict__ o)
{
    __shared__ float s1[8], s2[8], mv[2];
    int b = blockIdx.x, j = threadIdx.x;
    const float* g0 = gip + (size_t)b * G3;
    const size_t P = (size_t)BB * G3;
    float vr = bih[j], vz = bih[256 + j], vn = bih[512 + j];
    for (int s = 0; s < S; s++) {
        vr += g0[s * P + j];
        vz += g0[s * P + 256 + j];
        vn += g0[s * P + 512 + j];
    }
    float r = 1.f / (1.f + __expf(-(vr + bhh[j])));
    float z = 1.f / (1.f + __expf(-(vz + bhh[256 + j])));
    float n = tanhf(vn + r * bhh[512 + j]);
    float hv = (1.f - z) * n;

    float s = hv, q = hv * hv;
    #pragma unroll
    for (int off = 16; off; off >>= 1) {
        s += __shfl_xor_sync(0xffffffffu, s, off);
        q += __shfl_xor_sync(0xffffffffu, q, off);
    }
    if ((j & 31) == 0) { s1[j >> 5] = s; s2[j >> 5] = q; }
    __syncthreads();
    if (j == 0) {
        float S = 0.f, Q = 0.f;
        #pragma unroll
        for (int i = 0; i < 8; i++) { S += s1[i]; Q += s2[i]; }
        float m = S * (1.f / 256.f);
        float var = Q * (1.f / 256.f) - m * m;
        mv[0] = m; mv[1] = rsqrtf(var + 1e-5f);
    }
    __syncthreads();
    o[(size_t)b * GRUU + j] = (hv - mv[0]) * mv[1] * gam[j] + bet[j];
}

// =======================================================================
// host launcher
// =======================================================================
extern "C" void kernel_launch(void* const* d_in, const int* in_sizes, int n_in,
                              void* d_out, int out_size)
{
    const float* X    = (const float*)d_in[0];
    const int*   A    = (const int*)  d_in[1];
    const float* W1   = (const float*)d_in[2];
    const float* a1   = (const float*)d_in[3];
    const float* W2   = (const float*)d_in[4];
    const float* a2   = (const float*)d_in[5];
    const float* Wr   = (const float*)d_in[6];
    const float* br   = (const float*)d_in[7];
    const float* g1   = (const float*)d_in[8];
    const float* b1   = (const float*)d_in[9];
    const float* g2   = (const float*)d_in[10];
    const float* b2   = (const float*)d_in[11];
    const float* Wih0 = (const float*)d_in[12];
    const float* bih0 = (const float*)d_in[14];
    const float* bhh0 = (const float*)d_in[15];
    const float* Wih1 = (const float*)d_in[16];
    const float* bih1 = (const float*)d_in[18];
    const float* bhh1 = (const float*)d_in[19];
    const float* Wih2 = (const float*)d_in[20];
    const float* bih2 = (const float*)d_in[22];
    const float* bhh2 = (const float*)d_in[23];
    const float* gng  = (const float*)d_in[24];
    const float* gnb  = (const float*)d_in[25];
    const float* We   = (const float*)d_in[26];
    const float* be   = (const float*)d_in[27];
    const float* Wp   = (const float*)d_in[28];
    const float* bp   = (const float*)d_in[29];
    float* out = (float*)d_out;

    float *px, *pgip, *ph, *phln, *pemb;
    cudaGetSymbolAddress((void**)&px,   g_x);
    cudaGetSymbolAddress((void**)&pgip, g_gip);
    cudaGetSymbolAddress((void**)&ph,   g_h);
    cudaGetSymbolAddress((void**)&phln, g_hln);
    cudaGetSymbolAddress((void**)&pemb, g_emb);

    const int GAT_SMEM = GAT_WORDS * 4;   // 73728
    cudaFuncSetAttribute(gat_kernel, cudaFuncAttributeMaxDynamicSharedMemorySize, GAT_SMEM);
    cudaFuncSetAttribute(gemm_nk, cudaFuncAttributeMaxDynamicSharedMemorySize, GEMM_SMEM);

    gat_kernel<<<BB, TG, GAT_SMEM>>>(X, A, W1, a1, W2, a2, Wr, br, g1, b1, g2, b2);

    // GRU layer 0: split-K x8 (chunk 768 -> 24 BK32 tiles, grid 1536)
    dim3 g0(G3 / 64, BB / 64, SK0);
    gemm_nk<<<g0, 256, GEMM_SMEM>>>(px, Wih0, pgip, BB, G3, XG, XG / SK0);
    gru_gatesS<<<BB, 256>>>(pgip, SK0, bih0, bhh0, ph);

    // GRU layers 1 & 2: split-K x2 (proven optimum)
    dim3 g12(G3 / 64, BB / 64, 2);
    gemm_nk<<<g12, 256, GEMM_SMEM>>>(ph, Wih1, pgip, BB, G3, GRUU, GRUU / 2);
    gru_gatesS<<<BB, 256>>>(pgip, 2, bih1, bhh1, ph);
    gemm_nk<<<g12, 256, GEMM_SMEM>>>(ph, Wih2, pgip, BB, G3, GRUU, GRUU / 2);
    gru_gates_ln<<<BB, 256>>>(pgip, 2, bih2, bhh2, gng, gnb, phln);

    float* embp = (out_size >= 2 * BB * EMBB) ? (out + (size_t)BB * EMBB) : pemb;

    // emb = relu(hln @ We + be): split-K x4 (K=256, chunk 64)
    dim3 gEmb(EMBB / 64, BB / 64, 4);
    gemm_t<<<gEmb, 256>>>(phln, We, pgip, BB, EMBB, GRUU, EMBB, GRUU / 4);
    reduceSK<<<(BB * EMBB + 255) / 256, 256>>>(pgip, 4, BB * EMBB, be, 1,
                                               embp, BB * EMBB, EMBB);

    // pred = emb @ Wp + bp: split-K x2 (K=128, chunk 64)
    dim3 gPred(NN / 64, BB / 64, 2);
    gemm_t<<<gPred, 256>>>(embp, Wp, pgip, BB, NN, EMBB, NN, EMBB / 2);
    reduceSK<<<(BB * NN + 255) / 256, 256>>>(pgip, 2, BB * NN, bp, 0,
                                             out, BB * NN, NN);
}